// round 12
// baseline (speedup 1.0000x reference)
#include <cuda_runtime.h>
#include <cuda_fp16.h>
#include <math.h>

#define NN 30000
#define NE 480000
#define H 128
#define NL 4
#define NGR 32
#define NOUT 12
#define AVG_LOG 1.38214548f
#define EPS_BN 1e-5f
#define EPS_STD 1e-5f
#define KP_EDGE 80
#define KP_POST 832
#define KP_LIN 64
#define KP_D 64
#define WS_STRIDE 136
#define SCAN_B 128
#define CHUNK 235
#define STAGE_W2 12544     // words per stage: 2 subs x (A 2x2048 + W 2176)
#define SUB_W2 6272
#define BIG_SMEM2 100352   // 2 stages * 12544 words * 4 B; m tile 128*132*4=67584 fits

// ---------------- scratch ----------------
__device__ float g_h2[NN * H];
__device__ __half g_h16[NN * H];
__device__ __half g_tmp16[NN * H];
__device__ __half g_D16[NN * H];
__device__ __half g_mean16[NN * H];
__device__ __half g_std16[NN * H];
__device__ __half g_mn16[NN * H];
__device__ __half g_mx16[NN * H];
__device__ __half g_ea16[NE * 32];
__device__ float g_bsum[NN * H];
__device__ float g_bsq[NN * H];
__device__ float g_bmn[NN * H];
__device__ float g_bmx[NN * H];
__device__ int   g_cnt[NN];
__device__ int   g_start[NN + 1];
__device__ int   g_cursor[NN];
__device__ int   g_part[SCAN_B];
__device__ int   g_psrc[NE];
__device__ int   g_pdst[NE];
__device__ int   g_peid[NE];
__device__ int   g_blist[NN];
__device__ int   g_bcnt;
__device__ float g_amp[NN];
__device__ float g_iamp[NN];
__device__ unsigned g_WsrcH[NL * KP_EDGE * H];
__device__ unsigned g_postWH[NL * KP_POST * H];
__device__ unsigned g_linWH[NL * KP_LIN * H];
__device__ unsigned g_dWH[NL * KP_D * H];
__device__ float g_T1[NL * H * H];
__device__ float g_W2[NL * 16 * H];
__device__ float g_biasmL[NL * H];
__device__ float g_bn[2 * H];
__device__ float g_pool[NGR * H];
__device__ float g_z[NGR * 64];

// ---------------- helpers ----------------
__device__ __forceinline__ void atomicMaxF(float* a, float v) {
    if (v >= 0.f) atomicMax((int*)a, __float_as_int(v));
    else          atomicMin((unsigned int*)a, __float_as_uint(v));
}
__device__ __forceinline__ void atomicMinF(float* a, float v) {
    if (v >= 0.f) atomicMin((int*)a, __float_as_int(v));
    else          atomicMax((unsigned int*)a, __float_as_uint(v));
}
__device__ __forceinline__ void cp16(void* smem, const void* g) {
    unsigned sa = (unsigned)__cvta_generic_to_shared(smem);
    asm volatile("cp.async.cg.shared.global [%0], [%1], 16;\n" :: "r"(sa), "l"(g));
}
#define CP_COMMIT() asm volatile("cp.async.commit_group;\n" ::: "memory")
#define CP_WAIT1()  asm volatile("cp.async.wait_group 1;\n" ::: "memory")
#define CP_WAIT0()  asm volatile("cp.async.wait_group 0;\n" ::: "memory")

__device__ __forceinline__ int map_t32(int t) {
    return (t < 16) ? 36 + t : (t < 32) ? 20 + (t - 16) : (t - 32);
}
__device__ __forceinline__ unsigned ld_a(const unsigned* As, int r, int slot, int c) {
    return As[r * 16 + ((slot ^ ((r >> 1) & 3)) << 2) + c];
}

__device__ __forceinline__ void mma_tile32(const unsigned* As, const unsigned* Ws,
                                           float (&acc)[4][4][4], int lane,
                                           int wm, int wn)
{
#pragma unroll
    for (int ks = 0; ks < 2; ks++) {
        unsigned b0[4], b1[4];
        int bk = ks * 8 + (lane & 3);
        int bn = wn * 32 + (lane >> 2);
#pragma unroll
        for (int nt = 0; nt < 4; nt++) {
            b0[nt] = Ws[bk * WS_STRIDE + bn + nt * 8];
            b1[nt] = Ws[(bk + 4) * WS_STRIDE + bn + nt * 8];
        }
#pragma unroll
        for (int mt = 0; mt < 4; mt++) {
            int r0 = wm * 64 + mt * 16 + (lane >> 2);
            int r1 = r0 + 8;
            int c = lane & 3;
            unsigned a0 = ld_a(As, r0, ks * 2,     c);
            unsigned a1 = ld_a(As, r1, ks * 2,     c);
            unsigned a2 = ld_a(As, r0, ks * 2 + 1, c);
            unsigned a3 = ld_a(As, r1, ks * 2 + 1, c);
#pragma unroll
            for (int nt = 0; nt < 4; nt++) {
                asm volatile(
                    "mma.sync.aligned.m16n8k16.row.col.f32.f16.f16.f32 "
                    "{%0,%1,%2,%3}, {%4,%5,%6,%7}, {%8,%9}, {%0,%1,%2,%3};"
                    : "+f"(acc[mt][nt][0]), "+f"(acc[mt][nt][1]),
                      "+f"(acc[mt][nt][2]), "+f"(acc[mt][nt][3])
                    : "r"(a0), "r"(a1), "r"(a2), "r"(a3),
                      "r"(b0[nt]), "r"(b1[nt]));
            }
        }
    }
}

// tf32 path for emb GEMM
__device__ __forceinline__ unsigned ld_asf(const float* As, int r, int slot, int c) {
    return __float_as_uint(As[r * 16 + ((slot ^ ((r >> 1) & 3)) << 2) + c]);
}
__device__ __forceinline__ void mma_tile16f(const float* As, const float* Ws,
                                            float (&acc)[4][4][4], int lane,
                                            int wm, int wn)
{
#pragma unroll
    for (int ks = 0; ks < 2; ks++) {
        unsigned b0[4], b1[4];
        int bk = ks * 8 + (lane & 3);
        int bn = wn * 32 + (lane >> 2);
#pragma unroll
        for (int nt = 0; nt < 4; nt++) {
            b0[nt] = __float_as_uint(Ws[bk * WS_STRIDE + bn + nt * 8]);
            b1[nt] = __float_as_uint(Ws[(bk + 4) * WS_STRIDE + bn + nt * 8]);
        }
#pragma unroll
        for (int mt = 0; mt < 4; mt++) {
            int r0 = wm * 64 + mt * 16 + (lane >> 2);
            int r1 = r0 + 8;
            int c = lane & 3;
            unsigned a0 = ld_asf(As, r0, ks * 2,     c);
            unsigned a1 = ld_asf(As, r1, ks * 2,     c);
            unsigned a2 = ld_asf(As, r0, ks * 2 + 1, c);
            unsigned a3 = ld_asf(As, r1, ks * 2 + 1, c);
#pragma unroll
            for (int nt = 0; nt < 4; nt++) {
                asm volatile(
                    "mma.sync.aligned.m16n8k8.row.col.f32.tf32.tf32.f32 "
                    "{%0,%1,%2,%3}, {%4,%5,%6,%7}, {%8,%9}, {%0,%1,%2,%3};"
                    : "+f"(acc[mt][nt][0]), "+f"(acc[mt][nt][1]),
                      "+f"(acc[mt][nt][2]), "+f"(acc[mt][nt][3])
                    : "r"(a0), "r"(a1), "r"(a2), "r"(a3),
                      "r"(b0[nt]), "r"(b1[nt]));
            }
        }
    }
}

// ---------------- batched fp32 GEMM for weight prep ----------------
__global__ __launch_bounds__(256) void gemm128L(
    const float* __restrict__ Ab, size_t aStride,
    const float* __restrict__ Wb, size_t wStride,
    float* __restrict__ Cb, size_t cStride, int M, int K)
{
    const float* A = Ab + blockIdx.y * aStride;
    const float* W = Wb + blockIdx.y * wStride;
    float* C = Cb + blockIdx.y * cStride;
    __shared__ float As[16 * 132];
    __shared__ float Ws[16 * 128];
    int tid = threadIdx.x;
    int m0 = blockIdx.x * 128;
    int trow = tid >> 4, tcol = tid & 15;
    int r8 = trow * 8, c8 = tcol * 8;
    int arow = tid >> 2;
    int ac4 = (tid & 3) * 4;

    float acc[8][8];
#pragma unroll
    for (int i = 0; i < 8; i++)
#pragma unroll
        for (int j = 0; j < 8; j++) acc[i][j] = 0.f;

    for (int k0 = 0; k0 < K; k0 += 16) {
#pragma unroll
        for (int t = 0; t < 2; t++) {
            int r = arow + t * 64;
            int gr = m0 + r;
            float4 v = make_float4(0.f, 0.f, 0.f, 0.f);
            if (gr < M) v = *(const float4*)(A + (size_t)gr * K + k0 + ac4);
            As[(ac4 + 0) * 132 + r] = v.x;
            As[(ac4 + 1) * 132 + r] = v.y;
            As[(ac4 + 2) * 132 + r] = v.z;
            As[(ac4 + 3) * 132 + r] = v.w;
        }
#pragma unroll
        for (int t = 0; t < 2; t++) {
            int f4i = tid + t * 256;
            int wr = f4i >> 5, wc = (f4i & 31) * 4;
            *(float4*)&Ws[wr * 128 + wc] = *(const float4*)(W + (size_t)(k0 + wr) * 128 + wc);
        }
        __syncthreads();
#pragma unroll
        for (int kk = 0; kk < 16; kk++) {
            float4 a0 = *(const float4*)&As[kk * 132 + r8];
            float4 a1 = *(const float4*)&As[kk * 132 + r8 + 4];
            float4 w0 = *(const float4*)&Ws[kk * 128 + c8];
            float4 w1 = *(const float4*)&Ws[kk * 128 + c8 + 4];
            float a[8] = {a0.x, a0.y, a0.z, a0.w, a1.x, a1.y, a1.z, a1.w};
            float w[8] = {w0.x, w0.y, w0.z, w0.w, w1.x, w1.y, w1.z, w1.w};
#pragma unroll
            for (int i = 0; i < 8; i++)
#pragma unroll
                for (int j = 0; j < 8; j++) acc[i][j] += a[i] * w[j];
        }
        __syncthreads();
    }

#pragma unroll
    for (int i = 0; i < 8; i++) {
        int gr = m0 + r8 + i;
        if (gr < M) {
            float4 o0, o1;
            o0.x = acc[i][0]; o0.y = acc[i][1]; o0.z = acc[i][2]; o0.w = acc[i][3];
            o1.x = acc[i][4]; o1.y = acc[i][5]; o1.z = acc[i][6]; o1.w = acc[i][7];
            *(float4*)(C + (size_t)gr * 128 + c8) = o0;
            *(float4*)(C + (size_t)gr * 128 + c8 + 4) = o1;
        }
    }
}

// ---------------- emb GEMM (tf32): writes fp16 h ----------------
__global__ __launch_bounds__(256) void emb_gemmt(
    const float* __restrict__ A, const float* __restrict__ W,
    const float* __restrict__ bias, int K)
{
    __shared__ float As[128 * 16];
    __shared__ float Ws[16 * WS_STRIDE];
    int tid = threadIdx.x;
    int lane = tid & 31, warp = tid >> 5;
    int wm = warp >> 2, wn = warp & 3;
    int m0 = blockIdx.x * 128;
    int arow = tid >> 2;
    int slot = tid & 3;
    float4* As4 = (float4*)As;

    float acc[4][4][4];
#pragma unroll
    for (int a = 0; a < 4; a++)
#pragma unroll
        for (int b = 0; b < 4; b++)
#pragma unroll
            for (int c = 0; c < 4; c++) acc[a][b][c] = 0.f;

    for (int k0 = 0; k0 < K; k0 += 16) {
#pragma unroll
        for (int t = 0; t < 2; t++) {
            int r = arow + t * 64;
            int gr = m0 + r;
            float4 v = make_float4(0.f, 0.f, 0.f, 0.f);
            if (gr < NN) v = *(const float4*)(A + (size_t)gr * K + k0 + slot * 4);
            As4[r * 4 + (slot ^ ((r >> 1) & 3))] = v;
        }
#pragma unroll
        for (int t = 0; t < 2; t++) {
            int f4i = tid + t * 256;
            int wr = f4i >> 5, wc = (f4i & 31) * 4;
            *(float4*)&Ws[wr * WS_STRIDE + wc] =
                *(const float4*)(W + (size_t)(k0 + wr) * 128 + wc);
        }
        __syncthreads();
        mma_tile16f(As, Ws, acc, lane, wm, wn);
        __syncthreads();
    }

#pragma unroll
    for (int mt = 0; mt < 4; mt++) {
        int r0 = m0 + wm * 64 + mt * 16 + (lane >> 2);
#pragma unroll
        for (int nt = 0; nt < 4; nt++) {
            int col = wn * 32 + nt * 8 + 2 * (lane & 3);
            float b0 = bias[col], b1 = bias[col + 1];
            if (r0 < NN)
                *(__half2*)(g_h16 + (size_t)r0 * 128 + col) =
                    __floats2half2_rn(acc[mt][nt][0] + b0, acc[mt][nt][1] + b1);
            if (r0 + 8 < NN)
                *(__half2*)(g_h16 + (size_t)(r0 + 8) * 128 + col) =
                    __floats2half2_rn(acc[mt][nt][2] + b0, acc[mt][nt][3] + b1);
        }
    }
}

// ---------------- D GEMM (layer 0) ----------------
__global__ __launch_bounds__(256) void d_gemm(
    const unsigned* __restrict__ Wp, const float* __restrict__ bias)
{
    __shared__ unsigned As2[128 * 16];
    __shared__ unsigned Ws2[16 * WS_STRIDE];
    int tid = threadIdx.x;
    int lane = tid & 31, warp = tid >> 5;
    int wm = warp >> 2, wn = warp & 3;
    int m0 = blockIdx.x * 128;
    int arow = tid >> 2;
    int slot = tid & 3;
    uint4* As4 = (uint4*)As2;

    float acc[4][4][4];
#pragma unroll
    for (int a = 0; a < 4; a++)
#pragma unroll
        for (int b = 0; b < 4; b++)
#pragma unroll
            for (int c = 0; c < 4; c++) acc[a][b][c] = 0.f;

    for (int kt = 0; kt < 4; kt++) {
#pragma unroll
        for (int t = 0; t < 2; t++) {
            int r = arow + t * 64;
            int gr = m0 + r;
            uint4 v = make_uint4(0, 0, 0, 0);
            if (gr < NN)
                v = *(const uint4*)(g_h16 + (size_t)gr * 128 + kt * 32 + slot * 8);
            As4[r * 4 + (slot ^ ((r >> 1) & 3))] = v;
        }
#pragma unroll
        for (int t = 0; t < 2; t++) {
            int f4i = tid + t * 256;
            int wr = f4i >> 5, wc = (f4i & 31) * 4;
            *(uint4*)&Ws2[wr * WS_STRIDE + wc] =
                *(const uint4*)(Wp + (size_t)(kt * 16 + wr) * 128 + wc);
        }
        __syncthreads();
        mma_tile32(As2, Ws2, acc, lane, wm, wn);
        __syncthreads();
    }

#pragma unroll
    for (int mt = 0; mt < 4; mt++) {
        int r0 = m0 + wm * 64 + mt * 16 + (lane >> 2);
#pragma unroll
        for (int nt = 0; nt < 4; nt++) {
            int col = wn * 32 + nt * 8 + 2 * (lane & 3);
            float b0 = bias[col], b1 = bias[col + 1];
            if (r0 < NN)
                *(__half2*)(g_D16 + (size_t)r0 * 128 + col) =
                    __floats2half2_rn(acc[mt][nt][0] + b0, acc[mt][nt][1] + b1);
            if (r0 + 8 < NN)
                *(__half2*)(g_D16 + (size_t)(r0 + 8) * 128 + col) =
                    __floats2half2_rn(acc[mt][nt][2] + b0, acc[mt][nt][3] + b1);
        }
    }
}

// ---------------- fused BN+ReLU + next-layer D GEMM ----------------
__global__ __launch_bounds__(256) void bn_d_gemm(
    const float* __restrict__ gamma, const float* __restrict__ beta,
    const unsigned* __restrict__ Wp, const float* __restrict__ dbias, int doD)
{
    __shared__ unsigned As2[128 * 16];
    __shared__ unsigned Ws2[16 * WS_STRIDE];
    __shared__ float ssc[128], sof[128];
    int tid = threadIdx.x;
    int lane = tid & 31, warp = tid >> 5;
    int wm = warp >> 2, wn = warp & 3;
    int m0 = blockIdx.x * 128;
    int arow = tid >> 2;
    int slot = tid & 3;
    uint4* As4 = (uint4*)As2;

    if (tid < 128) {
        const float invN = 1.f / (float)NN;
        float mu = g_bn[tid] * invN;
        float var = g_bn[128 + tid] * invN - mu * mu;
        float sc = rsqrtf(var + EPS_BN) * gamma[tid];
        ssc[tid] = sc;
        sof[tid] = beta[tid] - mu * sc;
    }
    __syncthreads();

    float acc[4][4][4];
#pragma unroll
    for (int a = 0; a < 4; a++)
#pragma unroll
        for (int b = 0; b < 4; b++)
#pragma unroll
            for (int c = 0; c < 4; c++) acc[a][b][c] = 0.f;

    for (int kt = 0; kt < 4; kt++) {
#pragma unroll
        for (int t = 0; t < 2; t++) {
            int r = arow + t * 64;
            int gr = m0 + r;
            int c0 = kt * 32 + slot * 8;
            uint4 hv = make_uint4(0, 0, 0, 0);
            if (gr < NN) {
                float4 x0 = *(const float4*)(g_h2 + (size_t)gr * 128 + c0);
                float4 x1 = *(const float4*)(g_h2 + (size_t)gr * 128 + c0 + 4);
                float y0 = fmaxf(x0.x * ssc[c0 + 0] + sof[c0 + 0], 0.f);
                float y1 = fmaxf(x0.y * ssc[c0 + 1] + sof[c0 + 1], 0.f);
                float y2 = fmaxf(x0.z * ssc[c0 + 2] + sof[c0 + 2], 0.f);
                float y3 = fmaxf(x0.w * ssc[c0 + 3] + sof[c0 + 3], 0.f);
                float y4 = fmaxf(x1.x * ssc[c0 + 4] + sof[c0 + 4], 0.f);
                float y5 = fmaxf(x1.y * ssc[c0 + 5] + sof[c0 + 5], 0.f);
                float y6 = fmaxf(x1.z * ssc[c0 + 6] + sof[c0 + 6], 0.f);
                float y7 = fmaxf(x1.w * ssc[c0 + 7] + sof[c0 + 7], 0.f);
                __half2 p0 = __floats2half2_rn(y0, y1);
                __half2 p1 = __floats2half2_rn(y2, y3);
                __half2 p2 = __floats2half2_rn(y4, y5);
                __half2 p3 = __floats2half2_rn(y6, y7);
                hv = make_uint4(*(unsigned*)&p0, *(unsigned*)&p1,
                                *(unsigned*)&p2, *(unsigned*)&p3);
                *(uint4*)(g_h16 + (size_t)gr * 128 + c0) = hv;
            }
            As4[r * 4 + (slot ^ ((r >> 1) & 3))] = hv;
        }
        if (doD) {
#pragma unroll
            for (int t = 0; t < 2; t++) {
                int f4i = tid + t * 256;
                int wr = f4i >> 5, wc = (f4i & 31) * 4;
                *(uint4*)&Ws2[wr * WS_STRIDE + wc] =
                    *(const uint4*)(Wp + (size_t)(kt * 16 + wr) * 128 + wc);
            }
        }
        __syncthreads();
        if (doD) mma_tile32(As2, Ws2, acc, lane, wm, wn);
        __syncthreads();
    }

    if (doD) {
#pragma unroll
        for (int mt = 0; mt < 4; mt++) {
            int r0 = m0 + wm * 64 + mt * 16 + (lane >> 2);
#pragma unroll
            for (int nt = 0; nt < 4; nt++) {
                int col = wn * 32 + nt * 8 + 2 * (lane & 3);
                float b0 = dbias[col], b1 = dbias[col + 1];
                if (r0 < NN)
                    *(__half2*)(g_D16 + (size_t)r0 * 128 + col) =
                        __floats2half2_rn(acc[mt][nt][0] + b0, acc[mt][nt][1] + b1);
                if (r0 + 8 < NN)
                    *(__half2*)(g_D16 + (size_t)(r0 + 8) * 128 + col) =
                        __floats2half2_rn(acc[mt][nt][2] + b0, acc[mt][nt][3] + b1);
            }
        }
    }
}

// ---------------- lin GEMM fp16 with fused BN stats ----------------
__global__ __launch_bounds__(256) void lin_gemm_bn(
    const unsigned* __restrict__ Wp, const float* __restrict__ bias)
{
    __shared__ unsigned As2[128 * 16];
    __shared__ unsigned Ws2[16 * WS_STRIDE];
    __shared__ float sbn[256];
    int tid = threadIdx.x;
    int lane = tid & 31, warp = tid >> 5;
    int wm = warp >> 2, wn = warp & 3;
    int m0 = blockIdx.x * 128;
    int arow = tid >> 2;
    int slot = tid & 3;
    uint4* As4 = (uint4*)As2;
    sbn[tid] = 0.f;

    float acc[4][4][4];
#pragma unroll
    for (int a = 0; a < 4; a++)
#pragma unroll
        for (int b = 0; b < 4; b++)
#pragma unroll
            for (int c = 0; c < 4; c++) acc[a][b][c] = 0.f;

    for (int kt = 0; kt < 4; kt++) {
#pragma unroll
        for (int t = 0; t < 2; t++) {
            int r = arow + t * 64;
            int gr = m0 + r;
            uint4 v = make_uint4(0, 0, 0, 0);
            if (gr < NN)
                v = *(const uint4*)(g_tmp16 + (size_t)gr * 128 + kt * 32 + slot * 8);
            As4[r * 4 + (slot ^ ((r >> 1) & 3))] = v;
        }
#pragma unroll
        for (int t = 0; t < 2; t++) {
            int f4i = tid + t * 256;
            int wr = f4i >> 5, wc = (f4i & 31) * 4;
            *(uint4*)&Ws2[wr * WS_STRIDE + wc] =
                *(const uint4*)(Wp + (size_t)(kt * 16 + wr) * 128 + wc);
        }
        __syncthreads();
        mma_tile32(As2, Ws2, acc, lane, wm, wn);
        __syncthreads();
    }

    float csum[4][2] = {}, csq[4][2] = {};
#pragma unroll
    for (int mt = 0; mt < 4; mt++) {
        int r0 = m0 + wm * 64 + mt * 16 + (lane >> 2);
#pragma unroll
        for (int nt = 0; nt < 4; nt++) {
            int col = wn * 32 + nt * 8 + 2 * (lane & 3);
            float b0 = bias[col], b1 = bias[col + 1];
            float v0 = acc[mt][nt][0] + b0, v1 = acc[mt][nt][1] + b1;
            float v2 = acc[mt][nt][2] + b0, v3 = acc[mt][nt][3] + b1;
            if (r0 < NN) {
                *(float2*)(g_h2 + (size_t)r0 * 128 + col) = make_float2(v0, v1);
                csum[nt][0] += v0; csq[nt][0] += v0 * v0;
                csum[nt][1] += v1; csq[nt][1] += v1 * v1;
            }
            if (r0 + 8 < NN) {
                *(float2*)(g_h2 + (size_t)(r0 + 8) * 128 + col) = make_float2(v2, v3);
                csum[nt][0] += v2; csq[nt][0] += v2 * v2;
                csum[nt][1] += v3; csq[nt][1] += v3 * v3;
            }
        }
    }
#pragma unroll
    for (int nt = 0; nt < 4; nt++)
#pragma unroll
        for (int j = 0; j < 2; j++) {
            float s = csum[nt][j], q = csq[nt][j];
            s += __shfl_down_sync(0xffffffffu, s, 16);
            s += __shfl_down_sync(0xffffffffu, s, 8);
            s += __shfl_down_sync(0xffffffffu, s, 4);
            q += __shfl_down_sync(0xffffffffu, q, 16);
            q += __shfl_down_sync(0xffffffffu, q, 8);
            q += __shfl_down_sync(0xffffffffu, q, 4);
            if (lane < 4) {
                int col = wn * 32 + nt * 8 + 2 * lane + j;
                atomicAdd(&sbn[col], s);
                atomicAdd(&sbn[128 + col], q);
            }
        }
    __syncthreads();
    atomicAdd(&g_bn[tid], sbn[tid]);
}

// ---------------- fused edge GEMM (fp16, 256 edges/block) + aggregation ----------------
__global__ __launch_bounds__(512) void edge_agg(const unsigned* __restrict__ Wp)
{
    extern __shared__ float s_dyn[];
    unsigned* su = (unsigned*)s_dyn;
    float* mt_ = s_dyn;                      // [128 x 132] fp32 tile, reused per half
    __shared__ int sdst[256], ssrc[256], seid[256];

    int tid = threadIdx.x;
    int lane = tid & 31, warp = tid >> 5;    // 0..15
    int wm2 = warp >> 2, wn = warp & 3;      // wm2 0..3 over 256 rows
    int half = wm2 >> 1, wmL = wm2 & 1;
    int e0 = blockIdx.x * 256;
    int arow = tid >> 2;                     // 0..127
    int slot = tid & 3;

    if (tid < 256) {
        int p = e0 + tid;
        sdst[tid] = g_pdst[p];
        ssrc[tid] = g_psrc[p];
        seid[tid] = g_peid[p];
    }
    __syncthreads();

    float acc[4][4][4];
#pragma unroll
    for (int a = 0; a < 4; a++)
#pragma unroll
        for (int b = 0; b < 4; b++)
#pragma unroll
            for (int c = 0; c < 4; c++) acc[a][b][c] = 0.f;

    auto a_ptr = [&](int st, int j, int h) { return su + st * STAGE_W2 + j * SUB_W2 + h * 2048; };
    auto w_ptr = [&](int st, int j) { return su + st * STAGE_W2 + j * SUB_W2 + 4096; };

    auto load_sub = [&](int kt, int st, int j) {   // kt in 0..4 (32-k tiles)
#pragma unroll
        for (int h = 0; h < 2; h++) {
            int r = h * 128 + arow;
            const __half* src;
            if (kt < 4) src = g_h16 + (size_t)ssrc[r] * H + kt * 32 + slot * 8;
            else        src = g_ea16 + (size_t)seid[r] * 32 + slot * 8;
            cp16(&a_ptr(st, j, h)[arow * 16 + ((slot ^ ((arow >> 1) & 3)) << 2)], src);
        }
        {
            int wr = tid >> 5, wc = (tid & 31) * 4;
            cp16(&w_ptr(st, j)[wr * WS_STRIDE + wc], Wp + (size_t)(kt * 16 + wr) * 128 + wc);
        }
    };

    load_sub(0, 0, 0); load_sub(1, 0, 1);
    CP_COMMIT();
    for (int p = 0; p < 3; p++) {            // 5 tiles as 2 pairs + 1
        if (p < 2) {
            int st = (p + 1) & 1;
            load_sub(2 * p + 2, st, 0);
            if (2 * p + 3 < 5) load_sub(2 * p + 3, st, 1);
            CP_COMMIT(); CP_WAIT1();
        } else CP_WAIT0();
        __syncthreads();
        int st = p & 1;
        mma_tile32(a_ptr(st, 0, half), w_ptr(st, 0), acc, lane, wmL, wn);
        if (2 * p + 1 < 5)
            mma_tile32(a_ptr(st, 1, half), w_ptr(st, 1), acc, lane, wmL, wn);
        __syncthreads();
    }

    // two half-tiles: write v to SMEM, segmented reduce with 128-aligned chunks
    for (int h = 0; h < 2; h++) {
        __syncthreads();
        if (half == h) {
#pragma unroll
            for (int mt2 = 0; mt2 < 4; mt2++) {
                int r0 = wmL * 64 + mt2 * 16 + (lane >> 2);
#pragma unroll
                for (int nt = 0; nt < 4; nt++) {
                    int col = wn * 32 + nt * 8 + 2 * (lane & 3);
                    *(float2*)&mt_[r0 * 132 + col] =
                        make_float2(acc[mt2][nt][0], acc[mt2][nt][1]);
                    *(float2*)&mt_[(r0 + 8) * 132 + col] =
                        make_float2(acc[mt2][nt][2], acc[mt2][nt][3]);
                }
            }
        }
        __syncthreads();

        int c = tid & 127, g4 = tid >> 7;    // 4 groups
        int base = h * 128;
        int e0h = e0 + base;
        int nfirst = sdst[base], nlast = sdst[base + 127];
        for (int n = nfirst + g4; n <= nlast; n += 4) {
            int s = g_start[n], e = g_start[n + 1];
            if (s == e) continue;
            int lo = max(s, e0h), hi = min(e, e0h + 128);
            if (lo >= hi) continue;
            float sumv = 0.f, sq = 0.f, mn = INFINITY, mx = -INFINITY;
            for (int r = lo - e0h; r < hi - e0h; r++) {
                float v = mt_[r * 132 + c];
                sumv += v; sq += v * v;
                mn = fminf(mn, v); mx = fmaxf(mx, v);
            }
            size_t idx = (size_t)n * H + c;
            if (s >= e0h && e <= e0h + 128) {
                float Dv = __half2float(g_D16[idx]);
                float degc = (float)(e - s);
                float inv = 1.f / degc;
                float mean = sumv * inv;
                float var = fmaxf(sq * inv - mean * mean, 0.f);
                g_mean16[idx] = __float2half_rn(Dv + mean);
                g_std16[idx] = __float2half_rn(sqrtf(var + EPS_STD));
                g_mn16[idx] = __float2half_rn(Dv + mn);
                g_mx16[idx] = __float2half_rn(Dv + mx);
            } else {
                atomicAdd(&g_bsum[idx], sumv);
                atomicAdd(&g_bsq[idx], sq);
                atomicMinF(&g_bmn[idx], mn);
                atomicMaxF(&g_bmx[idx], mx);
            }
        }
    }
}

// ---------------- boundary helpers (128-edge granularity, unchanged) ----------------
__global__ void bnd_build() {
    int n = blockIdx.x * blockDim.x + threadIdx.x;
    if (n >= NN) return;
    int s = g_start[n], e = g_start[n + 1];
    bool bnd = (s == e) || ((s >> 7) != ((e - 1) >> 7));
    if (bnd) {
        int p = atomicAdd(&g_bcnt, 1);
        g_blist[p] = n;
    }
}
__global__ void init_bnd() {
    int B = g_bcnt;
    int total = B * 128;
    for (int i = blockIdx.x * blockDim.x + threadIdx.x; i < total;
         i += gridDim.x * blockDim.x) {
        int n = g_blist[i >> 7];
        int c = i & 127;
        size_t idx = (size_t)n * H + c;
        g_bsum[idx] = 0.f; g_bsq[idx] = 0.f;
        g_bmn[idx] = INFINITY; g_bmx[idx] = -INFINITY;
    }
}
__global__ void fin_bnd() {
    int B = g_bcnt;
    int total = B * 128;
    for (int i = blockIdx.x * blockDim.x + threadIdx.x; i < total;
         i += gridDim.x * blockDim.x) {
        int n = g_blist[i >> 7];
        int c = i & 127;
        size_t idx = (size_t)n * H + c;
        int cnt = g_start[n + 1] - g_start[n];
        if (cnt == 0) {
            g_mean16[idx] = __float2half_rn(0.f);
            g_std16[idx] = __float2half_rn(sqrtf(EPS_STD));
            g_mn16[idx] = __float2half_rn(0.f);
            g_mx16[idx] = __float2half_rn(0.f);
        } else {
            float Dv = __half2float(g_D16[idx]);
            float inv = 1.f / (float)cnt;
            float mean = g_bsum[idx] * inv;
            float var = fmaxf(g_bsq[idx] * inv - mean * mean, 0.f);
            g_mean16[idx] = __float2half_rn(Dv + mean);
            g_std16[idx] = __float2half_rn(sqrtf(var + EPS_STD));
            g_mn16[idx] = __float2half_rn(Dv + g_bmn[idx]);
            g_mx16[idx] = __float2half_rn(Dv + g_bmx[idx]);
        }
    }
}

// ---------------- post-NN gather-GEMM fp16 (256 nodes/block) ----------------
__global__ __launch_bounds__(512) void post_gemmt(const unsigned* __restrict__ Wp,
                                                  const float* __restrict__ bias)
{
    extern __shared__ float s_dyn[];
    unsigned* su = (unsigned*)s_dyn;
    int tid = threadIdx.x;
    int lane = tid & 31, warp = tid >> 5;
    int wm2 = warp >> 2, wn = warp & 3;
    int half = wm2 >> 1, wmL = wm2 & 1;
    int n0 = blockIdx.x * 256;
    int arow = tid >> 2;
    int slot = tid & 3;

    float sa[8], si2[8];
#pragma unroll
    for (int mt = 0; mt < 4; mt++)
#pragma unroll
        for (int hh = 0; hh < 2; hh++) {
            int n = n0 + wm2 * 64 + mt * 16 + (lane >> 2) + hh * 8;
            if (n >= NN) n = NN - 1;
            float a = g_amp[n], ia = g_iamp[n];
            sa[mt * 2 + hh] = a;
            si2[mt * 2 + hh] = ia * ia;
        }

    float acc[4][4][4];
#pragma unroll
    for (int a = 0; a < 4; a++)
#pragma unroll
        for (int b = 0; b < 4; b++)
#pragma unroll
            for (int c = 0; c < 4; c++) acc[a][b][c] = 0.f;

    auto a_ptr = [&](int st, int j, int h) { return su + st * STAGE_W2 + j * SUB_W2 + h * 2048; };
    auto w_ptr = [&](int st, int j) { return su + st * STAGE_W2 + j * SUB_W2 + 4096; };

    auto load_sub = [&](int t, int st, int j) {
        int kt = map_t32(t);
        int b = kt >> 2;
        const __half* srcb;
        if (b == 0) srcb = g_h16;
        else {
            int a = (b - 1) & 3;
            srcb = (a == 0) ? g_mean16 : (a == 1) ? g_mn16 : (a == 2) ? g_mx16 : g_std16;
        }
        int kk0 = (kt & 3) * 32;
#pragma unroll
        for (int h = 0; h < 2; h++) {
            int n = n0 + h * 128 + arow;
            if (n >= NN) n = NN - 1;
            cp16(&a_ptr(st, j, h)[arow * 16 + ((slot ^ ((arow >> 1) & 3)) << 2)],
                 srcb + (size_t)n * H + kk0 + slot * 8);
        }
        {
            int wr = tid >> 5, wc = (tid & 31) * 4;
            cp16(&w_ptr(st, j)[wr * WS_STRIDE + wc], Wp + (size_t)(kt * 16 + wr) * 128 + wc);
        }
    };

    load_sub(0, 0, 0); load_sub(1, 0, 1);
    CP_COMMIT();
    for (int p = 0; p < 26; p++) {
        if (p < 25) {
            int st = (p + 1) & 1;
            load_sub(2 * p + 2, st, 0);
            load_sub(2 * p + 3, st, 1);
            CP_COMMIT(); CP_WAIT1();
        } else CP_WAIT0();
        __syncthreads();
        int st = p & 1;
        mma_tile32(a_ptr(st, 0, half), w_ptr(st, 0), acc, lane, wmL, wn);
        mma_tile32(a_ptr(st, 1, half), w_ptr(st, 1), acc, lane, wmL, wn);
        __syncthreads();
        if (p == 7) {
#pragma unroll
            for (int mt = 0; mt < 4; mt++)
#pragma unroll
                for (int nt = 0; nt < 4; nt++) {
                    acc[mt][nt][0] *= si2[mt * 2];     acc[mt][nt][1] *= si2[mt * 2];
                    acc[mt][nt][2] *= si2[mt * 2 + 1]; acc[mt][nt][3] *= si2[mt * 2 + 1];
                }
        } else if (p == 15) {
#pragma unroll
            for (int mt = 0; mt < 4; mt++)
#pragma unroll
                for (int nt = 0; nt < 4; nt++) {
                    acc[mt][nt][0] *= sa[mt * 2];     acc[mt][nt][1] *= sa[mt * 2];
                    acc[mt][nt][2] *= sa[mt * 2 + 1]; acc[mt][nt][3] *= sa[mt * 2 + 1];
                }
        }
    }

#pragma unroll
    for (int mt = 0; mt < 4; mt++) {
        int r0 = n0 + wm2 * 64 + mt * 16 + (lane >> 2);
#pragma unroll
        for (int nt = 0; nt < 4; nt++) {
            int col = wn * 32 + nt * 8 + 2 * (lane & 3);
            float b0 = bias[col], b1 = bias[col + 1];
            if (r0 < NN)
                *(__half2*)(g_tmp16 + (size_t)r0 * 128 + col) =
                    __floats2half2_rn(acc[mt][nt][0] + b0, acc[mt][nt][1] + b1);
            if (r0 + 8 < NN)
                *(__half2*)(g_tmp16 + (size_t)(r0 + 8) * 128 + col) =
                    __floats2half2_rn(acc[mt][nt][2] + b0, acc[mt][nt][3] + b1);
        }
    }
}

// ---------------- batched packing / conversion ----------------
__global__ void pack_dL(const float* __restrict__ preW) {
    int idx = blockIdx.x * blockDim.x + threadIdx.x;
    if (idx >= NL * KP_D * 128) return;
    int l = idx / (KP_D * 128);
    int r = idx - l * (KP_D * 128);
    int kp = r >> 7, n = r & 127;
    const float* base = preW + (size_t)l * 384 * H;
    float lo = base[(size_t)(2 * kp) * H + n];
    float hi = base[(size_t)(2 * kp + 1) * H + n];
    __half2 h = __floats2half2_rn(lo, hi);
    g_dWH[idx] = *(unsigned*)&h;
}
__global__ void pack_eL(const float* __restrict__ preW) {
    int idx = blockIdx.x * blockDim.x + threadIdx.x;
    if (idx >= NL * KP_EDGE * 128) return;
    int l = idx / (KP_EDGE * 128);
    int r = idx - l * (KP_EDGE * 128);
    int kp = r >> 7, n = r & 127;
    float v[2];
#pragma unroll
    for (int j = 0; j < 2; j++) {
        int k = 2 * kp + j;
        if (k < 128)      v[j] = preW[(size_t)l * 384 * H + (size_t)(128 + k) * H + n];
        else if (k < 144) v[j] = g_W2[(size_t)l * 16 * H + (size_t)(k - 128) * H + n];
        else              v[j] = 0.f;
    }
    __half2 h = __floats2half2_rn(v[0], v[1]);
    g_WsrcH[idx] = *(unsigned*)&h;
}
__global__ void pack_genL(const float* __restrict__ src, size_t strideL,
                          unsigned* __restrict__ out, int kpairs, int kmax) {
    int idx = blockIdx.x * blockDim.x + threadIdx.x;
    if (idx >= NL * kpairs * 128) return;
    int l = idx / (kpairs * 128);
    int r = idx - l * (kpairs * 128);
    int kp = r >> 7, n = r & 127;
    const float* base = src + (size_t)l * strideL;
    float lo = (2 * kp < kmax) ? base[(size_t)(2 * kp) * 128 + n] : 0.f;
    float hi = (2 * kp + 1 < kmax) ? base[(size_t)(2 * kp + 1) * 128 + n] : 0.f;
    __half2 h = __floats2half2_rn(lo, hi);
    out[idx] = *(unsigned*)&h;
}
__global__ void ea_pack(const float* __restrict__ ea) {
    int idx = blockIdx.x * blockDim.x + threadIdx.x;
    if (idx >= NE * 32) return;
    int e = idx >> 5, j = idx & 31;
    g_ea16[idx] = __float2half_rn(j < 16 ? ea[(size_t)e * 16 + j] : 0.f);
}
__global__ void biasm_kL(const float* __restrict__ be, const float* __restrict__ ebB,
                         const float* __restrict__ preW, const float* __restrict__ pbB) {
    int l = blockIdx.x;
    int j = threadIdx.x;
    const float* T1 = g_T1 + (size_t)l * H * H;
    const float* P2 = preW + (size_t)l * 384 * H + 256 * H;
    float s = pbB[l * H + j];
    for (int k = 0; k < H; k++) s += be[k] * T1[k * H + j];
    for (int k = 0; k < H; k++) s += ebB[l * H + k] * P2[k * H + j];
    g_biasmL[l * H + j] = s;
}

// ---------------- sort / scan ----------------
__global__ void deg_count(const int* __restrict__ dstI) {
    int e = blockIdx.x * blockDim.x + threadIdx.x;
    if (e < NE) atomicAdd(&g_cnt[dstI[e]], 1);
}
__global__ __launch_bounds__(256) void scan1() {
    int b = blockIdx.x, t = threadIdx.x;
    int n = b * CHUNK + t;
    int v = (t < CHUNK && n < NN) ? g_cnt[n] : 0;
    int lane = t & 31, wid = t >> 5;
    int x = v;
#pragma unroll
    for (int off = 1; off < 32; off <<= 1) {
        int u = __shfl_up_sync(0xffffffffu, x, off);
        if (lane >= off) x += u;
    }
    __shared__ int wsum[8];
    if (lane == 31) wsum[wid] = x;
    __syncthreads();
    if (t == 0) {
        int r = 0;
#pragma unroll
        for (int i = 0; i < 8; i++) { int tmp = wsum[i]; wsum[i] = r; r += tmp; }
        g_part[b] = r;
    }
    __syncthreads();
    int excl = x - v + wsum[wid];
    if (t < CHUNK && n < NN) g_start[n] = excl;
}
__global__ void scan2() {
    int t = threadIdx.x;
    int v = g_part[t];
    int lane = t & 31, wid = t >> 5;
    int x = v;
#pragma unroll
    for (int off = 1; off < 32; off <<= 1) {
        int u = __shfl_up_sync(0xffffffffu, x, off);
        if (lane >= off) x += u;
    }
    __shared__ int wsum[4];
    if (lane == 31) wsum[wid] = x;
    __syncthreads();
    if (t == 0) {
        int r = 0;
#pragma unroll
        for (int i = 0; i < 4; i++) { int tmp = wsum[i]; wsum[i] = r; r += tmp; }
    }
    __syncthreads();
    g_part[t] = x - v + wsum[wid];
}
__global__ void scan3() {
    int n = blockIdx.x * blockDim.x + threadIdx.x;
    if (n < NN) {
        int s = g_start[n] + g_part[n / CHUNK];
        g_start[n] = s;
        g_cursor[n] = s;
    }
    if (n == 0) g_start[NN] = NE;
}
__global__ void scatter_k(const int* __restrict__ srcI, const int* __restrict__ dstI) {
    int e = blockIdx.x * blockDim.x + threadIdx.x;
    if (e >= NE) return;
    int d = dstI[e];
    int p = atomicAdd(&g_cursor[d], 1);
    g_psrc[p] = srcI[e];
    g_pdst[p] = d;
    g_peid[p] = e;
}
__global__ void amp_k() {
    int n = blockIdx.x * blockDim.x + threadIdx.x;
    if (n >= NN) return;
    float degc = fmaxf((float)g_cnt[n], 1.f);
    float a = logf(degc + 1.f) / AVG_LOG;
    g_amp[n] = a;
    g_iamp[n] = 1.f / a;
}

// ---------------- pool / head ----------------
__global__ void pool_k(const int* __restrict__ batch) {
    int c = threadIdx.x;
    int start = blockIdx.x * 256;
    int end = min(start + 256, NN);
    if (start >= NN) return;
    float acc = 0.f;
    int cur = batch[start];
    for (int n = start; n < end; n++) {
        int g = batch[n];
        if (g != cur) { atomicAdd(&g_pool[cur * H + c], acc); acc = 0.f; cur = g; }
        acc += __half2float(g_h16[(size_t)n * H + c]);
    }
    atomicAdd(&g_pool[cur * H + c], acc);
}
__global__ void head1_k(const float* __restrict__ W1, const float* __restrict__ b1) {
    int idx = blockIdx.x * blockDim.x + threadIdx.x;
    if (idx >= NGR * 64) return;
    int g = idx >> 6, j = idx & 63;
    float s = b1[j];
    for (int k = 0; k < H; k++) s += g_pool[g * H + k] * W1[k * 64 + j];
    g_z[idx] = fmaxf(s, 0.f);
}
__global__ void head2_k(const float* __restrict__ W2, const float* __restrict__ b2,
                        float* __restrict__ out) {
    int idx = blockIdx.x * blockDim.x + threadIdx.x;
    if (idx >= NGR * NOUT) return;
    int g = idx / NOUT, j = idx % NOUT;
    float s = b2[j];
    for (int k = 0; k < 64; k++) s += g_z[g * 64 + k] * W2[k * NOUT + j];
    out[idx] = s;
}

// ---------------- launch ----------------
extern "C" void kernel_launch(void* const* d_in, const int* in_sizes, int n_in,
                              void* d_out, int out_size)
{
    int iEI = 1, iBatch = 2, iEA = 3;
    if (in_sizes[1] == NE * 16) { iEA = 1; iEI = 2; iBatch = 3; }

    const float* x         = (const float*)d_in[0];
    const int*   edge_index= (const int*)  d_in[iEI];
    const int*   batch     = (const int*)  d_in[iBatch];
    const float* edge_attr = (const float*)d_in[iEA];
    const float* node_emb_W= (const float*)d_in[4];
    const float* node_emb_b= (const float*)d_in[5];
    const float* edge_emb_W= (const float*)d_in[6];
    const float* edge_emb_b= (const float*)d_in[7];
    const float* edge_enc_W= (const float*)d_in[8];
    const float* edge_enc_b= (const float*)d_in[9];
    const float* pre_W     = (const float*)d_in[10];
    const float* pre_b     = (const float*)d_in[11];
    const float* post_W    = (const float*)d_in[12];
    const float* post_b    = (const float*)d_in[13];
    const float* lin_W     = (const float*)d_in[14];
    const float* lin_b     = (const float*)d_in[15];
    const float* bn_gamma  = (const float*)d_in[16];
    const float* bn_beta   = (const float*)d_in[17];
    const float* head1_W   = (const float*)d_in[18];
    const float* head1_b   = (const float*)d_in[19];
    const float* head2_W   = (const float*)d_in[20];
    const float* head2_b   = (const float*)d_in[21];

    const int* srcI = edge_index;
    const int* dstI = edge_index + NE;

    float *p_T1, *p_W2, *p_biasm, *p_bn, *p_pool;
    unsigned *p_wsrcH, *p_postWH, *p_linWH, *p_dWH;
    int *p_cnt, *p_bcnt;
    cudaGetSymbolAddress((void**)&p_T1,     g_T1);
    cudaGetSymbolAddress((void**)&p_W2,     g_W2);
    cudaGetSymbolAddress((void**)&p_wsrcH,  g_WsrcH);
    cudaGetSymbolAddress((void**)&p_postWH, g_postWH);
    cudaGetSymbolAddress((void**)&p_linWH,  g_linWH);
    cudaGetSymbolAddress((void**)&p_dWH,    g_dWH);
    cudaGetSymbolAddress((void**)&p_biasm,  g_biasmL);
    cudaGetSymbolAddress((void**)&p_bn,     g_bn);
    cudaGetSymbolAddress((void**)&p_pool,   g_pool);
    cudaGetSymbolAddress((void**)&p_cnt,    g_cnt);
    cudaGetSymbolAddress((void**)&p_bcnt,   g_bcnt);

    cudaFuncSetAttribute(edge_agg, cudaFuncAttributeMaxDynamicSharedMemorySize, BIG_SMEM2);
    cudaFuncSetAttribute(post_gemmt, cudaFuncAttributeMaxDynamicSharedMemorySize, BIG_SMEM2);

    // sort prep
    cudaMemsetAsync(p_cnt, 0, NN * sizeof(int));
    cudaMemsetAsync(p_bcnt, 0, sizeof(int));
    deg_count<<<(NE + 255) / 256, 256>>>(dstI);
    scan1<<<SCAN_B, 256>>>();
    scan2<<<1, 128>>>();
    emb_gemmt<<<(NN + 127) / 128, 256>>>(x, node_emb_W, node_emb_b, 64);
    scan3<<<(NN + 255) / 256, 256>>>();
    scatter_k<<<(NE + 255) / 256, 256>>>(srcI, dstI);
    amp_k<<<(NN + 255) / 256, 256>>>();
    bnd_build<<<(NN + 255) / 256, 256>>>();
    ea_pack<<<(NE * 32 + 255) / 256, 256>>>(edge_attr);

    // batched weight prep
    gemm128L<<<dim3(1, NL), 256>>>(edge_enc_W, (size_t)H * H,
                                   pre_W + 256 * H, (size_t)384 * H,
                                   p_T1, (size_t)H * H, 128, 128);
    gemm128L<<<dim3(1, NL), 256>>>(edge_emb_W, 0,
                                   p_T1, (size_t)H * H,
                                   p_W2, (size_t)16 * H, 16, 128);
    biasm_kL<<<NL, 128>>>(edge_emb_b, edge_enc_b, pre_W, pre_b);
    pack_dL<<<(NL * KP_D * 128 + 255) / 256, 256>>>(pre_W);
    pack_eL<<<(NL * KP_EDGE * 128 + 255) / 256, 256>>>(pre_W);
    pack_genL<<<(NL * KP_POST * 128 + 255) / 256, 256>>>(post_W, (size_t)13 * H * H,
                                                         p_postWH, KP_POST, 13 * H);
    pack_genL<<<(NL * KP_LIN * 128 + 255) / 256, 256>>>(lin_W, (size_t)H * H,
                                                        p_linWH, KP_LIN, H);

    d_gemm<<<(NN + 127) / 128, 256>>>(p_dWH, p_biasm);

    for (int l = 0; l < NL; l++) {
        init_bnd<<<64, 256>>>();
        edge_agg<<<NE / 256, 512, BIG_SMEM2>>>(p_wsrcH + (size_t)l * KP_EDGE * H);
        fin_bnd<<<64, 256>>>();

        post_gemmt<<<(NN + 255) / 256, 512, BIG_SMEM2>>>(
            p_postWH + (size_t)l * KP_POST * H, post_b + l * H);

        cudaMemsetAsync(p_bn, 0, 2 * H * sizeof(float));
        lin_gemm_bn<<<(NN + 127) / 128, 256>>>(p_linWH + (size_t)l * KP_LIN * H,
                                               lin_b + l * H);
        if (l < NL - 1)
            bn_d_gemm<<<(NN + 127) / 128, 256>>>(bn_gamma + l * H, bn_beta + l * H,
                                                 p_dWH + (size_t)(l + 1) * KP_D * H,
                                                 p_biasm + (l + 1) * H, 1);
        else
            bn_d_gemm<<<(NN + 127) / 128, 256>>>(bn_gamma + l * H, bn_beta + l * H,
                                                 p_dWH, p_biasm, 0);
    }

    cudaMemsetAsync(p_pool, 0, NGR * H * sizeof(float));
    pool_k<<<(NN + 255) / 256, 128>>>(batch);
    head1_k<<<8, 256>>>(head1_W, head1_b);
    head2_k<<<2, 256>>>(head2_W, head2_b, (float*)d_out);
}

// round 14
// speedup vs baseline: 1.1070x; 1.1070x over previous
#include <cuda_runtime.h>
#include <cuda_fp16.h>
#include <math.h>

#define NN 30000
#define NE 480000
#define H 128
#define NL 4
#define NGR 32
#define NOUT 12
#define AVG_LOG 1.38214548f
#define EPS_BN 1e-5f
#define EPS_STD 1e-5f
#define KP_EDGE 80
#define KP_POST 832
#define KP_LIN 64
#define KP_D 64
#define WS_STRIDE 136
#define SCAN_B 128
#define CHUNK 235
#define PAIR_W 8448        // words per pair-stage: A 2x2048 + W 2x2176
#define BIG_SMEM 67584     // edge_agg: 2-stage pipeline / m-tile reuse
#define POST_SMEM 101376   // post_gemmt: 3 pair-stages * 8448 words * 4 B

// ---------------- scratch ----------------
__device__ float g_h2[NN * H];
__device__ __half g_h16[NN * H];
__device__ __half g_tmp16[NN * H];
__device__ __half g_D16[NN * H];
__device__ __half g_mean16[NN * H];
__device__ __half g_std16[NN * H];
__device__ __half g_mn16[NN * H];
__device__ __half g_mx16[NN * H];
__device__ __half g_ea16[NE * 32];
__device__ float g_bsum[NN * H];
__device__ float g_bsq[NN * H];
__device__ float g_bmn[NN * H];
__device__ float g_bmx[NN * H];
__device__ int   g_cnt[NN];
__device__ int   g_start[NN + 1];
__device__ int   g_cursor[NN];
__device__ int   g_part[SCAN_B];
__device__ int   g_psrc[NE];
__device__ int   g_pdst[NE];
__device__ int   g_peid[NE];
__device__ int   g_blist[NN];
__device__ int   g_bcnt;
__device__ float g_amp[NN];
__device__ float g_iamp[NN];
__device__ unsigned g_WsrcH[NL * KP_EDGE * H];
__device__ unsigned g_postWH[NL * KP_POST * H];
__device__ unsigned g_linWH[NL * KP_LIN * H];
__device__ unsigned g_dWH[NL * KP_D * H];
__device__ float g_T1[NL * H * H];
__device__ float g_W2[NL * 16 * H];
__device__ float g_biasmL[NL * H];
__device__ float g_bn[2 * H];
__device__ float g_pool[NGR * H];
__device__ float g_z[NGR * 64];

// ---------------- helpers ----------------
__device__ __forceinline__ void atomicMaxF(float* a, float v) {
    if (v >= 0.f) atomicMax((int*)a, __float_as_int(v));
    else          atomicMin((unsigned int*)a, __float_as_uint(v));
}
__device__ __forceinline__ void atomicMinF(float* a, float v) {
    if (v >= 0.f) atomicMin((int*)a, __float_as_int(v));
    else          atomicMax((unsigned int*)a, __float_as_uint(v));
}
__device__ __forceinline__ void cp16(void* smem, const void* g) {
    unsigned sa = (unsigned)__cvta_generic_to_shared(smem);
    asm volatile("cp.async.cg.shared.global [%0], [%1], 16;\n" :: "r"(sa), "l"(g));
}
#define CP_COMMIT() asm volatile("cp.async.commit_group;\n" ::: "memory")
#define CP_WAIT2()  asm volatile("cp.async.wait_group 2;\n" ::: "memory")
#define CP_WAIT1()  asm volatile("cp.async.wait_group 1;\n" ::: "memory")
#define CP_WAIT0()  asm volatile("cp.async.wait_group 0;\n" ::: "memory")

__device__ __forceinline__ int map_t32(int t) {
    return (t < 16) ? 36 + t : (t < 32) ? 20 + (t - 16) : (t - 32);
}
__device__ __forceinline__ unsigned ld_a(const unsigned* As, int r, int slot, int c) {
    return As[r * 16 + ((slot ^ ((r >> 1) & 3)) << 2) + c];
}

__device__ __forceinline__ void mma_tile32(const unsigned* As, const unsigned* Ws,
                                           float (&acc)[4][4][4], int lane,
                                           int wm, int wn)
{
#pragma unroll
    for (int ks = 0; ks < 2; ks++) {
        unsigned b0[4], b1[4];
        int bk = ks * 8 + (lane & 3);
        int bn = wn * 32 + (lane >> 2);
#pragma unroll
        for (int nt = 0; nt < 4; nt++) {
            b0[nt] = Ws[bk * WS_STRIDE + bn + nt * 8];
            b1[nt] = Ws[(bk + 4) * WS_STRIDE + bn + nt * 8];
        }
#pragma unroll
        for (int mt = 0; mt < 4; mt++) {
            int r0 = wm * 64 + mt * 16 + (lane >> 2);
            int r1 = r0 + 8;
            int c = lane & 3;
            unsigned a0 = ld_a(As, r0, ks * 2,     c);
            unsigned a1 = ld_a(As, r1, ks * 2,     c);
            unsigned a2 = ld_a(As, r0, ks * 2 + 1, c);
            unsigned a3 = ld_a(As, r1, ks * 2 + 1, c);
#pragma unroll
            for (int nt = 0; nt < 4; nt++) {
                asm volatile(
                    "mma.sync.aligned.m16n8k16.row.col.f32.f16.f16.f32 "
                    "{%0,%1,%2,%3}, {%4,%5,%6,%7}, {%8,%9}, {%0,%1,%2,%3};"
                    : "+f"(acc[mt][nt][0]), "+f"(acc[mt][nt][1]),
                      "+f"(acc[mt][nt][2]), "+f"(acc[mt][nt][3])
                    : "r"(a0), "r"(a1), "r"(a2), "r"(a3),
                      "r"(b0[nt]), "r"(b1[nt]));
            }
        }
    }
}

// tf32 path for emb GEMM
__device__ __forceinline__ unsigned ld_asf(const float* As, int r, int slot, int c) {
    return __float_as_uint(As[r * 16 + ((slot ^ ((r >> 1) & 3)) << 2) + c]);
}
__device__ __forceinline__ void mma_tile16f(const float* As, const float* Ws,
                                            float (&acc)[4][4][4], int lane,
                                            int wm, int wn)
{
#pragma unroll
    for (int ks = 0; ks < 2; ks++) {
        unsigned b0[4], b1[4];
        int bk = ks * 8 + (lane & 3);
        int bn = wn * 32 + (lane >> 2);
#pragma unroll
        for (int nt = 0; nt < 4; nt++) {
            b0[nt] = __float_as_uint(Ws[bk * WS_STRIDE + bn + nt * 8]);
            b1[nt] = __float_as_uint(Ws[(bk + 4) * WS_STRIDE + bn + nt * 8]);
        }
#pragma unroll
        for (int mt = 0; mt < 4; mt++) {
            int r0 = wm * 64 + mt * 16 + (lane >> 2);
            int r1 = r0 + 8;
            int c = lane & 3;
            unsigned a0 = ld_asf(As, r0, ks * 2,     c);
            unsigned a1 = ld_asf(As, r1, ks * 2,     c);
            unsigned a2 = ld_asf(As, r0, ks * 2 + 1, c);
            unsigned a3 = ld_asf(As, r1, ks * 2 + 1, c);
#pragma unroll
            for (int nt = 0; nt < 4; nt++) {
                asm volatile(
                    "mma.sync.aligned.m16n8k8.row.col.f32.tf32.tf32.f32 "
                    "{%0,%1,%2,%3}, {%4,%5,%6,%7}, {%8,%9}, {%0,%1,%2,%3};"
                    : "+f"(acc[mt][nt][0]), "+f"(acc[mt][nt][1]),
                      "+f"(acc[mt][nt][2]), "+f"(acc[mt][nt][3])
                    : "r"(a0), "r"(a1), "r"(a2), "r"(a3),
                      "r"(b0[nt]), "r"(b1[nt]));
            }
        }
    }
}

// ---------------- batched fp32 GEMM for weight prep ----------------
__global__ __launch_bounds__(256) void gemm128L(
    const float* __restrict__ Ab, size_t aStride,
    const float* __restrict__ Wb, size_t wStride,
    float* __restrict__ Cb, size_t cStride, int M, int K)
{
    const float* A = Ab + blockIdx.y * aStride;
    const float* W = Wb + blockIdx.y * wStride;
    float* C = Cb + blockIdx.y * cStride;
    __shared__ float As[16 * 132];
    __shared__ float Ws[16 * 128];
    int tid = threadIdx.x;
    int m0 = blockIdx.x * 128;
    int trow = tid >> 4, tcol = tid & 15;
    int r8 = trow * 8, c8 = tcol * 8;
    int arow = tid >> 2;
    int ac4 = (tid & 3) * 4;

    float acc[8][8];
#pragma unroll
    for (int i = 0; i < 8; i++)
#pragma unroll
        for (int j = 0; j < 8; j++) acc[i][j] = 0.f;

    for (int k0 = 0; k0 < K; k0 += 16) {
#pragma unroll
        for (int t = 0; t < 2; t++) {
            int r = arow + t * 64;
            int gr = m0 + r;
            float4 v = make_float4(0.f, 0.f, 0.f, 0.f);
            if (gr < M) v = *(const float4*)(A + (size_t)gr * K + k0 + ac4);
            As[(ac4 + 0) * 132 + r] = v.x;
            As[(ac4 + 1) * 132 + r] = v.y;
            As[(ac4 + 2) * 132 + r] = v.z;
            As[(ac4 + 3) * 132 + r] = v.w;
        }
#pragma unroll
        for (int t = 0; t < 2; t++) {
            int f4i = tid + t * 256;
            int wr = f4i >> 5, wc = (f4i & 31) * 4;
            *(float4*)&Ws[wr * 128 + wc] = *(const float4*)(W + (size_t)(k0 + wr) * 128 + wc);
        }
        __syncthreads();
#pragma unroll
        for (int kk = 0; kk < 16; kk++) {
            float4 a0 = *(const float4*)&As[kk * 132 + r8];
            float4 a1 = *(const float4*)&As[kk * 132 + r8 + 4];
            float4 w0 = *(const float4*)&Ws[kk * 128 + c8];
            float4 w1 = *(const float4*)&Ws[kk * 128 + c8 + 4];
            float a[8] = {a0.x, a0.y, a0.z, a0.w, a1.x, a1.y, a1.z, a1.w};
            float w[8] = {w0.x, w0.y, w0.z, w0.w, w1.x, w1.y, w1.z, w1.w};
#pragma unroll
            for (int i = 0; i < 8; i++)
#pragma unroll
                for (int j = 0; j < 8; j++) acc[i][j] += a[i] * w[j];
        }
        __syncthreads();
    }

#pragma unroll
    for (int i = 0; i < 8; i++) {
        int gr = m0 + r8 + i;
        if (gr < M) {
            float4 o0, o1;
            o0.x = acc[i][0]; o0.y = acc[i][1]; o0.z = acc[i][2]; o0.w = acc[i][3];
            o1.x = acc[i][4]; o1.y = acc[i][5]; o1.z = acc[i][6]; o1.w = acc[i][7];
            *(float4*)(C + (size_t)gr * 128 + c8) = o0;
            *(float4*)(C + (size_t)gr * 128 + c8 + 4) = o1;
        }
    }
}

// ---------------- emb GEMM (tf32): writes fp16 h ----------------
__global__ __launch_bounds__(256) void emb_gemmt(
    const float* __restrict__ A, const float* __restrict__ W,
    const float* __restrict__ bias, int K)
{
    __shared__ float As[128 * 16];
    __shared__ float Ws[16 * WS_STRIDE];
    int tid = threadIdx.x;
    int lane = tid & 31, warp = tid >> 5;
    int wm = warp >> 2, wn = warp & 3;
    int m0 = blockIdx.x * 128;
    int arow = tid >> 2;
    int slot = tid & 3;
    float4* As4 = (float4*)As;

    float acc[4][4][4];
#pragma unroll
    for (int a = 0; a < 4; a++)
#pragma unroll
        for (int b = 0; b < 4; b++)
#pragma unroll
            for (int c = 0; c < 4; c++) acc[a][b][c] = 0.f;

    for (int k0 = 0; k0 < K; k0 += 16) {
#pragma unroll
        for (int t = 0; t < 2; t++) {
            int r = arow + t * 64;
            int gr = m0 + r;
            float4 v = make_float4(0.f, 0.f, 0.f, 0.f);
            if (gr < NN) v = *(const float4*)(A + (size_t)gr * K + k0 + slot * 4);
            As4[r * 4 + (slot ^ ((r >> 1) & 3))] = v;
        }
#pragma unroll
        for (int t = 0; t < 2; t++) {
            int f4i = tid + t * 256;
            int wr = f4i >> 5, wc = (f4i & 31) * 4;
            *(float4*)&Ws[wr * WS_STRIDE + wc] =
                *(const float4*)(W + (size_t)(k0 + wr) * 128 + wc);
        }
        __syncthreads();
        mma_tile16f(As, Ws, acc, lane, wm, wn);
        __syncthreads();
    }

#pragma unroll
    for (int mt = 0; mt < 4; mt++) {
        int r0 = m0 + wm * 64 + mt * 16 + (lane >> 2);
#pragma unroll
        for (int nt = 0; nt < 4; nt++) {
            int col = wn * 32 + nt * 8 + 2 * (lane & 3);
            float b0 = bias[col], b1 = bias[col + 1];
            if (r0 < NN)
                *(__half2*)(g_h16 + (size_t)r0 * 128 + col) =
                    __floats2half2_rn(acc[mt][nt][0] + b0, acc[mt][nt][1] + b1);
            if (r0 + 8 < NN)
                *(__half2*)(g_h16 + (size_t)(r0 + 8) * 128 + col) =
                    __floats2half2_rn(acc[mt][nt][2] + b0, acc[mt][nt][3] + b1);
        }
    }
}

// ---------------- D GEMM (layer 0) ----------------
__global__ __launch_bounds__(256) void d_gemm(
    const unsigned* __restrict__ Wp, const float* __restrict__ bias)
{
    __shared__ unsigned As2[128 * 16];
    __shared__ unsigned Ws2[16 * WS_STRIDE];
    int tid = threadIdx.x;
    int lane = tid & 31, warp = tid >> 5;
    int wm = warp >> 2, wn = warp & 3;
    int m0 = blockIdx.x * 128;
    int arow = tid >> 2;
    int slot = tid & 3;
    uint4* As4 = (uint4*)As2;

    float acc[4][4][4];
#pragma unroll
    for (int a = 0; a < 4; a++)
#pragma unroll
        for (int b = 0; b < 4; b++)
#pragma unroll
            for (int c = 0; c < 4; c++) acc[a][b][c] = 0.f;

    for (int kt = 0; kt < 4; kt++) {
#pragma unroll
        for (int t = 0; t < 2; t++) {
            int r = arow + t * 64;
            int gr = m0 + r;
            uint4 v = make_uint4(0, 0, 0, 0);
            if (gr < NN)
                v = *(const uint4*)(g_h16 + (size_t)gr * 128 + kt * 32 + slot * 8);
            As4[r * 4 + (slot ^ ((r >> 1) & 3))] = v;
        }
#pragma unroll
        for (int t = 0; t < 2; t++) {
            int f4i = tid + t * 256;
            int wr = f4i >> 5, wc = (f4i & 31) * 4;
            *(uint4*)&Ws2[wr * WS_STRIDE + wc] =
                *(const uint4*)(Wp + (size_t)(kt * 16 + wr) * 128 + wc);
        }
        __syncthreads();
        mma_tile32(As2, Ws2, acc, lane, wm, wn);
        __syncthreads();
    }

#pragma unroll
    for (int mt = 0; mt < 4; mt++) {
        int r0 = m0 + wm * 64 + mt * 16 + (lane >> 2);
#pragma unroll
        for (int nt = 0; nt < 4; nt++) {
            int col = wn * 32 + nt * 8 + 2 * (lane & 3);
            float b0 = bias[col], b1 = bias[col + 1];
            if (r0 < NN)
                *(__half2*)(g_D16 + (size_t)r0 * 128 + col) =
                    __floats2half2_rn(acc[mt][nt][0] + b0, acc[mt][nt][1] + b1);
            if (r0 + 8 < NN)
                *(__half2*)(g_D16 + (size_t)(r0 + 8) * 128 + col) =
                    __floats2half2_rn(acc[mt][nt][2] + b0, acc[mt][nt][3] + b1);
        }
    }
}

// ---------------- fused BN+ReLU + next-layer D GEMM ----------------
__global__ __launch_bounds__(256) void bn_d_gemm(
    const float* __restrict__ gamma, const float* __restrict__ beta,
    const unsigned* __restrict__ Wp, const float* __restrict__ dbias, int doD)
{
    __shared__ unsigned As2[128 * 16];
    __shared__ unsigned Ws2[16 * WS_STRIDE];
    __shared__ float ssc[128], sof[128];
    int tid = threadIdx.x;
    int lane = tid & 31, warp = tid >> 5;
    int wm = warp >> 2, wn = warp & 3;
    int m0 = blockIdx.x * 128;
    int arow = tid >> 2;
    int slot = tid & 3;
    uint4* As4 = (uint4*)As2;

    if (tid < 128) {
        const float invN = 1.f / (float)NN;
        float mu = g_bn[tid] * invN;
        float var = g_bn[128 + tid] * invN - mu * mu;
        float sc = rsqrtf(var + EPS_BN) * gamma[tid];
        ssc[tid] = sc;
        sof[tid] = beta[tid] - mu * sc;
    }
    __syncthreads();

    float acc[4][4][4];
#pragma unroll
    for (int a = 0; a < 4; a++)
#pragma unroll
        for (int b = 0; b < 4; b++)
#pragma unroll
            for (int c = 0; c < 4; c++) acc[a][b][c] = 0.f;

    for (int kt = 0; kt < 4; kt++) {
#pragma unroll
        for (int t = 0; t < 2; t++) {
            int r = arow + t * 64;
            int gr = m0 + r;
            int c0 = kt * 32 + slot * 8;
            uint4 hv = make_uint4(0, 0, 0, 0);
            if (gr < NN) {
                float4 x0 = *(const float4*)(g_h2 + (size_t)gr * 128 + c0);
                float4 x1 = *(const float4*)(g_h2 + (size_t)gr * 128 + c0 + 4);
                float y0 = fmaxf(x0.x * ssc[c0 + 0] + sof[c0 + 0], 0.f);
                float y1 = fmaxf(x0.y * ssc[c0 + 1] + sof[c0 + 1], 0.f);
                float y2 = fmaxf(x0.z * ssc[c0 + 2] + sof[c0 + 2], 0.f);
                float y3 = fmaxf(x0.w * ssc[c0 + 3] + sof[c0 + 3], 0.f);
                float y4 = fmaxf(x1.x * ssc[c0 + 4] + sof[c0 + 4], 0.f);
                float y5 = fmaxf(x1.y * ssc[c0 + 5] + sof[c0 + 5], 0.f);
                float y6 = fmaxf(x1.z * ssc[c0 + 6] + sof[c0 + 6], 0.f);
                float y7 = fmaxf(x1.w * ssc[c0 + 7] + sof[c0 + 7], 0.f);
                __half2 p0 = __floats2half2_rn(y0, y1);
                __half2 p1 = __floats2half2_rn(y2, y3);
                __half2 p2 = __floats2half2_rn(y4, y5);
                __half2 p3 = __floats2half2_rn(y6, y7);
                hv = make_uint4(*(unsigned*)&p0, *(unsigned*)&p1,
                                *(unsigned*)&p2, *(unsigned*)&p3);
                *(uint4*)(g_h16 + (size_t)gr * 128 + c0) = hv;
            }
            As4[r * 4 + (slot ^ ((r >> 1) & 3))] = hv;
        }
        if (doD) {
#pragma unroll
            for (int t = 0; t < 2; t++) {
                int f4i = tid + t * 256;
                int wr = f4i >> 5, wc = (f4i & 31) * 4;
                *(uint4*)&Ws2[wr * WS_STRIDE + wc] =
                    *(const uint4*)(Wp + (size_t)(kt * 16 + wr) * 128 + wc);
            }
        }
        __syncthreads();
        if (doD) mma_tile32(As2, Ws2, acc, lane, wm, wn);
        __syncthreads();
    }

    if (doD) {
#pragma unroll
        for (int mt = 0; mt < 4; mt++) {
            int r0 = m0 + wm * 64 + mt * 16 + (lane >> 2);
#pragma unroll
            for (int nt = 0; nt < 4; nt++) {
                int col = wn * 32 + nt * 8 + 2 * (lane & 3);
                float b0 = dbias[col], b1 = dbias[col + 1];
                if (r0 < NN)
                    *(__half2*)(g_D16 + (size_t)r0 * 128 + col) =
                        __floats2half2_rn(acc[mt][nt][0] + b0, acc[mt][nt][1] + b1);
                if (r0 + 8 < NN)
                    *(__half2*)(g_D16 + (size_t)(r0 + 8) * 128 + col) =
                        __floats2half2_rn(acc[mt][nt][2] + b0, acc[mt][nt][3] + b1);
            }
        }
    }
}

// ---------------- lin GEMM fp16 with fused BN stats ----------------
__global__ __launch_bounds__(256) void lin_gemm_bn(
    const unsigned* __restrict__ Wp, const float* __restrict__ bias)
{
    __shared__ unsigned As2[128 * 16];
    __shared__ unsigned Ws2[16 * WS_STRIDE];
    __shared__ float sbn[256];
    int tid = threadIdx.x;
    int lane = tid & 31, warp = tid >> 5;
    int wm = warp >> 2, wn = warp & 3;
    int m0 = blockIdx.x * 128;
    int arow = tid >> 2;
    int slot = tid & 3;
    uint4* As4 = (uint4*)As2;
    sbn[tid] = 0.f;

    float acc[4][4][4];
#pragma unroll
    for (int a = 0; a < 4; a++)
#pragma unroll
        for (int b = 0; b < 4; b++)
#pragma unroll
            for (int c = 0; c < 4; c++) acc[a][b][c] = 0.f;

    for (int kt = 0; kt < 4; kt++) {
#pragma unroll
        for (int t = 0; t < 2; t++) {
            int r = arow + t * 64;
            int gr = m0 + r;
            uint4 v = make_uint4(0, 0, 0, 0);
            if (gr < NN)
                v = *(const uint4*)(g_tmp16 + (size_t)gr * 128 + kt * 32 + slot * 8);
            As4[r * 4 + (slot ^ ((r >> 1) & 3))] = v;
        }
#pragma unroll
        for (int t = 0; t < 2; t++) {
            int f4i = tid + t * 256;
            int wr = f4i >> 5, wc = (f4i & 31) * 4;
            *(uint4*)&Ws2[wr * WS_STRIDE + wc] =
                *(const uint4*)(Wp + (size_t)(kt * 16 + wr) * 128 + wc);
        }
        __syncthreads();
        mma_tile32(As2, Ws2, acc, lane, wm, wn);
        __syncthreads();
    }

    float csum[4][2] = {}, csq[4][2] = {};
#pragma unroll
    for (int mt = 0; mt < 4; mt++) {
        int r0 = m0 + wm * 64 + mt * 16 + (lane >> 2);
#pragma unroll
        for (int nt = 0; nt < 4; nt++) {
            int col = wn * 32 + nt * 8 + 2 * (lane & 3);
            float b0 = bias[col], b1 = bias[col + 1];
            float v0 = acc[mt][nt][0] + b0, v1 = acc[mt][nt][1] + b1;
            float v2 = acc[mt][nt][2] + b0, v3 = acc[mt][nt][3] + b1;
            if (r0 < NN) {
                *(float2*)(g_h2 + (size_t)r0 * 128 + col) = make_float2(v0, v1);
                csum[nt][0] += v0; csq[nt][0] += v0 * v0;
                csum[nt][1] += v1; csq[nt][1] += v1 * v1;
            }
            if (r0 + 8 < NN) {
                *(float2*)(g_h2 + (size_t)(r0 + 8) * 128 + col) = make_float2(v2, v3);
                csum[nt][0] += v2; csq[nt][0] += v2 * v2;
                csum[nt][1] += v3; csq[nt][1] += v3 * v3;
            }
        }
    }
#pragma unroll
    for (int nt = 0; nt < 4; nt++)
#pragma unroll
        for (int j = 0; j < 2; j++) {
            float s = csum[nt][j], q = csq[nt][j];
            s += __shfl_down_sync(0xffffffffu, s, 16);
            s += __shfl_down_sync(0xffffffffu, s, 8);
            s += __shfl_down_sync(0xffffffffu, s, 4);
            q += __shfl_down_sync(0xffffffffu, q, 16);
            q += __shfl_down_sync(0xffffffffu, q, 8);
            q += __shfl_down_sync(0xffffffffu, q, 4);
            if (lane < 4) {
                int col = wn * 32 + nt * 8 + 2 * lane + j;
                atomicAdd(&sbn[col], s);
                atomicAdd(&sbn[128 + col], q);
            }
        }
    __syncthreads();
    atomicAdd(&g_bn[tid], sbn[tid]);
}

// ---------------- fused edge GEMM (fp16, src+edge, K=160) + aggregation ----------------
__global__ __launch_bounds__(256) void edge_agg(const unsigned* __restrict__ Wp)
{
    extern __shared__ float s_dyn[];
    unsigned* su = (unsigned*)s_dyn;
    float* mt_ = s_dyn;
    __shared__ int sdst[128], ssrc[128], seid[128];

    int tid = threadIdx.x;
    int lane = tid & 31, warp = tid >> 5;
    int wm = warp >> 2, wn = warp & 3;
    int e0 = blockIdx.x * 128;
    int arow = tid >> 2;
    int slot = tid & 3;

    if (tid < 128) {
        int p = e0 + tid;
        sdst[tid] = g_pdst[p];
        ssrc[tid] = g_psrc[p];
        seid[tid] = g_peid[p];
    }
    __syncthreads();

    float acc[4][4][4];
#pragma unroll
    for (int a = 0; a < 4; a++)
#pragma unroll
        for (int b = 0; b < 4; b++)
#pragma unroll
            for (int c = 0; c < 4; c++) acc[a][b][c] = 0.f;

    auto a_sub = [&](int st, int j) { return su + st * 4096 + j * 2048; };
    auto w_sub = [&](int st, int j) { return su + 8192 + st * 4352 + j * 2176; };

    auto load_sub = [&](int kt, int st, int j) {
        unsigned* ab = a_sub(st, j);
        unsigned* wb = w_sub(st, j);
#pragma unroll
        for (int t = 0; t < 2; t++) {
            int r = arow + t * 64;
            const __half* src;
            if (kt < 4) src = g_h16 + (size_t)ssrc[r] * H + kt * 32 + slot * 8;
            else        src = g_ea16 + (size_t)seid[r] * 32 + slot * 8;
            cp16(&ab[r * 16 + ((slot ^ ((r >> 1) & 3)) << 2)], src);
        }
#pragma unroll
        for (int t = 0; t < 2; t++) {
            int f4i = tid + t * 256;
            int wr = f4i >> 5, wc = (f4i & 31) * 4;
            cp16(&wb[wr * WS_STRIDE + wc], Wp + (size_t)(kt * 16 + wr) * 128 + wc);
        }
    };

    load_sub(0, 0, 0); load_sub(1, 0, 1);
    CP_COMMIT();
    for (int p = 0; p < 3; p++) {
        if (p < 2) {
            int st = (p + 1) & 1;
            load_sub(2 * p + 2, st, 0);
            if (2 * p + 3 < 5) load_sub(2 * p + 3, st, 1);
            CP_COMMIT(); CP_WAIT1();
        } else CP_WAIT0();
        __syncthreads();
        int st = p & 1;
        mma_tile32(a_sub(st, 0), w_sub(st, 0), acc, lane, wm, wn);
        if (2 * p + 1 < 5)
            mma_tile32(a_sub(st, 1), w_sub(st, 1), acc, lane, wm, wn);
        __syncthreads();
    }

#pragma unroll
    for (int mt2 = 0; mt2 < 4; mt2++) {
        int r0 = wm * 64 + mt2 * 16 + (lane >> 2);
#pragma unroll
        for (int nt = 0; nt < 4; nt++) {
            int col = wn * 32 + nt * 8 + 2 * (lane & 3);
            *(float2*)&mt_[r0 * 132 + col] =
                make_float2(acc[mt2][nt][0], acc[mt2][nt][1]);
            *(float2*)&mt_[(r0 + 8) * 132 + col] =
                make_float2(acc[mt2][nt][2], acc[mt2][nt][3]);
        }
    }
    __syncthreads();

    int c = tid & 127, g2 = tid >> 7;
    int nfirst = sdst[0], nlast = sdst[127];
    for (int n = nfirst + g2; n <= nlast; n += 2) {
        int s = g_start[n], e = g_start[n + 1];
        if (s == e) continue;
        int lo = max(s, e0), hi = min(e, e0 + 128);
        if (lo >= hi) continue;
        float sumv = 0.f, sq = 0.f, mn = INFINITY, mx = -INFINITY;
        for (int r = lo - e0; r < hi - e0; r++) {
            float v = mt_[r * 132 + c];
            sumv += v; sq += v * v;
            mn = fminf(mn, v); mx = fmaxf(mx, v);
        }
        size_t idx = (size_t)n * H + c;
        if (s >= e0 && e <= e0 + 128) {
            float Dv = __half2float(g_D16[idx]);
            float degc = (float)(e - s);
            float inv = 1.f / degc;
            float mean = sumv * inv;
            float var = fmaxf(sq * inv - mean * mean, 0.f);
            g_mean16[idx] = __float2half_rn(Dv + mean);
            g_std16[idx] = __float2half_rn(sqrtf(var + EPS_STD));
            g_mn16[idx] = __float2half_rn(Dv + mn);
            g_mx16[idx] = __float2half_rn(Dv + mx);
        } else {
            atomicAdd(&g_bsum[idx], sumv);
            atomicAdd(&g_bsq[idx], sq);
            atomicMinF(&g_bmn[idx], mn);
            atomicMaxF(&g_bmx[idx], mx);
        }
    }
}

// ---------------- boundary helpers ----------------
__global__ void bnd_build() {
    int n = blockIdx.x * blockDim.x + threadIdx.x;
    if (n >= NN) return;
    int s = g_start[n], e = g_start[n + 1];
    bool bnd = (s == e) || ((s >> 7) != ((e - 1) >> 7));
    if (bnd) {
        int p = atomicAdd(&g_bcnt, 1);
        g_blist[p] = n;
    }
}
__global__ void init_bnd() {
    int B = g_bcnt;
    int total = B * 128;
    for (int i = blockIdx.x * blockDim.x + threadIdx.x; i < total;
         i += gridDim.x * blockDim.x) {
        int n = g_blist[i >> 7];
        int c = i & 127;
        size_t idx = (size_t)n * H + c;
        g_bsum[idx] = 0.f; g_bsq[idx] = 0.f;
        g_bmn[idx] = INFINITY; g_bmx[idx] = -INFINITY;
    }
}
__global__ void fin_bnd() {
    int B = g_bcnt;
    int total = B * 128;
    for (int i = blockIdx.x * blockDim.x + threadIdx.x; i < total;
         i += gridDim.x * blockDim.x) {
        int n = g_blist[i >> 7];
        int c = i & 127;
        size_t idx = (size_t)n * H + c;
        int cnt = g_start[n + 1] - g_start[n];
        if (cnt == 0) {
            g_mean16[idx] = __float2half_rn(0.f);
            g_std16[idx] = __float2half_rn(sqrtf(EPS_STD));
            g_mn16[idx] = __float2half_rn(0.f);
            g_mx16[idx] = __float2half_rn(0.f);
        } else {
            float Dv = __half2float(g_D16[idx]);
            float inv = 1.f / (float)cnt;
            float mean = g_bsum[idx] * inv;
            float var = fmaxf(g_bsq[idx] * inv - mean * mean, 0.f);
            g_mean16[idx] = __float2half_rn(Dv + mean);
            g_std16[idx] = __float2half_rn(sqrtf(var + EPS_STD));
            g_mn16[idx] = __float2half_rn(Dv + g_bmn[idx]);
            g_mx16[idx] = __float2half_rn(Dv + g_bmx[idx]);
        }
    }
}

// ---------------- post-NN gather-GEMM fp16 (3 pair-stages, R7 ordering) ----------------
__global__ __launch_bounds__(256) void post_gemmt(const unsigned* __restrict__ Wp,
                                                  const float* __restrict__ bias)
{
    extern __shared__ float s_dyn[];
    unsigned* su = (unsigned*)s_dyn;
    int tid = threadIdx.x;
    int lane = tid & 31, warp = tid >> 5;
    int wm = warp >> 2, wn = warp & 3;
    int n0 = blockIdx.x * 128;
    int arow = tid >> 2;
    int slot = tid & 3;

    float sa[8], si2[8];
#pragma unroll
    for (int mt = 0; mt < 4; mt++)
#pragma unroll
        for (int hh = 0; hh < 2; hh++) {
            int n = n0 + wm * 64 + mt * 16 + (lane >> 2) + hh * 8;
            if (n >= NN) n = NN - 1;
            float a = g_amp[n], ia = g_iamp[n];
            sa[mt * 2 + hh] = a;
            si2[mt * 2 + hh] = ia * ia;
        }

    float acc[4][4][4];
#pragma unroll
    for (int a = 0; a < 4; a++)
#pragma unroll
        for (int b = 0; b < 4; b++)
#pragma unroll
            for (int c = 0; c < 4; c++) acc[a][b][c] = 0.f;

    // 3 pair-stages of PAIR_W words: A0 +0, A1 +2048, W0 +4096, W1 +6272
    auto a_sub = [&](int st, int j) { return su + st * PAIR_W + j * 2048; };
    auto w_sub = [&](int st, int j) { return su + st * PAIR_W + 4096 + j * 2176; };

    auto load_pair = [&](int p, int st) {
#pragma unroll
        for (int j = 0; j < 2; j++) {
            int kt = map_t32(2 * p + j);
            int b = kt >> 2;
            const __half* srcb;
            if (b == 0) srcb = g_h16;
            else {
                int a = (b - 1) & 3;
                srcb = (a == 0) ? g_mean16 : (a == 1) ? g_mn16 : (a == 2) ? g_mx16 : g_std16;
            }
            int kk0 = (kt & 3) * 32;
            unsigned* ab = a_sub(st, j);
            unsigned* wb = w_sub(st, j);
#pragma unroll
            for (int tt = 0; tt < 2; tt++) {
                int r = arow + tt * 64;
                int n = n0 + r;
                if (n >= NN) n = NN - 1;
                cp16(&ab[r * 16 + ((slot ^ ((r >> 1) & 3)) << 2)],
                     srcb + (size_t)n * H + kk0 + slot * 8);
            }
#pragma unroll
            for (int tt = 0; tt < 2; tt++) {
                int f4i = tid + tt * 256;
                int wr = f4i >> 5, wc = (f4i & 31) * 4;
                cp16(&wb[wr * WS_STRIDE + wc], Wp + (size_t)(kt * 16 + wr) * 128 + wc);
            }
        }
    };

    load_pair(0, 0); CP_COMMIT();
    load_pair(1, 1); CP_COMMIT();
    for (int p = 0; p < 26; p++) {
        int st = p % 3;
        if (p < 24) { load_pair(p + 2, (p + 2) % 3); CP_COMMIT(); CP_WAIT2(); }
        else if (p == 24) CP_WAIT1();
        else CP_WAIT0();
        __syncthreads();
        mma_tile32(a_sub(st, 0), w_sub(st, 0), acc, lane, wm, wn);
        mma_tile32(a_sub(st, 1), w_sub(st, 1), acc, lane, wm, wn);
        __syncthreads();
        if (p == 7) {            // U3 done -> * iamp^2
#pragma unroll
            for (int mt = 0; mt < 4; mt++)
#pragma unroll
                for (int nt = 0; nt < 4; nt++) {
                    acc[mt][nt][0] *= si2[mt * 2];     acc[mt][nt][1] *= si2[mt * 2];
                    acc[mt][nt][2] *= si2[mt * 2 + 1]; acc[mt][nt][3] *= si2[mt * 2 + 1];
                }
        } else if (p == 15) {    // U2 done -> * amp
#pragma unroll
            for (int mt = 0; mt < 4; mt++)
#pragma unroll
                for (int nt = 0; nt < 4; nt++) {
                    acc[mt][nt][0] *= sa[mt * 2];     acc[mt][nt][1] *= sa[mt * 2];
                    acc[mt][nt][2] *= sa[mt * 2 + 1]; acc[mt][nt][3] *= sa[mt * 2 + 1];
                }
        }
    }

#pragma unroll
    for (int mt = 0; mt < 4; mt++) {
        int r0 = n0 + wm * 64 + mt * 16 + (lane >> 2);
#pragma unroll
        for (int nt = 0; nt < 4; nt++) {
            int col = wn * 32 + nt * 8 + 2 * (lane & 3);
            float b0 = bias[col], b1 = bias[col + 1];
            if (r0 < NN)
                *(__half2*)(g_tmp16 + (size_t)r0 * 128 + col) =
                    __floats2half2_rn(acc[mt][nt][0] + b0, acc[mt][nt][1] + b1);
            if (r0 + 8 < NN)
                *(__half2*)(g_tmp16 + (size_t)(r0 + 8) * 128 + col) =
                    __floats2half2_rn(acc[mt][nt][2] + b0, acc[mt][nt][3] + b1);
        }
    }
}

// ---------------- batched packing / conversion ----------------
__global__ void pack_dL(const float* __restrict__ preW) {
    int idx = blockIdx.x * blockDim.x + threadIdx.x;
    if (idx >= NL * KP_D * 128) return;
    int l = idx / (KP_D * 128);
    int r = idx - l * (KP_D * 128);
    int kp = r >> 7, n = r & 127;
    const float* base = preW + (size_t)l * 384 * H;
    float lo = base[(size_t)(2 * kp) * H + n];
    float hi = base[(size_t)(2 * kp + 1) * H + n];
    __half2 h = __floats2half2_rn(lo, hi);
    g_dWH[idx] = *(unsigned*)&h;
}
__global__ void pack_eL(const float* __restrict__ preW) {
    int idx = blockIdx.x * blockDim.x + threadIdx.x;
    if (idx >= NL * KP_EDGE * 128) return;
    int l = idx / (KP_EDGE * 128);
    int r = idx - l * (KP_EDGE * 128);
    int kp = r >> 7, n = r & 127;
    float v[2];
#pragma unroll
    for (int j = 0; j < 2; j++) {
        int k = 2 * kp + j;
        if (k < 128)      v[j] = preW[(size_t)l * 384 * H + (size_t)(128 + k) * H + n];
        else if (k < 144) v[j] = g_W2[(size_t)l * 16 * H + (size_t)(k - 128) * H + n];
        else              v[j] = 0.f;
    }
    __half2 h = __floats2half2_rn(v[0], v[1]);
    g_WsrcH[idx] = *(unsigned*)&h;
}
__global__ void pack_genL(const float* __restrict__ src, size_t strideL,
                          unsigned* __restrict__ out, int kpairs, int kmax) {
    int idx = blockIdx.x * blockDim.x + threadIdx.x;
    if (idx >= NL * kpairs * 128) return;
    int l = idx / (kpairs * 128);
    int r = idx - l * (kpairs * 128);
    int kp = r >> 7, n = r & 127;
    const float* base = src + (size_t)l * strideL;
    float lo = (2 * kp < kmax) ? base[(size_t)(2 * kp) * 128 + n] : 0.f;
    float hi = (2 * kp + 1 < kmax) ? base[(size_t)(2 * kp + 1) * 128 + n] : 0.f;
    __half2 h = __floats2half2_rn(lo, hi);
    out[idx] = *(unsigned*)&h;
}
__global__ void ea_pack(const float* __restrict__ ea) {
    int idx = blockIdx.x * blockDim.x + threadIdx.x;
    if (idx >= NE * 32) return;
    int e = idx >> 5, j = idx & 31;
    g_ea16[idx] = __float2half_rn(j < 16 ? ea[(size_t)e * 16 + j] : 0.f);
}
__global__ void biasm_kL(const float* __restrict__ be, const float* __restrict__ ebB,
                         const float* __restrict__ preW, const float* __restrict__ pbB) {
    int l = blockIdx.x;
    int j = threadIdx.x;
    const float* T1 = g_T1 + (size_t)l * H * H;
    const float* P2 = preW + (size_t)l * 384 * H + 256 * H;
    float s = pbB[l * H + j];
    for (int k = 0; k < H; k++) s += be[k] * T1[k * H + j];
    for (int k = 0; k < H; k++) s += ebB[l * H + k] * P2[k * H + j];
    g_biasmL[l * H + j] = s;
}

// ---------------- sort / scan ----------------
__global__ void deg_count(const int* __restrict__ dstI) {
    int e = blockIdx.x * blockDim.x + threadIdx.x;
    if (e < NE) atomicAdd(&g_cnt[dstI[e]], 1);
}
__global__ __launch_bounds__(256) void scan1() {
    int b = blockIdx.x, t = threadIdx.x;
    int n = b * CHUNK + t;
    int v = (t < CHUNK && n < NN) ? g_cnt[n] : 0;
    int lane = t & 31, wid = t >> 5;
    int x = v;
#pragma unroll
    for (int off = 1; off < 32; off <<= 1) {
        int u = __shfl_up_sync(0xffffffffu, x, off);
        if (lane >= off) x += u;
    }
    __shared__ int wsum[8];
    if (lane == 31) wsum[wid] = x;
    __syncthreads();
    if (t == 0) {
        int r = 0;
#pragma unroll
        for (int i = 0; i < 8; i++) { int tmp = wsum[i]; wsum[i] = r; r += tmp; }
        g_part[b] = r;
    }
    __syncthreads();
    int excl = x - v + wsum[wid];
    if (t < CHUNK && n < NN) g_start[n] = excl;
}
__global__ void scan2() {
    int t = threadIdx.x;
    int v = g_part[t];
    int lane = t & 31, wid = t >> 5;
    int x = v;
#pragma unroll
    for (int off = 1; off < 32; off <<= 1) {
        int u = __shfl_up_sync(0xffffffffu, x, off);
        if (lane >= off) x += u;
    }
    __shared__ int wsum[4];
    if (lane == 31) wsum[wid] = x;
    __syncthreads();
    if (t == 0) {
        int r = 0;
#pragma unroll
        for (int i = 0; i < 4; i++) { int tmp = wsum[i]; wsum[i] = r; r += tmp; }
    }
    __syncthreads();
    g_part[t] = x - v + wsum[wid];
}
__global__ void scan3() {
    int n = blockIdx.x * blockDim.x + threadIdx.x;
    if (n < NN) {
        int s = g_start[n] + g_part[n / CHUNK];
        g_start[n] = s;
        g_cursor[n] = s;
    }
    if (n == 0) g_start[NN] = NE;
}
__global__ void scatter_k(const int* __restrict__ srcI, const int* __restrict__ dstI) {
    int e = blockIdx.x * blockDim.x + threadIdx.x;
    if (e >= NE) return;
    int d = dstI[e];
    int p = atomicAdd(&g_cursor[d], 1);
    g_psrc[p] = srcI[e];
    g_pdst[p] = d;
    g_peid[p] = e;
}
__global__ void amp_k() {
    int n = blockIdx.x * blockDim.x + threadIdx.x;
    if (n >= NN) return;
    float degc = fmaxf((float)g_cnt[n], 1.f);
    float a = logf(degc + 1.f) / AVG_LOG;
    g_amp[n] = a;
    g_iamp[n] = 1.f / a;
}

// ---------------- pool / head ----------------
__global__ void pool_k(const int* __restrict__ batch) {
    int c = threadIdx.x;
    int start = blockIdx.x * 256;
    int end = min(start + 256, NN);
    if (start >= NN) return;
    float acc = 0.f;
    int cur = batch[start];
    for (int n = start; n < end; n++) {
        int g = batch[n];
        if (g != cur) { atomicAdd(&g_pool[cur * H + c], acc); acc = 0.f; cur = g; }
        acc += __half2float(g_h16[(size_t)n * H + c]);
    }
    atomicAdd(&g_pool[cur * H + c], acc);
}
__global__ void head1_k(const float* __restrict__ W1, const float* __restrict__ b1) {
    int idx = blockIdx.x * blockDim.x + threadIdx.x;
    if (idx >= NGR * 64) return;
    int g = idx >> 6, j = idx & 63;
    float s = b1[j];
    for (int k = 0; k < H; k++) s += g_pool[g * H + k] * W1[k * 64 + j];
    g_z[idx] = fmaxf(s, 0.f);
}
__global__ void head2_k(const float* __restrict__ W2, const float* __restrict__ b2,
                        float* __restrict__ out) {
    int idx = blockIdx.x * blockDim.x + threadIdx.x;
    if (idx >= NGR * NOUT) return;
    int g = idx / NOUT, j = idx % NOUT;
    float s = b2[j];
    for (int k = 0; k < 64; k++) s += g_z[g * 64 + k] * W2[k * NOUT + j];
    out[idx] = s;
}

// ---------------- launch ----------------
extern "C" void kernel_launch(void* const* d_in, const int* in_sizes, int n_in,
                              void* d_out, int out_size)
{
    int iEI = 1, iBatch = 2, iEA = 3;
    if (in_sizes[1] == NE * 16) { iEA = 1; iEI = 2; iBatch = 3; }

    const float* x         = (const float*)d_in[0];
    const int*   edge_index= (const int*)  d_in[iEI];
    const int*   batch     = (const int*)  d_in[iBatch];
    const float* edge_attr = (const float*)d_in[iEA];
    const float* node_emb_W= (const float*)d_in[4];
    const float* node_emb_b= (const float*)d_in[5];
    const float* edge_emb_W= (const float*)d_in[6];
    const float* edge_emb_b= (const float*)d_in[7];
    const float* edge_enc_W= (const float*)d_in[8];
    const float* edge_enc_b= (const float*)d_in[9];
    const float* pre_W     = (const float*)d_in[10];
    const float* pre_b     = (const float*)d_in[11];
    const float* post_W    = (const float*)d_in[12];
    const float* post_b    = (const float*)d_in[13];
    const float* lin_W     = (const float*)d_in[14];
    const float* lin_b     = (const float*)d_in[15];
    const float* bn_gamma  = (const float*)d_in[16];
    const float* bn_beta   = (const float*)d_in[17];
    const float* head1_W   = (const float*)d_in[18];
    const float* head1_b   = (const float*)d_in[19];
    const float* head2_W   = (const float*)d_in[20];
    const float* head2_b   = (const float*)d_in[21];

    const int* srcI = edge_index;
    const int* dstI = edge_index + NE;

    float *p_T1, *p_W2, *p_biasm, *p_bn, *p_pool;
    unsigned *p_wsrcH, *p_postWH, *p_linWH, *p_dWH;
    int *p_cnt, *p_bcnt;
    cudaGetSymbolAddress((void**)&p_T1,     g_T1);
    cudaGetSymbolAddress((void**)&p_W2,     g_W2);
    cudaGetSymbolAddress((void**)&p_wsrcH,  g_WsrcH);
    cudaGetSymbolAddress((void**)&p_postWH, g_postWH);
    cudaGetSymbolAddress((void**)&p_linWH,  g_linWH);
    cudaGetSymbolAddress((void**)&p_dWH,    g_dWH);
    cudaGetSymbolAddress((void**)&p_biasm,  g_biasmL);
    cudaGetSymbolAddress((void**)&p_bn,     g_bn);
    cudaGetSymbolAddress((void**)&p_pool,   g_pool);
    cudaGetSymbolAddress((void**)&p_cnt,    g_cnt);
    cudaGetSymbolAddress((void**)&p_bcnt,   g_bcnt);

    cudaFuncSetAttribute(edge_agg, cudaFuncAttributeMaxDynamicSharedMemorySize, BIG_SMEM);
    cudaFuncSetAttribute(post_gemmt, cudaFuncAttributeMaxDynamicSharedMemorySize, POST_SMEM);

    // sort prep
    cudaMemsetAsync(p_cnt, 0, NN * sizeof(int));
    cudaMemsetAsync(p_bcnt, 0, sizeof(int));
    deg_count<<<(NE + 255) / 256, 256>>>(dstI);
    scan1<<<SCAN_B, 256>>>();
    scan2<<<1, 128>>>();
    emb_gemmt<<<(NN + 127) / 128, 256>>>(x, node_emb_W, node_emb_b, 64);
    scan3<<<(NN + 255) / 256, 256>>>();
    scatter_k<<<(NE + 255) / 256, 256>>>(srcI, dstI);
    amp_k<<<(NN + 255) / 256, 256>>>();
    bnd_build<<<(NN + 255) / 256, 256>>>();
    ea_pack<<<(NE * 32 + 255) / 256, 256>>>(edge_attr);

    // batched weight prep
    gemm128L<<<dim3(1, NL), 256>>>(edge_enc_W, (size_t)H * H,
                                   pre_W + 256 * H, (size_t)384 * H,
                                   p_T1, (size_t)H * H, 128, 128);
    gemm128L<<<dim3(1, NL), 256>>>(edge_emb_W, 0,
                                   p_T1, (size_t)H * H,
                                   p_W2, (size_t)16 * H, 16, 128);
    biasm_kL<<<NL, 128>>>(edge_emb_b, edge_enc_b, pre_W, pre_b);
    pack_dL<<<(NL * KP_D * 128 + 255) / 256, 256>>>(pre_W);
    pack_eL<<<(NL * KP_EDGE * 128 + 255) / 256, 256>>>(pre_W);
    pack_genL<<<(NL * KP_POST * 128 + 255) / 256, 256>>>(post_W, (size_t)13 * H * H,
                                                         p_postWH, KP_POST, 13 * H);
    pack_genL<<<(NL * KP_LIN * 128 + 255) / 256, 256>>>(lin_W, (size_t)H * H,
                                                        p_linWH, KP_LIN, H);

    d_gemm<<<(NN + 127) / 128, 256>>>(p_dWH, p_biasm);

    for (int l = 0; l < NL; l++) {
        init_bnd<<<64, 256>>>();
        edge_agg<<<NE / 128, 256, BIG_SMEM>>>(p_wsrcH + (size_t)l * KP_EDGE * H);
        fin_bnd<<<64, 256>>>();

        post_gemmt<<<(NN + 127) / 128, 256, POST_SMEM>>>(
            p_postWH + (size_t)l * KP_POST * H, post_b + l * H);

        cudaMemsetAsync(p_bn, 0, 2 * H * sizeof(float));
        lin_gemm_bn<<<(NN + 127) / 128, 256>>>(p_linWH + (size_t)l * KP_LIN * H,
                                               lin_b + l * H);
        if (l < NL - 1)
            bn_d_gemm<<<(NN + 127) / 128, 256>>>(bn_gamma + l * H, bn_beta + l * H,
                                                 p_dWH + (size_t)(l + 1) * KP_D * H,
                                                 p_biasm + (l + 1) * H, 1);
        else
            bn_d_gemm<<<(NN + 127) / 128, 256>>>(bn_gamma + l * H, bn_beta + l * H,
                                                 p_dWH, p_biasm, 0);
    }

    cudaMemsetAsync(p_pool, 0, NGR * H * sizeof(float));
    pool_k<<<(NN + 255) / 256, 128>>>(batch);
    head1_k<<<8, 256>>>(head1_W, head1_b);
    head2_k<<<2, 256>>>(head2_W, head2_b, (float*)d_out);
}

// round 15
// speedup vs baseline: 1.1357x; 1.0259x over previous
#include <cuda_runtime.h>
#include <cuda_fp16.h>
#include <math.h>

#define NN 30000
#define NE 480000
#define H 128
#define NL 4
#define NGR 32
#define NOUT 12
#define AVG_LOG 1.38214548f
#define EPS_BN 1e-5f
#define EPS_STD 1e-5f
#define KP_EDGE 80
#define KP_POST 832
#define KP_LIN 64
#define KP_D 64
#define WS_STRIDE 136
#define SCAN_B 128
#define CHUNK 235
#define BIG_SMEM 67584

// ---------------- scratch ----------------
__device__ float g_h2[NN * H];
__device__ __half g_h16[NN * H];
__device__ __half g_tmp16[NN * H];
__device__ __half g_D16[NN * H];
__device__ __half g_mean16[NN * H];
__device__ __half g_std16[NN * H];
__device__ __half g_mn16[NN * H];
__device__ __half g_mx16[NN * H];
__device__ __half g_ea16[NE * 32];
__device__ float g_bsum[NN * H];
__device__ float g_bsq[NN * H];
__device__ float g_bmn[NN * H];
__device__ float g_bmx[NN * H];
__device__ int   g_cnt[NN];
__device__ int   g_start[NN + 1];
__device__ int   g_cursor[NN];
__device__ int   g_part[SCAN_B];
__device__ int   g_psrc[NE];
__device__ int   g_pdst[NE];
__device__ int   g_peid[NE];
__device__ int   g_blist[NN];
__device__ int   g_bcnt;
__device__ float g_amp[NN];
__device__ float g_iamp[NN];
__device__ unsigned g_WsrcH[NL * KP_EDGE * H];
__device__ unsigned g_postWH[NL * KP_POST * H];
__device__ unsigned g_linWH[NL * KP_LIN * H];
__device__ unsigned g_dWH[NL * KP_D * H];
__device__ float g_T1[NL * H * H];
__device__ float g_W2[NL * 16 * H];
__device__ float g_biasmL[NL * H];
__device__ float g_bn[2 * H];
__device__ float g_pool[NGR * H];
__device__ float g_z[NGR * 64];

// ---------------- helpers ----------------
__device__ __forceinline__ void atomicMaxF(float* a, float v) {
    if (v >= 0.f) atomicMax((int*)a, __float_as_int(v));
    else          atomicMin((unsigned int*)a, __float_as_uint(v));
}
__device__ __forceinline__ void atomicMinF(float* a, float v) {
    if (v >= 0.f) atomicMin((int*)a, __float_as_int(v));
    else          atomicMax((unsigned int*)a, __float_as_uint(v));
}
__device__ __forceinline__ void cp16(void* smem, const void* g) {
    unsigned sa = (unsigned)__cvta_generic_to_shared(smem);
    asm volatile("cp.async.cg.shared.global [%0], [%1], 16;\n" :: "r"(sa), "l"(g));
}
#define CP_COMMIT() asm volatile("cp.async.commit_group;\n" ::: "memory")
#define CP_WAIT1()  asm volatile("cp.async.wait_group 1;\n" ::: "memory")
#define CP_WAIT0()  asm volatile("cp.async.wait_group 0;\n" ::: "memory")

__device__ __forceinline__ int map_t32(int t) {
    return (t < 16) ? 36 + t : (t < 32) ? 20 + (t - 16) : (t - 32);
}
__device__ __forceinline__ unsigned ld_a(const unsigned* As, int r, int slot, int c) {
    return As[r * 16 + ((slot ^ ((r >> 1) & 3)) << 2) + c];
}

__device__ __forceinline__ void mma_tile32(const unsigned* As, const unsigned* Ws,
                                           float (&acc)[4][4][4], int lane,
                                           int wm, int wn)
{
#pragma unroll
    for (int ks = 0; ks < 2; ks++) {
        unsigned b0[4], b1[4];
        int bk = ks * 8 + (lane & 3);
        int bn = wn * 32 + (lane >> 2);
#pragma unroll
        for (int nt = 0; nt < 4; nt++) {
            b0[nt] = Ws[bk * WS_STRIDE + bn + nt * 8];
            b1[nt] = Ws[(bk + 4) * WS_STRIDE + bn + nt * 8];
        }
#pragma unroll
        for (int mt = 0; mt < 4; mt++) {
            int r0 = wm * 64 + mt * 16 + (lane >> 2);
            int r1 = r0 + 8;
            int c = lane & 3;
            unsigned a0 = ld_a(As, r0, ks * 2,     c);
            unsigned a1 = ld_a(As, r1, ks * 2,     c);
            unsigned a2 = ld_a(As, r0, ks * 2 + 1, c);
            unsigned a3 = ld_a(As, r1, ks * 2 + 1, c);
#pragma unroll
            for (int nt = 0; nt < 4; nt++) {
                asm volatile(
                    "mma.sync.aligned.m16n8k16.row.col.f32.f16.f16.f32 "
                    "{%0,%1,%2,%3}, {%4,%5,%6,%7}, {%8,%9}, {%0,%1,%2,%3};"
                    : "+f"(acc[mt][nt][0]), "+f"(acc[mt][nt][1]),
                      "+f"(acc[mt][nt][2]), "+f"(acc[mt][nt][3])
                    : "r"(a0), "r"(a1), "r"(a2), "r"(a3),
                      "r"(b0[nt]), "r"(b1[nt]));
            }
        }
    }
}

// tf32 path for emb GEMM
__device__ __forceinline__ unsigned ld_asf(const float* As, int r, int slot, int c) {
    return __float_as_uint(As[r * 16 + ((slot ^ ((r >> 1) & 3)) << 2) + c]);
}
__device__ __forceinline__ void mma_tile16f(const float* As, const float* Ws,
                                            float (&acc)[4][4][4], int lane,
                                            int wm, int wn)
{
#pragma unroll
    for (int ks = 0; ks < 2; ks++) {
        unsigned b0[4], b1[4];
        int bk = ks * 8 + (lane & 3);
        int bn = wn * 32 + (lane >> 2);
#pragma unroll
        for (int nt = 0; nt < 4; nt++) {
            b0[nt] = __float_as_uint(Ws[bk * WS_STRIDE + bn + nt * 8]);
            b1[nt] = __float_as_uint(Ws[(bk + 4) * WS_STRIDE + bn + nt * 8]);
        }
#pragma unroll
        for (int mt = 0; mt < 4; mt++) {
            int r0 = wm * 64 + mt * 16 + (lane >> 2);
            int r1 = r0 + 8;
            int c = lane & 3;
            unsigned a0 = ld_asf(As, r0, ks * 2,     c);
            unsigned a1 = ld_asf(As, r1, ks * 2,     c);
            unsigned a2 = ld_asf(As, r0, ks * 2 + 1, c);
            unsigned a3 = ld_asf(As, r1, ks * 2 + 1, c);
#pragma unroll
            for (int nt = 0; nt < 4; nt++) {
                asm volatile(
                    "mma.sync.aligned.m16n8k8.row.col.f32.tf32.tf32.f32 "
                    "{%0,%1,%2,%3}, {%4,%5,%6,%7}, {%8,%9}, {%0,%1,%2,%3};"
                    : "+f"(acc[mt][nt][0]), "+f"(acc[mt][nt][1]),
                      "+f"(acc[mt][nt][2]), "+f"(acc[mt][nt][3])
                    : "r"(a0), "r"(a1), "r"(a2), "r"(a3),
                      "r"(b0[nt]), "r"(b1[nt]));
            }
        }
    }
}

// ---------------- batched fp32 GEMM for weight prep ----------------
__global__ __launch_bounds__(256) void gemm128L(
    const float* __restrict__ Ab, size_t aStride,
    const float* __restrict__ Wb, size_t wStride,
    float* __restrict__ Cb, size_t cStride, int M, int K)
{
    const float* A = Ab + blockIdx.y * aStride;
    const float* W = Wb + blockIdx.y * wStride;
    float* C = Cb + blockIdx.y * cStride;
    __shared__ float As[16 * 132];
    __shared__ float Ws[16 * 128];
    int tid = threadIdx.x;
    int m0 = blockIdx.x * 128;
    int trow = tid >> 4, tcol = tid & 15;
    int r8 = trow * 8, c8 = tcol * 8;
    int arow = tid >> 2;
    int ac4 = (tid & 3) * 4;

    float acc[8][8];
#pragma unroll
    for (int i = 0; i < 8; i++)
#pragma unroll
        for (int j = 0; j < 8; j++) acc[i][j] = 0.f;

    for (int k0 = 0; k0 < K; k0 += 16) {
#pragma unroll
        for (int t = 0; t < 2; t++) {
            int r = arow + t * 64;
            int gr = m0 + r;
            float4 v = make_float4(0.f, 0.f, 0.f, 0.f);
            if (gr < M) v = *(const float4*)(A + (size_t)gr * K + k0 + ac4);
            As[(ac4 + 0) * 132 + r] = v.x;
            As[(ac4 + 1) * 132 + r] = v.y;
            As[(ac4 + 2) * 132 + r] = v.z;
            As[(ac4 + 3) * 132 + r] = v.w;
        }
#pragma unroll
        for (int t = 0; t < 2; t++) {
            int f4i = tid + t * 256;
            int wr = f4i >> 5, wc = (f4i & 31) * 4;
            *(float4*)&Ws[wr * 128 + wc] = *(const float4*)(W + (size_t)(k0 + wr) * 128 + wc);
        }
        __syncthreads();
#pragma unroll
        for (int kk = 0; kk < 16; kk++) {
            float4 a0 = *(const float4*)&As[kk * 132 + r8];
            float4 a1 = *(const float4*)&As[kk * 132 + r8 + 4];
            float4 w0 = *(const float4*)&Ws[kk * 128 + c8];
            float4 w1 = *(const float4*)&Ws[kk * 128 + c8 + 4];
            float a[8] = {a0.x, a0.y, a0.z, a0.w, a1.x, a1.y, a1.z, a1.w};
            float w[8] = {w0.x, w0.y, w0.z, w0.w, w1.x, w1.y, w1.z, w1.w};
#pragma unroll
            for (int i = 0; i < 8; i++)
#pragma unroll
                for (int j = 0; j < 8; j++) acc[i][j] += a[i] * w[j];
        }
        __syncthreads();
    }

#pragma unroll
    for (int i = 0; i < 8; i++) {
        int gr = m0 + r8 + i;
        if (gr < M) {
            float4 o0, o1;
            o0.x = acc[i][0]; o0.y = acc[i][1]; o0.z = acc[i][2]; o0.w = acc[i][3];
            o1.x = acc[i][4]; o1.y = acc[i][5]; o1.z = acc[i][6]; o1.w = acc[i][7];
            *(float4*)(C + (size_t)gr * 128 + c8) = o0;
            *(float4*)(C + (size_t)gr * 128 + c8 + 4) = o1;
        }
    }
}

// ---------------- emb GEMM (tf32): writes fp16 h ----------------
__global__ __launch_bounds__(256) void emb_gemmt(
    const float* __restrict__ A, const float* __restrict__ W,
    const float* __restrict__ bias, int K)
{
    __shared__ float As[128 * 16];
    __shared__ float Ws[16 * WS_STRIDE];
    int tid = threadIdx.x;
    int lane = tid & 31, warp = tid >> 5;
    int wm = warp >> 2, wn = warp & 3;
    int m0 = blockIdx.x * 128;
    int arow = tid >> 2;
    int slot = tid & 3;
    float4* As4 = (float4*)As;

    float acc[4][4][4];
#pragma unroll
    for (int a = 0; a < 4; a++)
#pragma unroll
        for (int b = 0; b < 4; b++)
#pragma unroll
            for (int c = 0; c < 4; c++) acc[a][b][c] = 0.f;

    for (int k0 = 0; k0 < K; k0 += 16) {
#pragma unroll
        for (int t = 0; t < 2; t++) {
            int r = arow + t * 64;
            int gr = m0 + r;
            float4 v = make_float4(0.f, 0.f, 0.f, 0.f);
            if (gr < NN) v = *(const float4*)(A + (size_t)gr * K + k0 + slot * 4);
            As4[r * 4 + (slot ^ ((r >> 1) & 3))] = v;
        }
#pragma unroll
        for (int t = 0; t < 2; t++) {
            int f4i = tid + t * 256;
            int wr = f4i >> 5, wc = (f4i & 31) * 4;
            *(float4*)&Ws[wr * WS_STRIDE + wc] =
                *(const float4*)(W + (size_t)(k0 + wr) * 128 + wc);
        }
        __syncthreads();
        mma_tile16f(As, Ws, acc, lane, wm, wn);
        __syncthreads();
    }

#pragma unroll
    for (int mt = 0; mt < 4; mt++) {
        int r0 = m0 + wm * 64 + mt * 16 + (lane >> 2);
#pragma unroll
        for (int nt = 0; nt < 4; nt++) {
            int col = wn * 32 + nt * 8 + 2 * (lane & 3);
            float b0 = bias[col], b1 = bias[col + 1];
            if (r0 < NN)
                *(__half2*)(g_h16 + (size_t)r0 * 128 + col) =
                    __floats2half2_rn(acc[mt][nt][0] + b0, acc[mt][nt][1] + b1);
            if (r0 + 8 < NN)
                *(__half2*)(g_h16 + (size_t)(r0 + 8) * 128 + col) =
                    __floats2half2_rn(acc[mt][nt][2] + b0, acc[mt][nt][3] + b1);
        }
    }
}

// ---------------- D GEMM (layer 0) ----------------
__global__ __launch_bounds__(256) void d_gemm(
    const unsigned* __restrict__ Wp, const float* __restrict__ bias)
{
    __shared__ unsigned As2[128 * 16];
    __shared__ unsigned Ws2[16 * WS_STRIDE];
    int tid = threadIdx.x;
    int lane = tid & 31, warp = tid >> 5;
    int wm = warp >> 2, wn = warp & 3;
    int m0 = blockIdx.x * 128;
    int arow = tid >> 2;
    int slot = tid & 3;
    uint4* As4 = (uint4*)As2;

    float acc[4][4][4];
#pragma unroll
    for (int a = 0; a < 4; a++)
#pragma unroll
        for (int b = 0; b < 4; b++)
#pragma unroll
            for (int c = 0; c < 4; c++) acc[a][b][c] = 0.f;

    for (int kt = 0; kt < 4; kt++) {
#pragma unroll
        for (int t = 0; t < 2; t++) {
            int r = arow + t * 64;
            int gr = m0 + r;
            uint4 v = make_uint4(0, 0, 0, 0);
            if (gr < NN)
                v = *(const uint4*)(g_h16 + (size_t)gr * 128 + kt * 32 + slot * 8);
            As4[r * 4 + (slot ^ ((r >> 1) & 3))] = v;
        }
#pragma unroll
        for (int t = 0; t < 2; t++) {
            int f4i = tid + t * 256;
            int wr = f4i >> 5, wc = (f4i & 31) * 4;
            *(uint4*)&Ws2[wr * WS_STRIDE + wc] =
                *(const uint4*)(Wp + (size_t)(kt * 16 + wr) * 128 + wc);
        }
        __syncthreads();
        mma_tile32(As2, Ws2, acc, lane, wm, wn);
        __syncthreads();
    }

#pragma unroll
    for (int mt = 0; mt < 4; mt++) {
        int r0 = m0 + wm * 64 + mt * 16 + (lane >> 2);
#pragma unroll
        for (int nt = 0; nt < 4; nt++) {
            int col = wn * 32 + nt * 8 + 2 * (lane & 3);
            float b0 = bias[col], b1 = bias[col + 1];
            if (r0 < NN)
                *(__half2*)(g_D16 + (size_t)r0 * 128 + col) =
                    __floats2half2_rn(acc[mt][nt][0] + b0, acc[mt][nt][1] + b1);
            if (r0 + 8 < NN)
                *(__half2*)(g_D16 + (size_t)(r0 + 8) * 128 + col) =
                    __floats2half2_rn(acc[mt][nt][2] + b0, acc[mt][nt][3] + b1);
        }
    }
}

// ---------------- fused BN+ReLU + next-layer D GEMM ----------------
__global__ __launch_bounds__(256) void bn_d_gemm(
    const float* __restrict__ gamma, const float* __restrict__ beta,
    const unsigned* __restrict__ Wp, const float* __restrict__ dbias, int doD)
{
    __shared__ unsigned As2[128 * 16];
    __shared__ unsigned Ws2[16 * WS_STRIDE];
    __shared__ float ssc[128], sof[128];
    int tid = threadIdx.x;
    int lane = tid & 31, warp = tid >> 5;
    int wm = warp >> 2, wn = warp & 3;
    int m0 = blockIdx.x * 128;
    int arow = tid >> 2;
    int slot = tid & 3;
    uint4* As4 = (uint4*)As2;

    if (tid < 128) {
        const float invN = 1.f / (float)NN;
        float mu = g_bn[tid] * invN;
        float var = g_bn[128 + tid] * invN - mu * mu;
        float sc = rsqrtf(var + EPS_BN) * gamma[tid];
        ssc[tid] = sc;
        sof[tid] = beta[tid] - mu * sc;
    }
    __syncthreads();

    float acc[4][4][4];
#pragma unroll
    for (int a = 0; a < 4; a++)
#pragma unroll
        for (int b = 0; b < 4; b++)
#pragma unroll
            for (int c = 0; c < 4; c++) acc[a][b][c] = 0.f;

    for (int kt = 0; kt < 4; kt++) {
#pragma unroll
        for (int t = 0; t < 2; t++) {
            int r = arow + t * 64;
            int gr = m0 + r;
            int c0 = kt * 32 + slot * 8;
            uint4 hv = make_uint4(0, 0, 0, 0);
            if (gr < NN) {
                float4 x0 = *(const float4*)(g_h2 + (size_t)gr * 128 + c0);
                float4 x1 = *(const float4*)(g_h2 + (size_t)gr * 128 + c0 + 4);
                float y0 = fmaxf(x0.x * ssc[c0 + 0] + sof[c0 + 0], 0.f);
                float y1 = fmaxf(x0.y * ssc[c0 + 1] + sof[c0 + 1], 0.f);
                float y2 = fmaxf(x0.z * ssc[c0 + 2] + sof[c0 + 2], 0.f);
                float y3 = fmaxf(x0.w * ssc[c0 + 3] + sof[c0 + 3], 0.f);
                float y4 = fmaxf(x1.x * ssc[c0 + 4] + sof[c0 + 4], 0.f);
                float y5 = fmaxf(x1.y * ssc[c0 + 5] + sof[c0 + 5], 0.f);
                float y6 = fmaxf(x1.z * ssc[c0 + 6] + sof[c0 + 6], 0.f);
                float y7 = fmaxf(x1.w * ssc[c0 + 7] + sof[c0 + 7], 0.f);
                __half2 p0 = __floats2half2_rn(y0, y1);
                __half2 p1 = __floats2half2_rn(y2, y3);
                __half2 p2 = __floats2half2_rn(y4, y5);
                __half2 p3 = __floats2half2_rn(y6, y7);
                hv = make_uint4(*(unsigned*)&p0, *(unsigned*)&p1,
                                *(unsigned*)&p2, *(unsigned*)&p3);
                *(uint4*)(g_h16 + (size_t)gr * 128 + c0) = hv;
            }
            As4[r * 4 + (slot ^ ((r >> 1) & 3))] = hv;
        }
        if (doD) {
#pragma unroll
            for (int t = 0; t < 2; t++) {
                int f4i = tid + t * 256;
                int wr = f4i >> 5, wc = (f4i & 31) * 4;
                *(uint4*)&Ws2[wr * WS_STRIDE + wc] =
                    *(const uint4*)(Wp + (size_t)(kt * 16 + wr) * 128 + wc);
            }
        }
        __syncthreads();
        if (doD) mma_tile32(As2, Ws2, acc, lane, wm, wn);
        __syncthreads();
    }

    if (doD) {
#pragma unroll
        for (int mt = 0; mt < 4; mt++) {
            int r0 = m0 + wm * 64 + mt * 16 + (lane >> 2);
#pragma unroll
            for (int nt = 0; nt < 4; nt++) {
                int col = wn * 32 + nt * 8 + 2 * (lane & 3);
                float b0 = dbias[col], b1 = dbias[col + 1];
                if (r0 < NN)
                    *(__half2*)(g_D16 + (size_t)r0 * 128 + col) =
                        __floats2half2_rn(acc[mt][nt][0] + b0, acc[mt][nt][1] + b1);
                if (r0 + 8 < NN)
                    *(__half2*)(g_D16 + (size_t)(r0 + 8) * 128 + col) =
                        __floats2half2_rn(acc[mt][nt][2] + b0, acc[mt][nt][3] + b1);
            }
        }
    }
}

// ---------------- lin GEMM fp16 with fused BN stats ----------------
__global__ __launch_bounds__(256) void lin_gemm_bn(
    const unsigned* __restrict__ Wp, const float* __restrict__ bias)
{
    __shared__ unsigned As2[128 * 16];
    __shared__ unsigned Ws2[16 * WS_STRIDE];
    __shared__ float sbn[256];
    int tid = threadIdx.x;
    int lane = tid & 31, warp = tid >> 5;
    int wm = warp >> 2, wn = warp & 3;
    int m0 = blockIdx.x * 128;
    int arow = tid >> 2;
    int slot = tid & 3;
    uint4* As4 = (uint4*)As2;
    sbn[tid] = 0.f;

    float acc[4][4][4];
#pragma unroll
    for (int a = 0; a < 4; a++)
#pragma unroll
        for (int b = 0; b < 4; b++)
#pragma unroll
            for (int c = 0; c < 4; c++) acc[a][b][c] = 0.f;

    for (int kt = 0; kt < 4; kt++) {
#pragma unroll
        for (int t = 0; t < 2; t++) {
            int r = arow + t * 64;
            int gr = m0 + r;
            uint4 v = make_uint4(0, 0, 0, 0);
            if (gr < NN)
                v = *(const uint4*)(g_tmp16 + (size_t)gr * 128 + kt * 32 + slot * 8);
            As4[r * 4 + (slot ^ ((r >> 1) & 3))] = v;
        }
#pragma unroll
        for (int t = 0; t < 2; t++) {
            int f4i = tid + t * 256;
            int wr = f4i >> 5, wc = (f4i & 31) * 4;
            *(uint4*)&Ws2[wr * WS_STRIDE + wc] =
                *(const uint4*)(Wp + (size_t)(kt * 16 + wr) * 128 + wc);
        }
        __syncthreads();
        mma_tile32(As2, Ws2, acc, lane, wm, wn);
        __syncthreads();
    }

    float csum[4][2] = {}, csq[4][2] = {};
#pragma unroll
    for (int mt = 0; mt < 4; mt++) {
        int r0 = m0 + wm * 64 + mt * 16 + (lane >> 2);
#pragma unroll
        for (int nt = 0; nt < 4; nt++) {
            int col = wn * 32 + nt * 8 + 2 * (lane & 3);
            float b0 = bias[col], b1 = bias[col + 1];
            float v0 = acc[mt][nt][0] + b0, v1 = acc[mt][nt][1] + b1;
            float v2 = acc[mt][nt][2] + b0, v3 = acc[mt][nt][3] + b1;
            if (r0 < NN) {
                *(float2*)(g_h2 + (size_t)r0 * 128 + col) = make_float2(v0, v1);
                csum[nt][0] += v0; csq[nt][0] += v0 * v0;
                csum[nt][1] += v1; csq[nt][1] += v1 * v1;
            }
            if (r0 + 8 < NN) {
                *(float2*)(g_h2 + (size_t)(r0 + 8) * 128 + col) = make_float2(v2, v3);
                csum[nt][0] += v2; csq[nt][0] += v2 * v2;
                csum[nt][1] += v3; csq[nt][1] += v3 * v3;
            }
        }
    }
#pragma unroll
    for (int nt = 0; nt < 4; nt++)
#pragma unroll
        for (int j = 0; j < 2; j++) {
            float s = csum[nt][j], q = csq[nt][j];
            s += __shfl_down_sync(0xffffffffu, s, 16);
            s += __shfl_down_sync(0xffffffffu, s, 8);
            s += __shfl_down_sync(0xffffffffu, s, 4);
            q += __shfl_down_sync(0xffffffffu, q, 16);
            q += __shfl_down_sync(0xffffffffu, q, 8);
            q += __shfl_down_sync(0xffffffffu, q, 4);
            if (lane < 4) {
                int col = wn * 32 + nt * 8 + 2 * lane + j;
                atomicAdd(&sbn[col], s);
                atomicAdd(&sbn[128 + col], q);
            }
        }
    __syncthreads();
    atomicAdd(&g_bn[tid], sbn[tid]);
}

// ---------------- fused edge GEMM (fp16, src+edge, K=160) + aggregation ----------------
__global__ __launch_bounds__(256) void edge_agg(const unsigned* __restrict__ Wp)
{
    extern __shared__ float s_dyn[];
    unsigned* su = (unsigned*)s_dyn;
    float* mt_ = s_dyn;
    __shared__ int sdst[128], ssrc[128], seid[128];

    int tid = threadIdx.x;
    int lane = tid & 31, warp = tid >> 5;
    int wm = warp >> 2, wn = warp & 3;
    int e0 = blockIdx.x * 128;
    int arow = tid >> 2;
    int slot = tid & 3;

    if (tid < 128) {
        int p = e0 + tid;
        sdst[tid] = g_pdst[p];
        ssrc[tid] = g_psrc[p];
        seid[tid] = g_peid[p];
    }
    __syncthreads();

    float acc[4][4][4];
#pragma unroll
    for (int a = 0; a < 4; a++)
#pragma unroll
        for (int b = 0; b < 4; b++)
#pragma unroll
            for (int c = 0; c < 4; c++) acc[a][b][c] = 0.f;

    auto a_sub = [&](int st, int j) { return su + st * 4096 + j * 2048; };
    auto w_sub = [&](int st, int j) { return su + 8192 + st * 4352 + j * 2176; };

    auto load_sub = [&](int kt, int st, int j) {
        unsigned* ab = a_sub(st, j);
        unsigned* wb = w_sub(st, j);
#pragma unroll
        for (int t = 0; t < 2; t++) {
            int r = arow + t * 64;
            const __half* src;
            if (kt < 4) src = g_h16 + (size_t)ssrc[r] * H + kt * 32 + slot * 8;
            else        src = g_ea16 + (size_t)seid[r] * 32 + slot * 8;
            cp16(&ab[r * 16 + ((slot ^ ((r >> 1) & 3)) << 2)], src);
        }
#pragma unroll
        for (int t = 0; t < 2; t++) {
            int f4i = tid + t * 256;
            int wr = f4i >> 5, wc = (f4i & 31) * 4;
            cp16(&wb[wr * WS_STRIDE + wc], Wp + (size_t)(kt * 16 + wr) * 128 + wc);
        }
    };

    load_sub(0, 0, 0); load_sub(1, 0, 1);
    CP_COMMIT();
    for (int p = 0; p < 3; p++) {
        if (p < 2) {
            int st = (p + 1) & 1;
            load_sub(2 * p + 2, st, 0);
            if (2 * p + 3 < 5) load_sub(2 * p + 3, st, 1);
            CP_COMMIT(); CP_WAIT1();
        } else CP_WAIT0();
        __syncthreads();
        int st = p & 1;
        mma_tile32(a_sub(st, 0), w_sub(st, 0), acc, lane, wm, wn);
        if (2 * p + 1 < 5)
            mma_tile32(a_sub(st, 1), w_sub(st, 1), acc, lane, wm, wn);
        __syncthreads();
    }

#pragma unroll
    for (int mt2 = 0; mt2 < 4; mt2++) {
        int r0 = wm * 64 + mt2 * 16 + (lane >> 2);
#pragma unroll
        for (int nt = 0; nt < 4; nt++) {
            int col = wn * 32 + nt * 8 + 2 * (lane & 3);
            *(float2*)&mt_[r0 * 132 + col] =
                make_float2(acc[mt2][nt][0], acc[mt2][nt][1]);
            *(float2*)&mt_[(r0 + 8) * 132 + col] =
                make_float2(acc[mt2][nt][2], acc[mt2][nt][3]);
        }
    }
    __syncthreads();

    int c = tid & 127, g2 = tid >> 7;
    int nfirst = sdst[0], nlast = sdst[127];
    for (int n = nfirst + g2; n <= nlast; n += 2) {
        int s = g_start[n], e = g_start[n + 1];
        if (s == e) continue;
        int lo = max(s, e0), hi = min(e, e0 + 128);
        if (lo >= hi) continue;
        float sumv = 0.f, sq = 0.f, mn = INFINITY, mx = -INFINITY;
        for (int r = lo - e0; r < hi - e0; r++) {
            float v = mt_[r * 132 + c];
            sumv += v; sq += v * v;
            mn = fminf(mn, v); mx = fmaxf(mx, v);
        }
        size_t idx = (size_t)n * H + c;
        if (s >= e0 && e <= e0 + 128) {
            float Dv = __half2float(g_D16[idx]);
            float degc = (float)(e - s);
            float inv = 1.f / degc;
            float mean = sumv * inv;
            float var = fmaxf(sq * inv - mean * mean, 0.f);
            g_mean16[idx] = __float2half_rn(Dv + mean);
            g_std16[idx] = __float2half_rn(sqrtf(var + EPS_STD));
            g_mn16[idx] = __float2half_rn(Dv + mn);
            g_mx16[idx] = __float2half_rn(Dv + mx);
        } else {
            atomicAdd(&g_bsum[idx], sumv);
            atomicAdd(&g_bsq[idx], sq);
            atomicMinF(&g_bmn[idx], mn);
            atomicMaxF(&g_bmx[idx], mx);
        }
    }
}

// ---------------- boundary helpers ----------------
__global__ void bnd_build() {
    int n = blockIdx.x * blockDim.x + threadIdx.x;
    if (n >= NN) return;
    int s = g_start[n], e = g_start[n + 1];
    bool bnd = (s == e) || ((s >> 7) != ((e - 1) >> 7));
    if (bnd) {
        int p = atomicAdd(&g_bcnt, 1);
        g_blist[p] = n;
    }
}
__global__ void init_bnd() {
    int B = g_bcnt;
    int total = B * 128;
    for (int i = blockIdx.x * blockDim.x + threadIdx.x; i < total;
         i += gridDim.x * blockDim.x) {
        int n = g_blist[i >> 7];
        int c = i & 127;
        size_t idx = (size_t)n * H + c;
        g_bsum[idx] = 0.f; g_bsq[idx] = 0.f;
        g_bmn[idx] = INFINITY; g_bmx[idx] = -INFINITY;
    }
}
// finalize boundary nodes for this layer, then (optionally) reset for next layer
__global__ void fin_init_bnd(int doInit) {
    int B = g_bcnt;
    int total = B * 128;
    for (int i = blockIdx.x * blockDim.x + threadIdx.x; i < total;
         i += gridDim.x * blockDim.x) {
        int n = g_blist[i >> 7];
        int c = i & 127;
        size_t idx = (size_t)n * H + c;
        int cnt = g_start[n + 1] - g_start[n];
        if (cnt == 0) {
            g_mean16[idx] = __float2half_rn(0.f);
            g_std16[idx] = __float2half_rn(sqrtf(EPS_STD));
            g_mn16[idx] = __float2half_rn(0.f);
            g_mx16[idx] = __float2half_rn(0.f);
        } else {
            float Dv = __half2float(g_D16[idx]);
            float inv = 1.f / (float)cnt;
            float mean = g_bsum[idx] * inv;
            float var = fmaxf(g_bsq[idx] * inv - mean * mean, 0.f);
            g_mean16[idx] = __float2half_rn(Dv + mean);
            g_std16[idx] = __float2half_rn(sqrtf(var + EPS_STD));
            g_mn16[idx] = __float2half_rn(Dv + g_bmn[idx]);
            g_mx16[idx] = __float2half_rn(Dv + g_bmx[idx]);
        }
        if (doInit) {
            g_bsum[idx] = 0.f; g_bsq[idx] = 0.f;
            g_bmn[idx] = INFINITY; g_bmx[idx] = -INFINITY;
        }
    }
}

// ---------------- post-NN gather-GEMM fp16 (2-stage, reordered scaling) ----------------
__global__ __launch_bounds__(256) void post_gemmt(const unsigned* __restrict__ Wp,
                                                  const float* __restrict__ bias)
{
    extern __shared__ float s_dyn[];
    unsigned* su = (unsigned*)s_dyn;
    int tid = threadIdx.x;
    int lane = tid & 31, warp = tid >> 5;
    int wm = warp >> 2, wn = warp & 3;
    int n0 = blockIdx.x * 128;
    int arow = tid >> 2;
    int slot = tid & 3;

    float sa[8], si2[8];
#pragma unroll
    for (int mt = 0; mt < 4; mt++)
#pragma unroll
        for (int hh = 0; hh < 2; hh++) {
            int n = n0 + wm * 64 + mt * 16 + (lane >> 2) + hh * 8;
            if (n >= NN) n = NN - 1;
            float a = g_amp[n], ia = g_iamp[n];
            sa[mt * 2 + hh] = a;
            si2[mt * 2 + hh] = ia * ia;
        }

    float acc[4][4][4];
#pragma unroll
    for (int a = 0; a < 4; a++)
#pragma unroll
        for (int b = 0; b < 4; b++)
#pragma unroll
            for (int c = 0; c < 4; c++) acc[a][b][c] = 0.f;

    auto a_sub = [&](int st, int j) { return su + st * 4096 + j * 2048; };
    auto w_sub = [&](int st, int j) { return su + 8192 + st * 4352 + j * 2176; };

    auto load_sub = [&](int t, int st, int j) {
        int kt = map_t32(t);
        int b = kt >> 2;
        const __half* srcb;
        if (b == 0) srcb = g_h16;
        else {
            int a = (b - 1) & 3;
            srcb = (a == 0) ? g_mean16 : (a == 1) ? g_mn16 : (a == 2) ? g_mx16 : g_std16;
        }
        int kk0 = (kt & 3) * 32;
        unsigned* ab = a_sub(st, j);
        unsigned* wb = w_sub(st, j);
#pragma unroll
        for (int tt = 0; tt < 2; tt++) {
            int r = arow + tt * 64;
            int n = n0 + r;
            if (n >= NN) n = NN - 1;
            cp16(&ab[r * 16 + ((slot ^ ((r >> 1) & 3)) << 2)],
                 srcb + (size_t)n * H + kk0 + slot * 8);
        }
#pragma unroll
        for (int tt = 0; tt < 2; tt++) {
            int f4i = tid + tt * 256;
            int wr = f4i >> 5, wc = (f4i & 31) * 4;
            cp16(&wb[wr * WS_STRIDE + wc], Wp + (size_t)(kt * 16 + wr) * 128 + wc);
        }
    };

    load_sub(0, 0, 0); load_sub(1, 0, 1);
    CP_COMMIT();
    for (int p = 0; p < 26; p++) {
        if (p < 25) {
            int st = (p + 1) & 1;
            load_sub(2 * p + 2, st, 0);
            load_sub(2 * p + 3, st, 1);
            CP_COMMIT(); CP_WAIT1();
        } else CP_WAIT0();
        __syncthreads();
        int st = p & 1;
        mma_tile32(a_sub(st, 0), w_sub(st, 0), acc, lane, wm, wn);
        mma_tile32(a_sub(st, 1), w_sub(st, 1), acc, lane, wm, wn);
        __syncthreads();
        if (p == 7) {
#pragma unroll
            for (int mt = 0; mt < 4; mt++)
#pragma unroll
                for (int nt = 0; nt < 4; nt++) {
                    acc[mt][nt][0] *= si2[mt * 2];     acc[mt][nt][1] *= si2[mt * 2];
                    acc[mt][nt][2] *= si2[mt * 2 + 1]; acc[mt][nt][3] *= si2[mt * 2 + 1];
                }
        } else if (p == 15) {
#pragma unroll
            for (int mt = 0; mt < 4; mt++)
#pragma unroll
                for (int nt = 0; nt < 4; nt++) {
                    acc[mt][nt][0] *= sa[mt * 2];     acc[mt][nt][1] *= sa[mt * 2];
                    acc[mt][nt][2] *= sa[mt * 2 + 1]; acc[mt][nt][3] *= sa[mt * 2 + 1];
                }
        }
    }

#pragma unroll
    for (int mt = 0; mt < 4; mt++) {
        int r0 = n0 + wm * 64 + mt * 16 + (lane >> 2);
#pragma unroll
        for (int nt = 0; nt < 4; nt++) {
            int col = wn * 32 + nt * 8 + 2 * (lane & 3);
            float b0 = bias[col], b1 = bias[col + 1];
            if (r0 < NN)
                *(__half2*)(g_tmp16 + (size_t)r0 * 128 + col) =
                    __floats2half2_rn(acc[mt][nt][0] + b0, acc[mt][nt][1] + b1);
            if (r0 + 8 < NN)
                *(__half2*)(g_tmp16 + (size_t)(r0 + 8) * 128 + col) =
                    __floats2half2_rn(acc[mt][nt][2] + b0, acc[mt][nt][3] + b1);
        }
    }
}

// ---------------- batched packing / conversion ----------------
__global__ void pack_dL(const float* __restrict__ preW) {
    int idx = blockIdx.x * blockDim.x + threadIdx.x;
    if (idx >= NL * KP_D * 128) return;
    int l = idx / (KP_D * 128);
    int r = idx - l * (KP_D * 128);
    int kp = r >> 7, n = r & 127;
    const float* base = preW + (size_t)l * 384 * H;
    float lo = base[(size_t)(2 * kp) * H + n];
    float hi = base[(size_t)(2 * kp + 1) * H + n];
    __half2 h = __floats2half2_rn(lo, hi);
    g_dWH[idx] = *(unsigned*)&h;
}
__global__ void pack_eL(const float* __restrict__ preW) {
    int idx = blockIdx.x * blockDim.x + threadIdx.x;
    if (idx >= NL * KP_EDGE * 128) return;
    int l = idx / (KP_EDGE * 128);
    int r = idx - l * (KP_EDGE * 128);
    int kp = r >> 7, n = r & 127;
    float v[2];
#pragma unroll
    for (int j = 0; j < 2; j++) {
        int k = 2 * kp + j;
        if (k < 128)      v[j] = preW[(size_t)l * 384 * H + (size_t)(128 + k) * H + n];
        else if (k < 144) v[j] = g_W2[(size_t)l * 16 * H + (size_t)(k - 128) * H + n];
        else              v[j] = 0.f;
    }
    __half2 h = __floats2half2_rn(v[0], v[1]);
    g_WsrcH[idx] = *(unsigned*)&h;
}
__global__ void pack_genL(const float* __restrict__ src, size_t strideL,
                          unsigned* __restrict__ out, int kpairs, int kmax) {
    int idx = blockIdx.x * blockDim.x + threadIdx.x;
    if (idx >= NL * kpairs * 128) return;
    int l = idx / (kpairs * 128);
    int r = idx - l * (kpairs * 128);
    int kp = r >> 7, n = r & 127;
    const float* base = src + (size_t)l * strideL;
    float lo = (2 * kp < kmax) ? base[(size_t)(2 * kp) * 128 + n] : 0.f;
    float hi = (2 * kp + 1 < kmax) ? base[(size_t)(2 * kp + 1) * 128 + n] : 0.f;
    __half2 h = __floats2half2_rn(lo, hi);
    out[idx] = *(unsigned*)&h;
}
__global__ void ea_pack(const float* __restrict__ ea) {
    int idx = blockIdx.x * blockDim.x + threadIdx.x;
    if (idx >= NE * 32) return;
    int e = idx >> 5, j = idx & 31;
    g_ea16[idx] = __float2half_rn(j < 16 ? ea[(size_t)e * 16 + j] : 0.f);
}
__global__ void biasm_kL(const float* __restrict__ be, const float* __restrict__ ebB,
                         const float* __restrict__ preW, const float* __restrict__ pbB) {
    int l = blockIdx.x;
    int j = threadIdx.x;
    const float* T1 = g_T1 + (size_t)l * H * H;
    const float* P2 = preW + (size_t)l * 384 * H + 256 * H;
    float s = pbB[l * H + j];
    for (int k = 0; k < H; k++) s += be[k] * T1[k * H + j];
    for (int k = 0; k < H; k++) s += ebB[l * H + k] * P2[k * H + j];
    g_biasmL[l * H + j] = s;
}

// ---------------- sort / scan ----------------
__global__ void deg_count(const int* __restrict__ dstI) {
    int e = blockIdx.x * blockDim.x + threadIdx.x;
    if (e < NE) atomicAdd(&g_cnt[dstI[e]], 1);
}
__global__ __launch_bounds__(256) void scan1() {
    int b = blockIdx.x, t = threadIdx.x;
    int n = b * CHUNK + t;
    int v = (t < CHUNK && n < NN) ? g_cnt[n] : 0;
    int lane = t & 31, wid = t >> 5;
    int x = v;
#pragma unroll
    for (int off = 1; off < 32; off <<= 1) {
        int u = __shfl_up_sync(0xffffffffu, x, off);
        if (lane >= off) x += u;
    }
    __shared__ int wsum[8];
    if (lane == 31) wsum[wid] = x;
    __syncthreads();
    if (t == 0) {
        int r = 0;
#pragma unroll
        for (int i = 0; i < 8; i++) { int tmp = wsum[i]; wsum[i] = r; r += tmp; }
        g_part[b] = r;
    }
    __syncthreads();
    int excl = x - v + wsum[wid];
    if (t < CHUNK && n < NN) g_start[n] = excl;
}
__global__ void scan2() {
    int t = threadIdx.x;
    int v = g_part[t];
    int lane = t & 31, wid = t >> 5;
    int x = v;
#pragma unroll
    for (int off = 1; off < 32; off <<= 1) {
        int u = __shfl_up_sync(0xffffffffu, x, off);
        if (lane >= off) x += u;
    }
    __shared__ int wsum[4];
    if (lane == 31) wsum[wid] = x;
    __syncthreads();
    if (t == 0) {
        int r = 0;
#pragma unroll
        for (int i = 0; i < 4; i++) { int tmp = wsum[i]; wsum[i] = r; r += tmp; }
    }
    __syncthreads();
    g_part[t] = x - v + wsum[wid];
}
__global__ void scan3() {
    int n = blockIdx.x * blockDim.x + threadIdx.x;
    if (n < NN) {
        int s = g_start[n] + g_part[n / CHUNK];
        g_start[n] = s;
        g_cursor[n] = s;
    }
    if (n == 0) g_start[NN] = NE;
}
__global__ void scatter_k(const int* __restrict__ srcI, const int* __restrict__ dstI) {
    int e = blockIdx.x * blockDim.x + threadIdx.x;
    if (e >= NE) return;
    int d = dstI[e];
    int p = atomicAdd(&g_cursor[d], 1);
    g_psrc[p] = srcI[e];
    g_pdst[p] = d;
    g_peid[p] = e;
}
__global__ void amp_k() {
    int n = blockIdx.x * blockDim.x + threadIdx.x;
    if (n >= NN) return;
    float degc = fmaxf((float)g_cnt[n], 1.f);
    float a = logf(degc + 1.f) / AVG_LOG;
    g_amp[n] = a;
    g_iamp[n] = 1.f / a;
}

// ---------------- pool / head ----------------
__global__ void pool_k(const int* __restrict__ batch) {
    int c = threadIdx.x;
    int start = blockIdx.x * 256;
    int end = min(start + 256, NN);
    if (start >= NN) return;
    float acc = 0.f;
    int cur = batch[start];
    for (int n = start; n < end; n++) {
        int g = batch[n];
        if (g != cur) { atomicAdd(&g_pool[cur * H + c], acc); acc = 0.f; cur = g; }
        acc += __half2float(g_h16[(size_t)n * H + c]);
    }
    atomicAdd(&g_pool[cur * H + c], acc);
}
__global__ void head1_k(const float* __restrict__ W1, const float* __restrict__ b1) {
    int idx = blockIdx.x * blockDim.x + threadIdx.x;
    if (idx >= NGR * 64) return;
    int g = idx >> 6, j = idx & 63;
    float s = b1[j];
    for (int k = 0; k < H; k++) s += g_pool[g * H + k] * W1[k * 64 + j];
    g_z[idx] = fmaxf(s, 0.f);
}
__global__ void head2_k(const float* __restrict__ W2, const float* __restrict__ b2,
                        float* __restrict__ out) {
    int idx = blockIdx.x * blockDim.x + threadIdx.x;
    if (idx >= NGR * NOUT) return;
    int g = idx / NOUT, j = idx % NOUT;
    float s = b2[j];
    for (int k = 0; k < 64; k++) s += g_z[g * 64 + k] * W2[k * NOUT + j];
    out[idx] = s;
}

// ---------------- launch ----------------
extern "C" void kernel_launch(void* const* d_in, const int* in_sizes, int n_in,
                              void* d_out, int out_size)
{
    int iEI = 1, iBatch = 2, iEA = 3;
    if (in_sizes[1] == NE * 16) { iEA = 1; iEI = 2; iBatch = 3; }

    const float* x         = (const float*)d_in[0];
    const int*   edge_index= (const int*)  d_in[iEI];
    const int*   batch     = (const int*)  d_in[iBatch];
    const float* edge_attr = (const float*)d_in[iEA];
    const float* node_emb_W= (const float*)d_in[4];
    const float* node_emb_b= (const float*)d_in[5];
    const float* edge_emb_W= (const float*)d_in[6];
    const float* edge_emb_b= (const float*)d_in[7];
    const float* edge_enc_W= (const float*)d_in[8];
    const float* edge_enc_b= (const float*)d_in[9];
    const float* pre_W     = (const float*)d_in[10];
    const float* pre_b     = (const float*)d_in[11];
    const float* post_W    = (const float*)d_in[12];
    const float* post_b    = (const float*)d_in[13];
    const float* lin_W     = (const float*)d_in[14];
    const float* lin_b     = (const float*)d_in[15];
    const float* bn_gamma  = (const float*)d_in[16];
    const float* bn_beta   = (const float*)d_in[17];
    const float* head1_W   = (const float*)d_in[18];
    const float* head1_b   = (const float*)d_in[19];
    const float* head2_W   = (const float*)d_in[20];
    const float* head2_b   = (const float*)d_in[21];

    const int* srcI = edge_index;
    const int* dstI = edge_index + NE;

    float *p_T1, *p_W2, *p_biasm, *p_bn, *p_pool;
    unsigned *p_wsrcH, *p_postWH, *p_linWH, *p_dWH;
    int *p_cnt, *p_bcnt;
    cudaGetSymbolAddress((void**)&p_T1,     g_T1);
    cudaGetSymbolAddress((void**)&p_W2,     g_W2);
    cudaGetSymbolAddress((void**)&p_wsrcH,  g_WsrcH);
    cudaGetSymbolAddress((void**)&p_postWH, g_postWH);
    cudaGetSymbolAddress((void**)&p_linWH,  g_linWH);
    cudaGetSymbolAddress((void**)&p_dWH,    g_dWH);
    cudaGetSymbolAddress((void**)&p_biasm,  g_biasmL);
    cudaGetSymbolAddress((void**)&p_bn,     g_bn);
    cudaGetSymbolAddress((void**)&p_pool,   g_pool);
    cudaGetSymbolAddress((void**)&p_cnt,    g_cnt);
    cudaGetSymbolAddress((void**)&p_bcnt,   g_bcnt);

    cudaFuncSetAttribute(edge_agg, cudaFuncAttributeMaxDynamicSharedMemorySize, BIG_SMEM);
    cudaFuncSetAttribute(post_gemmt, cudaFuncAttributeMaxDynamicSharedMemorySize, BIG_SMEM);

    // sort prep
    cudaMemsetAsync(p_cnt, 0, NN * sizeof(int));
    cudaMemsetAsync(p_bcnt, 0, sizeof(int));
    deg_count<<<(NE + 255) / 256, 256>>>(dstI);
    scan1<<<SCAN_B, 256>>>();
    scan2<<<1, 128>>>();
    emb_gemmt<<<(NN + 127) / 128, 256>>>(x, node_emb_W, node_emb_b, 64);
    scan3<<<(NN + 255) / 256, 256>>>();
    scatter_k<<<(NE + 255) / 256, 256>>>(srcI, dstI);
    amp_k<<<(NN + 255) / 256, 256>>>();
    bnd_build<<<(NN + 255) / 256, 256>>>();
    ea_pack<<<(NE * 32 + 255) / 256, 256>>>(edge_attr);

    // batched weight prep
    gemm128L<<<dim3(1, NL), 256>>>(edge_enc_W, (size_t)H * H,
                                   pre_W + 256 * H, (size_t)384 * H,
                                   p_T1, (size_t)H * H, 128, 128);
    gemm128L<<<dim3(1, NL), 256>>>(edge_emb_W, 0,
                                   p_T1, (size_t)H * H,
                                   p_W2, (size_t)16 * H, 16, 128);
    biasm_kL<<<NL, 128>>>(edge_emb_b, edge_enc_b, pre_W, pre_b);
    pack_dL<<<(NL * KP_D * 128 + 255) / 256, 256>>>(pre_W);
    pack_eL<<<(NL * KP_EDGE * 128 + 255) / 256, 256>>>(pre_W);
    pack_genL<<<(NL * KP_POST * 128 + 255) / 256, 256>>>(post_W, (size_t)13 * H * H,
                                                         p_postWH, KP_POST, 13 * H);
    pack_genL<<<(NL * KP_LIN * 128 + 255) / 256, 256>>>(lin_W, (size_t)H * H,
                                                        p_linWH, KP_LIN, H);

    d_gemm<<<(NN + 127) / 128, 256>>>(p_dWH, p_biasm);
    init_bnd<<<64, 256>>>();

    for (int l = 0; l < NL; l++) {
        edge_agg<<<NE / 128, 256, BIG_SMEM>>>(p_wsrcH + (size_t)l * KP_EDGE * H);
        fin_init_bnd<<<64, 256>>>(l < NL - 1 ? 1 : 0);

        post_gemmt<<<(NN + 127) / 128, 256, BIG_SMEM>>>(
            p_postWH + (size_t)l * KP_POST * H, post_b + l * H);

        cudaMemsetAsync(p_bn, 0, 2 * H * sizeof(float));
        lin_gemm_bn<<<(NN + 127) / 128, 256>>>(p_linWH + (size_t)l * KP_LIN * H,
                                               lin_b + l * H);
        if (l < NL - 1)
            bn_d_gemm<<<(NN + 127) / 128, 256>>>(bn_gamma + l * H, bn_beta + l * H,
                                                 p_dWH + (size_t)(l + 1) * KP_D * H,
                                                 p_biasm + (l + 1) * H, 1);
        else
            bn_d_gemm<<<(NN + 127) / 128, 256>>>(bn_gamma + l * H, bn_beta + l * H,
                                                 p_dWH, p_biasm, 0);
    }

    cudaMemsetAsync(p_pool, 0, NGR * H * sizeof(float));
    pool_k<<<(NN + 255) / 256, 128>>>(batch);
    head1_k<<<8, 256>>>(head1_W, head1_b);
    head2_k<<<2, 256>>>(head2_W, head2_b, (float*)d_out);
}

// round 16
// speedup vs baseline: 1.1378x; 1.0019x over previous
#include <cuda_runtime.h>
#include <cuda_fp16.h>
#include <math.h>

#define NN 30000
#define NE 480000
#define H 128
#define NL 4
#define NGR 32
#define NOUT 12
#define AVG_LOG 1.38214548f
#define EPS_BN 1e-5f
#define EPS_STD 1e-5f
#define KP_EDGE 80
#define KP_POST 832
#define KP_LIN 64
#define KP_D 64
#define WS_STRIDE 136
#define SCAN_B 128
#define CHUNK 235
#define BIG_SMEM 67584

// ---------------- scratch ----------------
__device__ float g_h2[NN * H];
__device__ __half g_h16[NN * H];
__device__ __half g_tmp16[NN * H];
__device__ __half g_D16[NN * H];
__device__ __half g_mean16[NN * H];
__device__ __half g_std16[NN * H];
__device__ __half g_mn16[NN * H];
__device__ __half g_mx16[NN * H];
__device__ __half g_ea16[NE * 32];
__device__ float g_bsum[NN * H];
__device__ float g_bsq[NN * H];
__device__ float g_bmn[NN * H];
__device__ float g_bmx[NN * H];
__device__ int   g_cnt[NN];
__device__ int   g_start[NN + 1];
__device__ int   g_cursor[NN];
__device__ int   g_part[SCAN_B];
__device__ int   g_psrc[NE];
__device__ int   g_pdst[NE];
__device__ int   g_peid[NE];
__device__ int   g_blist[NN];
__device__ int   g_bcnt;
__device__ float g_amp[NN];
__device__ float g_iamp[NN];
__device__ unsigned g_WsrcH[NL * KP_EDGE * H];
__device__ unsigned g_postWH[NL * KP_POST * H];
__device__ unsigned g_linWH[NL * KP_LIN * H];
__device__ unsigned g_dWH[NL * KP_D * H];
__device__ float g_T1[NL * H * H];
__device__ float g_W2[NL * 16 * H];
__device__ float g_biasmL[NL * H];
__device__ float g_bn[2 * H];
__device__ float g_pool[NGR * H];
__device__ float g_z[NGR * 64];

// ---------------- helpers ----------------
__device__ __forceinline__ void atomicMaxF(float* a, float v) {
    if (v >= 0.f) atomicMax((int*)a, __float_as_int(v));
    else          atomicMin((unsigned int*)a, __float_as_uint(v));
}
__device__ __forceinline__ void atomicMinF(float* a, float v) {
    if (v >= 0.f) atomicMin((int*)a, __float_as_int(v));
    else          atomicMax((unsigned int*)a, __float_as_uint(v));
}
__device__ __forceinline__ void cp16(void* smem, const void* g) {
    unsigned sa = (unsigned)__cvta_generic_to_shared(smem);
    asm volatile("cp.async.cg.shared.global [%0], [%1], 16;\n" :: "r"(sa), "l"(g));
}
#define CP_COMMIT() asm volatile("cp.async.commit_group;\n" ::: "memory")
#define CP_WAIT1()  asm volatile("cp.async.wait_group 1;\n" ::: "memory")
#define CP_WAIT0()  asm volatile("cp.async.wait_group 0;\n" ::: "memory")

__device__ __forceinline__ int map_t32(int t) {
    return (t < 16) ? 36 + t : (t < 32) ? 20 + (t - 16) : (t - 32);
}

// fp16 mma over one 32-k tile; A fragments via ldmatrix.x4 (layout verified
// against the float4-slot XOR swizzle: matrix j = rows base+(j&1)*8+(l&7),
// logical slot ks*2+(j>>1); the 8 addresses of each matrix land in distinct banks).
__device__ __forceinline__ void mma_tile32(const unsigned* As, const unsigned* Ws,
                                           float (&acc)[4][4][4], int lane,
                                           int wm, int wn)
{
    unsigned as_base = (unsigned)__cvta_generic_to_shared(As);
    int j = lane >> 3;
    int rlo = ((j & 1) << 3) + (lane & 7);          // row offset within 16-row tile
#pragma unroll
    for (int ks = 0; ks < 2; ks++) {
        unsigned b0[4], b1[4];
        int bk = ks * 8 + (lane & 3);
        int bn = wn * 32 + (lane >> 2);
#pragma unroll
        for (int nt = 0; nt < 4; nt++) {
            b0[nt] = Ws[bk * WS_STRIDE + bn + nt * 8];
            b1[nt] = Ws[(bk + 4) * WS_STRIDE + bn + nt * 8];
        }
#pragma unroll
        for (int mt = 0; mt < 4; mt++) {
            int r = wm * 64 + mt * 16 + rlo;
            int sl = (ks * 2 + (j >> 1)) ^ ((r >> 1) & 3);
            unsigned addr = as_base + (unsigned)((r * 16 + sl * 4) << 2);
            unsigned a0, a1, a2, a3;
            asm volatile(
                "ldmatrix.sync.aligned.m8n8.x4.shared.b16 {%0,%1,%2,%3}, [%4];"
                : "=r"(a0), "=r"(a1), "=r"(a2), "=r"(a3) : "r"(addr));
#pragma unroll
            for (int nt = 0; nt < 4; nt++) {
                asm volatile(
                    "mma.sync.aligned.m16n8k16.row.col.f32.f16.f16.f32 "
                    "{%0,%1,%2,%3}, {%4,%5,%6,%7}, {%8,%9}, {%0,%1,%2,%3};"
                    : "+f"(acc[mt][nt][0]), "+f"(acc[mt][nt][1]),
                      "+f"(acc[mt][nt][2]), "+f"(acc[mt][nt][3])
                    : "r"(a0), "r"(a1), "r"(a2), "r"(a3),
                      "r"(b0[nt]), "r"(b1[nt]));
            }
        }
    }
}

// tf32 path for emb GEMM (unchanged: no ldmatrix for tf32)
__device__ __forceinline__ unsigned ld_asf(const float* As, int r, int slot, int c) {
    return __float_as_uint(As[r * 16 + ((slot ^ ((r >> 1) & 3)) << 2) + c]);
}
__device__ __forceinline__ void mma_tile16f(const float* As, const float* Ws,
                                            float (&acc)[4][4][4], int lane,
                                            int wm, int wn)
{
#pragma unroll
    for (int ks = 0; ks < 2; ks++) {
        unsigned b0[4], b1[4];
        int bk = ks * 8 + (lane & 3);
        int bn = wn * 32 + (lane >> 2);
#pragma unroll
        for (int nt = 0; nt < 4; nt++) {
            b0[nt] = __float_as_uint(Ws[bk * WS_STRIDE + bn + nt * 8]);
            b1[nt] = __float_as_uint(Ws[(bk + 4) * WS_STRIDE + bn + nt * 8]);
        }
#pragma unroll
        for (int mt = 0; mt < 4; mt++) {
            int r0 = wm * 64 + mt * 16 + (lane >> 2);
            int r1 = r0 + 8;
            int c = lane & 3;
            unsigned a0 = ld_asf(As, r0, ks * 2,     c);
            unsigned a1 = ld_asf(As, r1, ks * 2,     c);
            unsigned a2 = ld_asf(As, r0, ks * 2 + 1, c);
            unsigned a3 = ld_asf(As, r1, ks * 2 + 1, c);
#pragma unroll
            for (int nt = 0; nt < 4; nt++) {
                asm volatile(
                    "mma.sync.aligned.m16n8k8.row.col.f32.tf32.tf32.f32 "
                    "{%0,%1,%2,%3}, {%4,%5,%6,%7}, {%8,%9}, {%0,%1,%2,%3};"
                    : "+f"(acc[mt][nt][0]), "+f"(acc[mt][nt][1]),
                      "+f"(acc[mt][nt][2]), "+f"(acc[mt][nt][3])
                    : "r"(a0), "r"(a1), "r"(a2), "r"(a3),
                      "r"(b0[nt]), "r"(b1[nt]));
            }
        }
    }
}

// ---------------- batched fp32 GEMM for weight prep ----------------
__global__ __launch_bounds__(256) void gemm128L(
    const float* __restrict__ Ab, size_t aStride,
    const float* __restrict__ Wb, size_t wStride,
    float* __restrict__ Cb, size_t cStride, int M, int K)
{
    const float* A = Ab + blockIdx.y * aStride;
    const float* W = Wb + blockIdx.y * wStride;
    float* C = Cb + blockIdx.y * cStride;
    __shared__ float As[16 * 132];
    __shared__ float Ws[16 * 128];
    int tid = threadIdx.x;
    int m0 = blockIdx.x * 128;
    int trow = tid >> 4, tcol = tid & 15;
    int r8 = trow * 8, c8 = tcol * 8;
    int arow = tid >> 2;
    int ac4 = (tid & 3) * 4;

    float acc[8][8];
#pragma unroll
    for (int i = 0; i < 8; i++)
#pragma unroll
        for (int j = 0; j < 8; j++) acc[i][j] = 0.f;

    for (int k0 = 0; k0 < K; k0 += 16) {
#pragma unroll
        for (int t = 0; t < 2; t++) {
            int r = arow + t * 64;
            int gr = m0 + r;
            float4 v = make_float4(0.f, 0.f, 0.f, 0.f);
            if (gr < M) v = *(const float4*)(A + (size_t)gr * K + k0 + ac4);
            As[(ac4 + 0) * 132 + r] = v.x;
            As[(ac4 + 1) * 132 + r] = v.y;
            As[(ac4 + 2) * 132 + r] = v.z;
            As[(ac4 + 3) * 132 + r] = v.w;
        }
#pragma unroll
        for (int t = 0; t < 2; t++) {
            int f4i = tid + t * 256;
            int wr = f4i >> 5, wc = (f4i & 31) * 4;
            *(float4*)&Ws[wr * 128 + wc] = *(const float4*)(W + (size_t)(k0 + wr) * 128 + wc);
        }
        __syncthreads();
#pragma unroll
        for (int kk = 0; kk < 16; kk++) {
            float4 a0 = *(const float4*)&As[kk * 132 + r8];
            float4 a1 = *(const float4*)&As[kk * 132 + r8 + 4];
            float4 w0 = *(const float4*)&Ws[kk * 128 + c8];
            float4 w1 = *(const float4*)&Ws[kk * 128 + c8 + 4];
            float a[8] = {a0.x, a0.y, a0.z, a0.w, a1.x, a1.y, a1.z, a1.w};
            float w[8] = {w0.x, w0.y, w0.z, w0.w, w1.x, w1.y, w1.z, w1.w};
#pragma unroll
            for (int i = 0; i < 8; i++)
#pragma unroll
                for (int j = 0; j < 8; j++) acc[i][j] += a[i] * w[j];
        }
        __syncthreads();
    }

#pragma unroll
    for (int i = 0; i < 8; i++) {
        int gr = m0 + r8 + i;
        if (gr < M) {
            float4 o0, o1;
            o0.x = acc[i][0]; o0.y = acc[i][1]; o0.z = acc[i][2]; o0.w = acc[i][3];
            o1.x = acc[i][4]; o1.y = acc[i][5]; o1.z = acc[i][6]; o1.w = acc[i][7];
            *(float4*)(C + (size_t)gr * 128 + c8) = o0;
            *(float4*)(C + (size_t)gr * 128 + c8 + 4) = o1;
        }
    }
}

// ---------------- emb GEMM (tf32): writes fp16 h ----------------
__global__ __launch_bounds__(256) void emb_gemmt(
    const float* __restrict__ A, const float* __restrict__ W,
    const float* __restrict__ bias, int K)
{
    __shared__ float As[128 * 16];
    __shared__ float Ws[16 * WS_STRIDE];
    int tid = threadIdx.x;
    int lane = tid & 31, warp = tid >> 5;
    int wm = warp >> 2, wn = warp & 3;
    int m0 = blockIdx.x * 128;
    int arow = tid >> 2;
    int slot = tid & 3;
    float4* As4 = (float4*)As;

    float acc[4][4][4];
#pragma unroll
    for (int a = 0; a < 4; a++)
#pragma unroll
        for (int b = 0; b < 4; b++)
#pragma unroll
            for (int c = 0; c < 4; c++) acc[a][b][c] = 0.f;

    for (int k0 = 0; k0 < K; k0 += 16) {
#pragma unroll
        for (int t = 0; t < 2; t++) {
            int r = arow + t * 64;
            int gr = m0 + r;
            float4 v = make_float4(0.f, 0.f, 0.f, 0.f);
            if (gr < NN) v = *(const float4*)(A + (size_t)gr * K + k0 + slot * 4);
            As4[r * 4 + (slot ^ ((r >> 1) & 3))] = v;
        }
#pragma unroll
        for (int t = 0; t < 2; t++) {
            int f4i = tid + t * 256;
            int wr = f4i >> 5, wc = (f4i & 31) * 4;
            *(float4*)&Ws[wr * WS_STRIDE + wc] =
                *(const float4*)(W + (size_t)(k0 + wr) * 128 + wc);
        }
        __syncthreads();
        mma_tile16f(As, Ws, acc, lane, wm, wn);
        __syncthreads();
    }

#pragma unroll
    for (int mt = 0; mt < 4; mt++) {
        int r0 = m0 + wm * 64 + mt * 16 + (lane >> 2);
#pragma unroll
        for (int nt = 0; nt < 4; nt++) {
            int col = wn * 32 + nt * 8 + 2 * (lane & 3);
            float b0 = bias[col], b1 = bias[col + 1];
            if (r0 < NN)
                *(__half2*)(g_h16 + (size_t)r0 * 128 + col) =
                    __floats2half2_rn(acc[mt][nt][0] + b0, acc[mt][nt][1] + b1);
            if (r0 + 8 < NN)
                *(__half2*)(g_h16 + (size_t)(r0 + 8) * 128 + col) =
                    __floats2half2_rn(acc[mt][nt][2] + b0, acc[mt][nt][3] + b1);
        }
    }
}

// ---------------- D GEMM (layer 0) ----------------
__global__ __launch_bounds__(256) void d_gemm(
    const unsigned* __restrict__ Wp, const float* __restrict__ bias)
{
    __shared__ unsigned As2[128 * 16];
    __shared__ unsigned Ws2[16 * WS_STRIDE];
    int tid = threadIdx.x;
    int lane = tid & 31, warp = tid >> 5;
    int wm = warp >> 2, wn = warp & 3;
    int m0 = blockIdx.x * 128;
    int arow = tid >> 2;
    int slot = tid & 3;
    uint4* As4 = (uint4*)As2;

    float acc[4][4][4];
#pragma unroll
    for (int a = 0; a < 4; a++)
#pragma unroll
        for (int b = 0; b < 4; b++)
#pragma unroll
            for (int c = 0; c < 4; c++) acc[a][b][c] = 0.f;

    for (int kt = 0; kt < 4; kt++) {
#pragma unroll
        for (int t = 0; t < 2; t++) {
            int r = arow + t * 64;
            int gr = m0 + r;
            uint4 v = make_uint4(0, 0, 0, 0);
            if (gr < NN)
                v = *(const uint4*)(g_h16 + (size_t)gr * 128 + kt * 32 + slot * 8);
            As4[r * 4 + (slot ^ ((r >> 1) & 3))] = v;
        }
#pragma unroll
        for (int t = 0; t < 2; t++) {
            int f4i = tid + t * 256;
            int wr = f4i >> 5, wc = (f4i & 31) * 4;
            *(uint4*)&Ws2[wr * WS_STRIDE + wc] =
                *(const uint4*)(Wp + (size_t)(kt * 16 + wr) * 128 + wc);
        }
        __syncthreads();
        mma_tile32(As2, Ws2, acc, lane, wm, wn);
        __syncthreads();
    }

#pragma unroll
    for (int mt = 0; mt < 4; mt++) {
        int r0 = m0 + wm * 64 + mt * 16 + (lane >> 2);
#pragma unroll
        for (int nt = 0; nt < 4; nt++) {
            int col = wn * 32 + nt * 8 + 2 * (lane & 3);
            float b0 = bias[col], b1 = bias[col + 1];
            if (r0 < NN)
                *(__half2*)(g_D16 + (size_t)r0 * 128 + col) =
                    __floats2half2_rn(acc[mt][nt][0] + b0, acc[mt][nt][1] + b1);
            if (r0 + 8 < NN)
                *(__half2*)(g_D16 + (size_t)(r0 + 8) * 128 + col) =
                    __floats2half2_rn(acc[mt][nt][2] + b0, acc[mt][nt][3] + b1);
        }
    }
}

// ---------------- fused BN+ReLU + next-layer D GEMM ----------------
__global__ __launch_bounds__(256) void bn_d_gemm(
    const float* __restrict__ gamma, const float* __restrict__ beta,
    const unsigned* __restrict__ Wp, const float* __restrict__ dbias, int doD)
{
    __shared__ unsigned As2[128 * 16];
    __shared__ unsigned Ws2[16 * WS_STRIDE];
    __shared__ float ssc[128], sof[128];
    int tid = threadIdx.x;
    int lane = tid & 31, warp = tid >> 5;
    int wm = warp >> 2, wn = warp & 3;
    int m0 = blockIdx.x * 128;
    int arow = tid >> 2;
    int slot = tid & 3;
    uint4* As4 = (uint4*)As2;

    if (tid < 128) {
        const float invN = 1.f / (float)NN;
        float mu = g_bn[tid] * invN;
        float var = g_bn[128 + tid] * invN - mu * mu;
        float sc = rsqrtf(var + EPS_BN) * gamma[tid];
        ssc[tid] = sc;
        sof[tid] = beta[tid] - mu * sc;
    }
    __syncthreads();

    float acc[4][4][4];
#pragma unroll
    for (int a = 0; a < 4; a++)
#pragma unroll
        for (int b = 0; b < 4; b++)
#pragma unroll
            for (int c = 0; c < 4; c++) acc[a][b][c] = 0.f;

    for (int kt = 0; kt < 4; kt++) {
#pragma unroll
        for (int t = 0; t < 2; t++) {
            int r = arow + t * 64;
            int gr = m0 + r;
            int c0 = kt * 32 + slot * 8;
            uint4 hv = make_uint4(0, 0, 0, 0);
            if (gr < NN) {
                float4 x0 = *(const float4*)(g_h2 + (size_t)gr * 128 + c0);
                float4 x1 = *(const float4*)(g_h2 + (size_t)gr * 128 + c0 + 4);
                float y0 = fmaxf(x0.x * ssc[c0 + 0] + sof[c0 + 0], 0.f);
                float y1 = fmaxf(x0.y * ssc[c0 + 1] + sof[c0 + 1], 0.f);
                float y2 = fmaxf(x0.z * ssc[c0 + 2] + sof[c0 + 2], 0.f);
                float y3 = fmaxf(x0.w * ssc[c0 + 3] + sof[c0 + 3], 0.f);
                float y4 = fmaxf(x1.x * ssc[c0 + 4] + sof[c0 + 4], 0.f);
                float y5 = fmaxf(x1.y * ssc[c0 + 5] + sof[c0 + 5], 0.f);
                float y6 = fmaxf(x1.z * ssc[c0 + 6] + sof[c0 + 6], 0.f);
                float y7 = fmaxf(x1.w * ssc[c0 + 7] + sof[c0 + 7], 0.f);
                __half2 p0 = __floats2half2_rn(y0, y1);
                __half2 p1 = __floats2half2_rn(y2, y3);
                __half2 p2 = __floats2half2_rn(y4, y5);
                __half2 p3 = __floats2half2_rn(y6, y7);
                hv = make_uint4(*(unsigned*)&p0, *(unsigned*)&p1,
                                *(unsigned*)&p2, *(unsigned*)&p3);
                *(uint4*)(g_h16 + (size_t)gr * 128 + c0) = hv;
            }
            As4[r * 4 + (slot ^ ((r >> 1) & 3))] = hv;
        }
        if (doD) {
#pragma unroll
            for (int t = 0; t < 2; t++) {
                int f4i = tid + t * 256;
                int wr = f4i >> 5, wc = (f4i & 31) * 4;
                *(uint4*)&Ws2[wr * WS_STRIDE + wc] =
                    *(const uint4*)(Wp + (size_t)(kt * 16 + wr) * 128 + wc);
            }
        }
        __syncthreads();
        if (doD) mma_tile32(As2, Ws2, acc, lane, wm, wn);
        __syncthreads();
    }

    if (doD) {
#pragma unroll
        for (int mt = 0; mt < 4; mt++) {
            int r0 = m0 + wm * 64 + mt * 16 + (lane >> 2);
#pragma unroll
            for (int nt = 0; nt < 4; nt++) {
                int col = wn * 32 + nt * 8 + 2 * (lane & 3);
                float b0 = dbias[col], b1 = dbias[col + 1];
                if (r0 < NN)
                    *(__half2*)(g_D16 + (size_t)r0 * 128 + col) =
                        __floats2half2_rn(acc[mt][nt][0] + b0, acc[mt][nt][1] + b1);
                if (r0 + 8 < NN)
                    *(__half2*)(g_D16 + (size_t)(r0 + 8) * 128 + col) =
                        __floats2half2_rn(acc[mt][nt][2] + b0, acc[mt][nt][3] + b1);
            }
        }
    }
}

// ---------------- lin GEMM fp16 with fused BN stats ----------------
__global__ __launch_bounds__(256) void lin_gemm_bn(
    const unsigned* __restrict__ Wp, const float* __restrict__ bias)
{
    __shared__ unsigned As2[128 * 16];
    __shared__ unsigned Ws2[16 * WS_STRIDE];
    __shared__ float sbn[256];
    int tid = threadIdx.x;
    int lane = tid & 31, warp = tid >> 5;
    int wm = warp >> 2, wn = warp & 3;
    int m0 = blockIdx.x * 128;
    int arow = tid >> 2;
    int slot = tid & 3;
    uint4* As4 = (uint4*)As2;
    sbn[tid] = 0.f;

    float acc[4][4][4];
#pragma unroll
    for (int a = 0; a < 4; a++)
#pragma unroll
        for (int b = 0; b < 4; b++)
#pragma unroll
            for (int c = 0; c < 4; c++) acc[a][b][c] = 0.f;

    for (int kt = 0; kt < 4; kt++) {
#pragma unroll
        for (int t = 0; t < 2; t++) {
            int r = arow + t * 64;
            int gr = m0 + r;
            uint4 v = make_uint4(0, 0, 0, 0);
            if (gr < NN)
                v = *(const uint4*)(g_tmp16 + (size_t)gr * 128 + kt * 32 + slot * 8);
            As4[r * 4 + (slot ^ ((r >> 1) & 3))] = v;
        }
#pragma unroll
        for (int t = 0; t < 2; t++) {
            int f4i = tid + t * 256;
            int wr = f4i >> 5, wc = (f4i & 31) * 4;
            *(uint4*)&Ws2[wr * WS_STRIDE + wc] =
                *(const uint4*)(Wp + (size_t)(kt * 16 + wr) * 128 + wc);
        }
        __syncthreads();
        mma_tile32(As2, Ws2, acc, lane, wm, wn);
        __syncthreads();
    }

    float csum[4][2] = {}, csq[4][2] = {};
#pragma unroll
    for (int mt = 0; mt < 4; mt++) {
        int r0 = m0 + wm * 64 + mt * 16 + (lane >> 2);
#pragma unroll
        for (int nt = 0; nt < 4; nt++) {
            int col = wn * 32 + nt * 8 + 2 * (lane & 3);
            float b0 = bias[col], b1 = bias[col + 1];
            float v0 = acc[mt][nt][0] + b0, v1 = acc[mt][nt][1] + b1;
            float v2 = acc[mt][nt][2] + b0, v3 = acc[mt][nt][3] + b1;
            if (r0 < NN) {
                *(float2*)(g_h2 + (size_t)r0 * 128 + col) = make_float2(v0, v1);
                csum[nt][0] += v0; csq[nt][0] += v0 * v0;
                csum[nt][1] += v1; csq[nt][1] += v1 * v1;
            }
            if (r0 + 8 < NN) {
                *(float2*)(g_h2 + (size_t)(r0 + 8) * 128 + col) = make_float2(v2, v3);
                csum[nt][0] += v2; csq[nt][0] += v2 * v2;
                csum[nt][1] += v3; csq[nt][1] += v3 * v3;
            }
        }
    }
#pragma unroll
    for (int nt = 0; nt < 4; nt++)
#pragma unroll
        for (int j = 0; j < 2; j++) {
            float s = csum[nt][j], q = csq[nt][j];
            s += __shfl_down_sync(0xffffffffu, s, 16);
            s += __shfl_down_sync(0xffffffffu, s, 8);
            s += __shfl_down_sync(0xffffffffu, s, 4);
            q += __shfl_down_sync(0xffffffffu, q, 16);
            q += __shfl_down_sync(0xffffffffu, q, 8);
            q += __shfl_down_sync(0xffffffffu, q, 4);
            if (lane < 4) {
                int col = wn * 32 + nt * 8 + 2 * lane + j;
                atomicAdd(&sbn[col], s);
                atomicAdd(&sbn[128 + col], q);
            }
        }
    __syncthreads();
    atomicAdd(&g_bn[tid], sbn[tid]);
}

// ---------------- fused edge GEMM (fp16, src+edge, K=160) + aggregation ----------------
__global__ __launch_bounds__(256) void edge_agg(const unsigned* __restrict__ Wp)
{
    extern __shared__ float s_dyn[];
    unsigned* su = (unsigned*)s_dyn;
    float* mt_ = s_dyn;
    __shared__ int sdst[128], ssrc[128], seid[128];

    int tid = threadIdx.x;
    int lane = tid & 31, warp = tid >> 5;
    int wm = warp >> 2, wn = warp & 3;
    int e0 = blockIdx.x * 128;
    int arow = tid >> 2;
    int slot = tid & 3;

    if (tid < 128) {
        int p = e0 + tid;
        sdst[tid] = g_pdst[p];
        ssrc[tid] = g_psrc[p];
        seid[tid] = g_peid[p];
    }
    __syncthreads();

    float acc[4][4][4];
#pragma unroll
    for (int a = 0; a < 4; a++)
#pragma unroll
        for (int b = 0; b < 4; b++)
#pragma unroll
            for (int c = 0; c < 4; c++) acc[a][b][c] = 0.f;

    auto a_sub = [&](int st, int j) { return su + st * 4096 + j * 2048; };
    auto w_sub = [&](int st, int j) { return su + 8192 + st * 4352 + j * 2176; };

    auto load_sub = [&](int kt, int st, int j) {
        unsigned* ab = a_sub(st, j);
        unsigned* wb = w_sub(st, j);
#pragma unroll
        for (int t = 0; t < 2; t++) {
            int r = arow + t * 64;
            const __half* src;
            if (kt < 4) src = g_h16 + (size_t)ssrc[r] * H + kt * 32 + slot * 8;
            else        src = g_ea16 + (size_t)seid[r] * 32 + slot * 8;
            cp16(&ab[r * 16 + ((slot ^ ((r >> 1) & 3)) << 2)], src);
        }
#pragma unroll
        for (int t = 0; t < 2; t++) {
            int f4i = tid + t * 256;
            int wr = f4i >> 5, wc = (f4i & 31) * 4;
            cp16(&wb[wr * WS_STRIDE + wc], Wp + (size_t)(kt * 16 + wr) * 128 + wc);
        }
    };

    load_sub(0, 0, 0); load_sub(1, 0, 1);
    CP_COMMIT();
    for (int p = 0; p < 3; p++) {
        if (p < 2) {
            int st = (p + 1) & 1;
            load_sub(2 * p + 2, st, 0);
            if (2 * p + 3 < 5) load_sub(2 * p + 3, st, 1);
            CP_COMMIT(); CP_WAIT1();
        } else CP_WAIT0();
        __syncthreads();
        int st = p & 1;
        mma_tile32(a_sub(st, 0), w_sub(st, 0), acc, lane, wm, wn);
        if (2 * p + 1 < 5)
            mma_tile32(a_sub(st, 1), w_sub(st, 1), acc, lane, wm, wn);
        __syncthreads();
    }

#pragma unroll
    for (int mt2 = 0; mt2 < 4; mt2++) {
        int r0 = wm * 64 + mt2 * 16 + (lane >> 2);
#pragma unroll
        for (int nt = 0; nt < 4; nt++) {
            int col = wn * 32 + nt * 8 + 2 * (lane & 3);
            *(float2*)&mt_[r0 * 132 + col] =
                make_float2(acc[mt2][nt][0], acc[mt2][nt][1]);
            *(float2*)&mt_[(r0 + 8) * 132 + col] =
                make_float2(acc[mt2][nt][2], acc[mt2][nt][3]);
        }
    }
    __syncthreads();

    int c = tid & 127, g2 = tid >> 7;
    int nfirst = sdst[0], nlast = sdst[127];
    for (int n = nfirst + g2; n <= nlast; n += 2) {
        int s = g_start[n], e = g_start[n + 1];
        if (s == e) continue;
        int lo = max(s, e0), hi = min(e, e0 + 128);
        if (lo >= hi) continue;
        float sumv = 0.f, sq = 0.f, mn = INFINITY, mx = -INFINITY;
        for (int r = lo - e0; r < hi - e0; r++) {
            float v = mt_[r * 132 + c];
            sumv += v; sq += v * v;
            mn = fminf(mn, v); mx = fmaxf(mx, v);
        }
        size_t idx = (size_t)n * H + c;
        if (s >= e0 && e <= e0 + 128) {
            float Dv = __half2float(g_D16[idx]);
            float degc = (float)(e - s);
            float inv = 1.f / degc;
            float mean = sumv * inv;
            float var = fmaxf(sq * inv - mean * mean, 0.f);
            g_mean16[idx] = __float2half_rn(Dv + mean);
            g_std16[idx] = __float2half_rn(sqrtf(var + EPS_STD));
            g_mn16[idx] = __float2half_rn(Dv + mn);
            g_mx16[idx] = __float2half_rn(Dv + mx);
        } else {
            atomicAdd(&g_bsum[idx], sumv);
            atomicAdd(&g_bsq[idx], sq);
            atomicMinF(&g_bmn[idx], mn);
            atomicMaxF(&g_bmx[idx], mx);
        }
    }
}

// ---------------- boundary helpers ----------------
__global__ void bnd_build() {
    int n = blockIdx.x * blockDim.x + threadIdx.x;
    if (n >= NN) return;
    int s = g_start[n], e = g_start[n + 1];
    bool bnd = (s == e) || ((s >> 7) != ((e - 1) >> 7));
    if (bnd) {
        int p = atomicAdd(&g_bcnt, 1);
        g_blist[p] = n;
    }
}
__global__ void init_bnd() {
    int B = g_bcnt;
    int total = B * 128;
    for (int i = blockIdx.x * blockDim.x + threadIdx.x; i < total;
         i += gridDim.x * blockDim.x) {
        int n = g_blist[i >> 7];
        int c = i & 127;
        size_t idx = (size_t)n * H + c;
        g_bsum[idx] = 0.f; g_bsq[idx] = 0.f;
        g_bmn[idx] = INFINITY; g_bmx[idx] = -INFINITY;
    }
}
__global__ void fin_init_bnd(int doInit) {
    int B = g_bcnt;
    int total = B * 128;
    for (int i = blockIdx.x * blockDim.x + threadIdx.x; i < total;
         i += gridDim.x * blockDim.x) {
        int n = g_blist[i >> 7];
        int c = i & 127;
        size_t idx = (size_t)n * H + c;
        int cnt = g_start[n + 1] - g_start[n];
        if (cnt == 0) {
            g_mean16[idx] = __float2half_rn(0.f);
            g_std16[idx] = __float2half_rn(sqrtf(EPS_STD));
            g_mn16[idx] = __float2half_rn(0.f);
            g_mx16[idx] = __float2half_rn(0.f);
        } else {
            float Dv = __half2float(g_D16[idx]);
            float inv = 1.f / (float)cnt;
            float mean = g_bsum[idx] * inv;
            float var = fmaxf(g_bsq[idx] * inv - mean * mean, 0.f);
            g_mean16[idx] = __float2half_rn(Dv + mean);
            g_std16[idx] = __float2half_rn(sqrtf(var + EPS_STD));
            g_mn16[idx] = __float2half_rn(Dv + g_bmn[idx]);
            g_mx16[idx] = __float2half_rn(Dv + g_bmx[idx]);
        }
        if (doInit) {
            g_bsum[idx] = 0.f; g_bsq[idx] = 0.f;
            g_bmn[idx] = INFINITY; g_bmx[idx] = -INFINITY;
        }
    }
}

// ---------------- post-NN gather-GEMM fp16 (2-stage, reordered scaling) ----------------
__global__ __launch_bounds__(256) void post_gemmt(const unsigned* __restrict__ Wp,
                                                  const float* __restrict__ bias)
{
    extern __shared__ float s_dyn[];
    unsigned* su = (unsigned*)s_dyn;
    int tid = threadIdx.x;
    int lane = tid & 31, warp = tid >> 5;
    int wm = warp >> 2, wn = warp & 3;
    int n0 = blockIdx.x * 128;
    int arow = tid >> 2;
    int slot = tid & 3;

    float sa[8], si2[8];
#pragma unroll
    for (int mt = 0; mt < 4; mt++)
#pragma unroll
        for (int hh = 0; hh < 2; hh++) {
            int n = n0 + wm * 64 + mt * 16 + (lane >> 2) + hh * 8;
            if (n >= NN) n = NN - 1;
            float a = g_amp[n], ia = g_iamp[n];
            sa[mt * 2 + hh] = a;
            si2[mt * 2 + hh] = ia * ia;
        }

    float acc[4][4][4];
#pragma unroll
    for (int a = 0; a < 4; a++)
#pragma unroll
        for (int b = 0; b < 4; b++)
#pragma unroll
            for (int c = 0; c < 4; c++) acc[a][b][c] = 0.f;

    auto a_sub = [&](int st, int j) { return su + st * 4096 + j * 2048; };
    auto w_sub = [&](int st, int j) { return su + 8192 + st * 4352 + j * 2176; };

    auto load_sub = [&](int t, int st, int j) {
        int kt = map_t32(t);
        int b = kt >> 2;
        const __half* srcb;
        if (b == 0) srcb = g_h16;
        else {
            int a = (b - 1) & 3;
            srcb = (a == 0) ? g_mean16 : (a == 1) ? g_mn16 : (a == 2) ? g_mx16 : g_std16;
        }
        int kk0 = (kt & 3) * 32;
        unsigned* ab = a_sub(st, j);
        unsigned* wb = w_sub(st, j);
#pragma unroll
        for (int tt = 0; tt < 2; tt++) {
            int r = arow + tt * 64;
            int n = n0 + r;
            if (n >= NN) n = NN - 1;
            cp16(&ab[r * 16 + ((slot ^ ((r >> 1) & 3)) << 2)],
                 srcb + (size_t)n * H + kk0 + slot * 8);
        }
#pragma unroll
        for (int tt = 0; tt < 2; tt++) {
            int f4i = tid + tt * 256;
            int wr = f4i >> 5, wc = (f4i & 31) * 4;
            cp16(&wb[wr * WS_STRIDE + wc], Wp + (size_t)(kt * 16 + wr) * 128 + wc);
        }
    };

    load_sub(0, 0, 0); load_sub(1, 0, 1);
    CP_COMMIT();
    for (int p = 0; p < 26; p++) {
        if (p < 25) {
            int st = (p + 1) & 1;
            load_sub(2 * p + 2, st, 0);
            load_sub(2 * p + 3, st, 1);
            CP_COMMIT(); CP_WAIT1();
        } else CP_WAIT0();
        __syncthreads();
        int st = p & 1;
        mma_tile32(a_sub(st, 0), w_sub(st, 0), acc, lane, wm, wn);
        mma_tile32(a_sub(st, 1), w_sub(st, 1), acc, lane, wm, wn);
        __syncthreads();
        if (p == 7) {
#pragma unroll
            for (int mt = 0; mt < 4; mt++)
#pragma unroll
                for (int nt = 0; nt < 4; nt++) {
                    acc[mt][nt][0] *= si2[mt * 2];     acc[mt][nt][1] *= si2[mt * 2];
                    acc[mt][nt][2] *= si2[mt * 2 + 1]; acc[mt][nt][3] *= si2[mt * 2 + 1];
                }
        } else if (p == 15) {
#pragma unroll
            for (int mt = 0; mt < 4; mt++)
#pragma unroll
                for (int nt = 0; nt < 4; nt++) {
                    acc[mt][nt][0] *= sa[mt * 2];     acc[mt][nt][1] *= sa[mt * 2];
                    acc[mt][nt][2] *= sa[mt * 2 + 1]; acc[mt][nt][3] *= sa[mt * 2 + 1];
                }
        }
    }

#pragma unroll
    for (int mt = 0; mt < 4; mt++) {
        int r0 = n0 + wm * 64 + mt * 16 + (lane >> 2);
#pragma unroll
        for (int nt = 0; nt < 4; nt++) {
            int col = wn * 32 + nt * 8 + 2 * (lane & 3);
            float b0 = bias[col], b1 = bias[col + 1];
            if (r0 < NN)
                *(__half2*)(g_tmp16 + (size_t)r0 * 128 + col) =
                    __floats2half2_rn(acc[mt][nt][0] + b0, acc[mt][nt][1] + b1);
            if (r0 + 8 < NN)
                *(__half2*)(g_tmp16 + (size_t)(r0 + 8) * 128 + col) =
                    __floats2half2_rn(acc[mt][nt][2] + b0, acc[mt][nt][3] + b1);
        }
    }
}

// ---------------- batched packing / conversion ----------------
__global__ void pack_dL(const float* __restrict__ preW) {
    int idx = blockIdx.x * blockDim.x + threadIdx.x;
    if (idx >= NL * KP_D * 128) return;
    int l = idx / (KP_D * 128);
    int r = idx - l * (KP_D * 128);
    int kp = r >> 7, n = r & 127;
    const float* base = preW + (size_t)l * 384 * H;
    float lo = base[(size_t)(2 * kp) * H + n];
    float hi = base[(size_t)(2 * kp + 1) * H + n];
    __half2 h = __floats2half2_rn(lo, hi);
    g_dWH[idx] = *(unsigned*)&h;
}
__global__ void pack_eL(const float* __restrict__ preW) {
    int idx = blockIdx.x * blockDim.x + threadIdx.x;
    if (idx >= NL * KP_EDGE * 128) return;
    int l = idx / (KP_EDGE * 128);
    int r = idx - l * (KP_EDGE * 128);
    int kp = r >> 7, n = r & 127;
    float v[2];
#pragma unroll
    for (int j = 0; j < 2; j++) {
        int k = 2 * kp + j;
        if (k < 128)      v[j] = preW[(size_t)l * 384 * H + (size_t)(128 + k) * H + n];
        else if (k < 144) v[j] = g_W2[(size_t)l * 16 * H + (size_t)(k - 128) * H + n];
        else              v[j] = 0.f;
    }
    __half2 h = __floats2half2_rn(v[0], v[1]);
    g_WsrcH[idx] = *(unsigned*)&h;
}
__global__ void pack_genL(const float* __restrict__ src, size_t strideL,
                          unsigned* __restrict__ out, int kpairs, int kmax) {
    int idx = blockIdx.x * blockDim.x + threadIdx.x;
    if (idx >= NL * kpairs * 128) return;
    int l = idx / (kpairs * 128);
    int r = idx - l * (kpairs * 128);
    int kp = r >> 7, n = r & 127;
    const float* base = src + (size_t)l * strideL;
    float lo = (2 * kp < kmax) ? base[(size_t)(2 * kp) * 128 + n] : 0.f;
    float hi = (2 * kp + 1 < kmax) ? base[(size_t)(2 * kp + 1) * 128 + n] : 0.f;
    __half2 h = __floats2half2_rn(lo, hi);
    out[idx] = *(unsigned*)&h;
}
__global__ void ea_pack(const float* __restrict__ ea) {
    int idx = blockIdx.x * blockDim.x + threadIdx.x;
    if (idx >= NE * 32) return;
    int e = idx >> 5, j = idx & 31;
    g_ea16[idx] = __float2half_rn(j < 16 ? ea[(size_t)e * 16 + j] : 0.f);
}
__global__ void biasm_kL(const float* __restrict__ be, const float* __restrict__ ebB,
                         const float* __restrict__ preW, const float* __restrict__ pbB) {
    int l = blockIdx.x;
    int j = threadIdx.x;
    const float* T1 = g_T1 + (size_t)l * H * H;
    const float* P2 = preW + (size_t)l * 384 * H + 256 * H;
    float s = pbB[l * H + j];
    for (int k = 0; k < H; k++) s += be[k] * T1[k * H + j];
    for (int k = 0; k < H; k++) s += ebB[l * H + k] * P2[k * H + j];
    g_biasmL[l * H + j] = s;
}

// ---------------- sort / scan ----------------
__global__ void deg_count(const int* __restrict__ dstI) {
    int e = blockIdx.x * blockDim.x + threadIdx.x;
    if (e < NE) atomicAdd(&g_cnt[dstI[e]], 1);
}
__global__ __launch_bounds__(256) void scan1() {
    int b = blockIdx.x, t = threadIdx.x;
    int n = b * CHUNK + t;
    int v = (t < CHUNK && n < NN) ? g_cnt[n] : 0;
    int lane = t & 31, wid = t >> 5;
    int x = v;
#pragma unroll
    for (int off = 1; off < 32; off <<= 1) {
        int u = __shfl_up_sync(0xffffffffu, x, off);
        if (lane >= off) x += u;
    }
    __shared__ int wsum[8];
    if (lane == 31) wsum[wid] = x;
    __syncthreads();
    if (t == 0) {
        int r = 0;
#pragma unroll
        for (int i = 0; i < 8; i++) { int tmp = wsum[i]; wsum[i] = r; r += tmp; }
        g_part[b] = r;
    }
    __syncthreads();
    int excl = x - v + wsum[wid];
    if (t < CHUNK && n < NN) g_start[n] = excl;
}
__global__ void scan2() {
    int t = threadIdx.x;
    int v = g_part[t];
    int lane = t & 31, wid = t >> 5;
    int x = v;
#pragma unroll
    for (int off = 1; off < 32; off <<= 1) {
        int u = __shfl_up_sync(0xffffffffu, x, off);
        if (lane >= off) x += u;
    }
    __shared__ int wsum[4];
    if (lane == 31) wsum[wid] = x;
    __syncthreads();
    if (t == 0) {
        int r = 0;
#pragma unroll
        for (int i = 0; i < 4; i++) { int tmp = wsum[i]; wsum[i] = r; r += tmp; }
    }
    __syncthreads();
    g_part[t] = x - v + wsum[wid];
}
__global__ void scan3() {
    int n = blockIdx.x * blockDim.x + threadIdx.x;
    if (n < NN) {
        int s = g_start[n] + g_part[n / CHUNK];
        g_start[n] = s;
        g_cursor[n] = s;
    }
    if (n == 0) g_start[NN] = NE;
}
__global__ void scatter_k(const int* __restrict__ srcI, const int* __restrict__ dstI) {
    int e = blockIdx.x * blockDim.x + threadIdx.x;
    if (e >= NE) return;
    int d = dstI[e];
    int p = atomicAdd(&g_cursor[d], 1);
    g_psrc[p] = srcI[e];
    g_pdst[p] = d;
    g_peid[p] = e;
}
__global__ void amp_k() {
    int n = blockIdx.x * blockDim.x + threadIdx.x;
    if (n >= NN) return;
    float degc = fmaxf((float)g_cnt[n], 1.f);
    float a = logf(degc + 1.f) / AVG_LOG;
    g_amp[n] = a;
    g_iamp[n] = 1.f / a;
}

// ---------------- pool / head ----------------
__global__ void pool_k(const int* __restrict__ batch) {
    int c = threadIdx.x;
    int start = blockIdx.x * 256;
    int end = min(start + 256, NN);
    if (start >= NN) return;
    float acc = 0.f;
    int cur = batch[start];
    for (int n = start; n < end; n++) {
        int g = batch[n];
        if (g != cur) { atomicAdd(&g_pool[cur * H + c], acc); acc = 0.f; cur = g; }
        acc += __half2float(g_h16[(size_t)n * H + c]);
    }
    atomicAdd(&g_pool[cur * H + c], acc);
}
__global__ void head1_k(const float* __restrict__ W1, const float* __restrict__ b1) {
    int idx = blockIdx.x * blockDim.x + threadIdx.x;
    if (idx >= NGR * 64) return;
    int g = idx >> 6, j = idx & 63;
    float s = b1[j];
    for (int k = 0; k < H; k++) s += g_pool[g * H + k] * W1[k * 64 + j];
    g_z[idx] = fmaxf(s, 0.f);
}
__global__ void head2_k(const float* __restrict__ W2, const float* __restrict__ b2,
                        float* __restrict__ out) {
    int idx = blockIdx.x * blockDim.x + threadIdx.x;
    if (idx >= NGR * NOUT) return;
    int g = idx / NOUT, j = idx % NOUT;
    float s = b2[j];
    for (int k = 0; k < 64; k++) s += g_z[g * 64 + k] * W2[k * NOUT + j];
    out[idx] = s;
}

// ---------------- launch ----------------
extern "C" void kernel_launch(void* const* d_in, const int* in_sizes, int n_in,
                              void* d_out, int out_size)
{
    int iEI = 1, iBatch = 2, iEA = 3;
    if (in_sizes[1] == NE * 16) { iEA = 1; iEI = 2; iBatch = 3; }

    const float* x         = (const float*)d_in[0];
    const int*   edge_index= (const int*)  d_in[iEI];
    const int*   batch     = (const int*)  d_in[iBatch];
    const float* edge_attr = (const float*)d_in[iEA];
    const float* node_emb_W= (const float*)d_in[4];
    const float* node_emb_b= (const float*)d_in[5];
    const float* edge_emb_W= (const float*)d_in[6];
    const float* edge_emb_b= (const float*)d_in[7];
    const float* edge_enc_W= (const float*)d_in[8];
    const float* edge_enc_b= (const float*)d_in[9];
    const float* pre_W     = (const float*)d_in[10];
    const float* pre_b     = (const float*)d_in[11];
    const float* post_W    = (const float*)d_in[12];
    const float* post_b    = (const float*)d_in[13];
    const float* lin_W     = (const float*)d_in[14];
    const float* lin_b     = (const float*)d_in[15];
    const float* bn_gamma  = (const float*)d_in[16];
    const float* bn_beta   = (const float*)d_in[17];
    const float* head1_W   = (const float*)d_in[18];
    const float* head1_b   = (const float*)d_in[19];
    const float* head2_W   = (const float*)d_in[20];
    const float* head2_b   = (const float*)d_in[21];

    const int* srcI = edge_index;
    const int* dstI = edge_index + NE;

    float *p_T1, *p_W2, *p_biasm, *p_bn, *p_pool;
    unsigned *p_wsrcH, *p_postWH, *p_linWH, *p_dWH;
    int *p_cnt, *p_bcnt;
    cudaGetSymbolAddress((void**)&p_T1,     g_T1);
    cudaGetSymbolAddress((void**)&p_W2,     g_W2);
    cudaGetSymbolAddress((void**)&p_wsrcH,  g_WsrcH);
    cudaGetSymbolAddress((void**)&p_postWH, g_postWH);
    cudaGetSymbolAddress((void**)&p_linWH,  g_linWH);
    cudaGetSymbolAddress((void**)&p_dWH,    g_dWH);
    cudaGetSymbolAddress((void**)&p_biasm,  g_biasmL);
    cudaGetSymbolAddress((void**)&p_bn,     g_bn);
    cudaGetSymbolAddress((void**)&p_pool,   g_pool);
    cudaGetSymbolAddress((void**)&p_cnt,    g_cnt);
    cudaGetSymbolAddress((void**)&p_bcnt,   g_bcnt);

    cudaFuncSetAttribute(edge_agg, cudaFuncAttributeMaxDynamicSharedMemorySize, BIG_SMEM);
    cudaFuncSetAttribute(post_gemmt, cudaFuncAttributeMaxDynamicSharedMemorySize, BIG_SMEM);

    // sort prep
    cudaMemsetAsync(p_cnt, 0, NN * sizeof(int));
    cudaMemsetAsync(p_bcnt, 0, sizeof(int));
    deg_count<<<(NE + 255) / 256, 256>>>(dstI);
    scan1<<<SCAN_B, 256>>>();
    scan2<<<1, 128>>>();
    emb_gemmt<<<(NN + 127) / 128, 256>>>(x, node_emb_W, node_emb_b, 64);
    scan3<<<(NN + 255) / 256, 256>>>();
    scatter_k<<<(NE + 255) / 256, 256>>>(srcI, dstI);
    amp_k<<<(NN + 255) / 256, 256>>>();
    bnd_build<<<(NN + 255) / 256, 256>>>();
    ea_pack<<<(NE * 32 + 255) / 256, 256>>>(edge_attr);

    // batched weight prep
    gemm128L<<<dim3(1, NL), 256>>>(edge_enc_W, (size_t)H * H,
                                   pre_W + 256 * H, (size_t)384 * H,
                                   p_T1, (size_t)H * H, 128, 128);
    gemm128L<<<dim3(1, NL), 256>>>(edge_emb_W, 0,
                                   p_T1, (size_t)H * H,
                                   p_W2, (size_t)16 * H, 16, 128);
    biasm_kL<<<NL, 128>>>(edge_emb_b, edge_enc_b, pre_W, pre_b);
    pack_dL<<<(NL * KP_D * 128 + 255) / 256, 256>>>(pre_W);
    pack_eL<<<(NL * KP_EDGE * 128 + 255) / 256, 256>>>(pre_W);
    pack_genL<<<(NL * KP_POST * 128 + 255) / 256, 256>>>(post_W, (size_t)13 * H * H,
                                                         p_postWH, KP_POST, 13 * H);
    pack_genL<<<(NL * KP_LIN * 128 + 255) / 256, 256>>>(lin_W, (size_t)H * H,
                                                        p_linWH, KP_LIN, H);

    d_gemm<<<(NN + 127) / 128, 256>>>(p_dWH, p_biasm);
    init_bnd<<<64, 256>>>();

    for (int l = 0; l < NL; l++) {
        edge_agg<<<NE / 128, 256, BIG_SMEM>>>(p_wsrcH + (size_t)l * KP_EDGE * H);
        fin_init_bnd<<<64, 256>>>(l < NL - 1 ? 1 : 0);

        post_gemmt<<<(NN + 127) / 128, 256, BIG_SMEM>>>(
            p_postWH + (size_t)l * KP_POST * H, post_b + l * H);

        cudaMemsetAsync(p_bn, 0, 2 * H * sizeof(float));
        lin_gemm_bn<<<(NN + 127) / 128, 256>>>(p_linWH + (size_t)l * KP_LIN * H,
                                               lin_b + l * H);
        if (l < NL - 1)
            bn_d_gemm<<<(NN + 127) / 128, 256>>>(bn_gamma + l * H, bn_beta + l * H,
                                                 p_dWH + (size_t)(l + 1) * KP_D * H,
                                                 p_biasm + (l + 1) * H, 1);
        else
            bn_d_gemm<<<(NN + 127) / 128, 256>>>(bn_gamma + l * H, bn_beta + l * H,
                                                 p_dWH, p_biasm, 0);
    }

    cudaMemsetAsync(p_pool, 0, NGR * H * sizeof(float));
    pool_k<<<(NN + 255) / 256, 128>>>(batch);
    head1_k<<<8, 256>>>(head1_W, head1_b);
    head2_k<<<2, 256>>>(head2_W, head2_b, (float*)d_out);
}

// round 17
// speedup vs baseline: 1.1630x; 1.0222x over previous
#include <cuda_runtime.h>
#include <cuda_fp16.h>
#include <math.h>

#define NN 30000
#define NE 480000
#define H 128
#define NL 4
#define NGR 32
#define NOUT 12
#define AVG_LOG 1.38214548f
#define EPS_BN 1e-5f
#define EPS_STD 1e-5f
#define KP_EDGE 80
#define KP_POST 832
#define KP_D 64
#define WS_STRIDE 136
#define SCAN_B 128
#define CHUNK 235
#define BIG_SMEM 67584

// ---------------- scratch ----------------
__device__ float g_h2[NN * H];
__device__ __half g_h16[NN * H];
__device__ __half g_D16[NN * H];
__device__ __half g_mean16[NN * H];
__device__ __half g_std16[NN * H];
__device__ __half g_mn16[NN * H];
__device__ __half g_mx16[NN * H];
__device__ __half g_ea16[NE * 32];
__device__ float g_bsum[NN * H];
__device__ float g_bsq[NN * H];
__device__ float g_bmn[NN * H];
__device__ float g_bmx[NN * H];
__device__ int   g_cnt[NN];
__device__ int   g_start[NN + 1];
__device__ int   g_cursor[NN];
__device__ int   g_part[SCAN_B];
__device__ int   g_psrc[NE];
__device__ int   g_pdst[NE];
__device__ int   g_peid[NE];
__device__ int   g_blist[NN];
__device__ int   g_bcnt;
__device__ float g_amp[NN];
__device__ float g_iamp[NN];
__device__ unsigned g_WsrcH[NL * KP_EDGE * H];
__device__ unsigned g_postWH[NL * KP_POST * H];
__device__ unsigned g_dWH[NL * KP_D * H];
__device__ float g_Wcomb[NL * 13 * H * H];   // postW @ linW (fp32)
__device__ float g_T1[NL * H * H];
__device__ float g_W2[NL * 16 * H];
__device__ float g_biasmL[NL * H];
__device__ float g_cbiasL[NL * H];           // post_b @ linW + lin_b
__device__ float g_bn[2 * H];
__device__ float g_pool[NGR * H];
__device__ float g_z[NGR * 64];

// ---------------- helpers ----------------
__device__ __forceinline__ void atomicMaxF(float* a, float v) {
    if (v >= 0.f) atomicMax((int*)a, __float_as_int(v));
    else          atomicMin((unsigned int*)a, __float_as_uint(v));
}
__device__ __forceinline__ void atomicMinF(float* a, float v) {
    if (v >= 0.f) atomicMin((int*)a, __float_as_int(v));
    else          atomicMax((unsigned int*)a, __float_as_uint(v));
}
__device__ __forceinline__ void cp16(void* smem, const void* g) {
    unsigned sa = (unsigned)__cvta_generic_to_shared(smem);
    asm volatile("cp.async.cg.shared.global [%0], [%1], 16;\n" :: "r"(sa), "l"(g));
}
#define CP_COMMIT() asm volatile("cp.async.commit_group;\n" ::: "memory")
#define CP_WAIT1()  asm volatile("cp.async.wait_group 1;\n" ::: "memory")
#define CP_WAIT0()  asm volatile("cp.async.wait_group 0;\n" ::: "memory")

__device__ __forceinline__ int map_t32(int t) {
    return (t < 16) ? 36 + t : (t < 32) ? 20 + (t - 16) : (t - 32);
}

// fp16 mma over one 32-k tile; A fragments via ldmatrix.x4 (layout verified R16).
__device__ __forceinline__ void mma_tile32(const unsigned* As, const unsigned* Ws,
                                           float (&acc)[4][4][4], int lane,
                                           int wm, int wn)
{
    unsigned as_base = (unsigned)__cvta_generic_to_shared(As);
    int j = lane >> 3;
    int rlo = ((j & 1) << 3) + (lane & 7);
#pragma unroll
    for (int ks = 0; ks < 2; ks++) {
        unsigned b0[4], b1[4];
        int bk = ks * 8 + (lane & 3);
        int bn = wn * 32 + (lane >> 2);
#pragma unroll
        for (int nt = 0; nt < 4; nt++) {
            b0[nt] = Ws[bk * WS_STRIDE + bn + nt * 8];
            b1[nt] = Ws[(bk + 4) * WS_STRIDE + bn + nt * 8];
        }
#pragma unroll
        for (int mt = 0; mt < 4; mt++) {
            int r = wm * 64 + mt * 16 + rlo;
            int sl = (ks * 2 + (j >> 1)) ^ ((r >> 1) & 3);
            unsigned addr = as_base + (unsigned)((r * 16 + sl * 4) << 2);
            unsigned a0, a1, a2, a3;
            asm volatile(
                "ldmatrix.sync.aligned.m8n8.x4.shared.b16 {%0,%1,%2,%3}, [%4];"
                : "=r"(a0), "=r"(a1), "=r"(a2), "=r"(a3) : "r"(addr));
#pragma unroll
            for (int nt = 0; nt < 4; nt++) {
                asm volatile(
                    "mma.sync.aligned.m16n8k16.row.col.f32.f16.f16.f32 "
                    "{%0,%1,%2,%3}, {%4,%5,%6,%7}, {%8,%9}, {%0,%1,%2,%3};"
                    : "+f"(acc[mt][nt][0]), "+f"(acc[mt][nt][1]),
                      "+f"(acc[mt][nt][2]), "+f"(acc[mt][nt][3])
                    : "r"(a0), "r"(a1), "r"(a2), "r"(a3),
                      "r"(b0[nt]), "r"(b1[nt]));
            }
        }
    }
}

// tf32 path for emb GEMM
__device__ __forceinline__ unsigned ld_asf(const float* As, int r, int slot, int c) {
    return __float_as_uint(As[r * 16 + ((slot ^ ((r >> 1) & 3)) << 2) + c]);
}
__device__ __forceinline__ void mma_tile16f(const float* As, const float* Ws,
                                            float (&acc)[4][4][4], int lane,
                                            int wm, int wn)
{
#pragma unroll
    for (int ks = 0; ks < 2; ks++) {
        unsigned b0[4], b1[4];
        int bk = ks * 8 + (lane & 3);
        int bn = wn * 32 + (lane >> 2);
#pragma unroll
        for (int nt = 0; nt < 4; nt++) {
            b0[nt] = __float_as_uint(Ws[bk * WS_STRIDE + bn + nt * 8]);
            b1[nt] = __float_as_uint(Ws[(bk + 4) * WS_STRIDE + bn + nt * 8]);
        }
#pragma unroll
        for (int mt = 0; mt < 4; mt++) {
            int r0 = wm * 64 + mt * 16 + (lane >> 2);
            int r1 = r0 + 8;
            int c = lane & 3;
            unsigned a0 = ld_asf(As, r0, ks * 2,     c);
            unsigned a1 = ld_asf(As, r1, ks * 2,     c);
            unsigned a2 = ld_asf(As, r0, ks * 2 + 1, c);
            unsigned a3 = ld_asf(As, r1, ks * 2 + 1, c);
#pragma unroll
            for (int nt = 0; nt < 4; nt++) {
                asm volatile(
                    "mma.sync.aligned.m16n8k8.row.col.f32.tf32.tf32.f32 "
                    "{%0,%1,%2,%3}, {%4,%5,%6,%7}, {%8,%9}, {%0,%1,%2,%3};"
                    : "+f"(acc[mt][nt][0]), "+f"(acc[mt][nt][1]),
                      "+f"(acc[mt][nt][2]), "+f"(acc[mt][nt][3])
                    : "r"(a0), "r"(a1), "r"(a2), "r"(a3),
                      "r"(b0[nt]), "r"(b1[nt]));
            }
        }
    }
}

// ---------------- batched fp32 GEMM for weight prep ----------------
__global__ __launch_bounds__(256) void gemm128L(
    const float* __restrict__ Ab, size_t aStride,
    const float* __restrict__ Wb, size_t wStride,
    float* __restrict__ Cb, size_t cStride, int M, int K)
{
    const float* A = Ab + blockIdx.y * aStride;
    const float* W = Wb + blockIdx.y * wStride;
    float* C = Cb + blockIdx.y * cStride;
    __shared__ float As[16 * 132];
    __shared__ float Ws[16 * 128];
    int tid = threadIdx.x;
    int m0 = blockIdx.x * 128;
    int trow = tid >> 4, tcol = tid & 15;
    int r8 = trow * 8, c8 = tcol * 8;
    int arow = tid >> 2;
    int ac4 = (tid & 3) * 4;

    float acc[8][8];
#pragma unroll
    for (int i = 0; i < 8; i++)
#pragma unroll
        for (int j = 0; j < 8; j++) acc[i][j] = 0.f;

    for (int k0 = 0; k0 < K; k0 += 16) {
#pragma unroll
        for (int t = 0; t < 2; t++) {
            int r = arow + t * 64;
            int gr = m0 + r;
            float4 v = make_float4(0.f, 0.f, 0.f, 0.f);
            if (gr < M) v = *(const float4*)(A + (size_t)gr * K + k0 + ac4);
            As[(ac4 + 0) * 132 + r] = v.x;
            As[(ac4 + 1) * 132 + r] = v.y;
            As[(ac4 + 2) * 132 + r] = v.z;
            As[(ac4 + 3) * 132 + r] = v.w;
        }
#pragma unroll
        for (int t = 0; t < 2; t++) {
            int f4i = tid + t * 256;
            int wr = f4i >> 5, wc = (f4i & 31) * 4;
            *(float4*)&Ws[wr * 128 + wc] = *(const float4*)(W + (size_t)(k0 + wr) * 128 + wc);
        }
        __syncthreads();
#pragma unroll
        for (int kk = 0; kk < 16; kk++) {
            float4 a0 = *(const float4*)&As[kk * 132 + r8];
            float4 a1 = *(const float4*)&As[kk * 132 + r8 + 4];
            float4 w0 = *(const float4*)&Ws[kk * 128 + c8];
            float4 w1 = *(const float4*)&Ws[kk * 128 + c8 + 4];
            float a[8] = {a0.x, a0.y, a0.z, a0.w, a1.x, a1.y, a1.z, a1.w};
            float w[8] = {w0.x, w0.y, w0.z, w0.w, w1.x, w1.y, w1.z, w1.w};
#pragma unroll
            for (int i = 0; i < 8; i++)
#pragma unroll
                for (int j = 0; j < 8; j++) acc[i][j] += a[i] * w[j];
        }
        __syncthreads();
    }

#pragma unroll
    for (int i = 0; i < 8; i++) {
        int gr = m0 + r8 + i;
        if (gr < M) {
            float4 o0, o1;
            o0.x = acc[i][0]; o0.y = acc[i][1]; o0.z = acc[i][2]; o0.w = acc[i][3];
            o1.x = acc[i][4]; o1.y = acc[i][5]; o1.z = acc[i][6]; o1.w = acc[i][7];
            *(float4*)(C + (size_t)gr * 128 + c8) = o0;
            *(float4*)(C + (size_t)gr * 128 + c8 + 4) = o1;
        }
    }
}

// ---------------- emb GEMM (tf32): writes fp16 h ----------------
__global__ __launch_bounds__(256) void emb_gemmt(
    const float* __restrict__ A, const float* __restrict__ W,
    const float* __restrict__ bias, int K)
{
    __shared__ float As[128 * 16];
    __shared__ float Ws[16 * WS_STRIDE];
    int tid = threadIdx.x;
    int lane = tid & 31, warp = tid >> 5;
    int wm = warp >> 2, wn = warp & 3;
    int m0 = blockIdx.x * 128;
    int arow = tid >> 2;
    int slot = tid & 3;
    float4* As4 = (float4*)As;

    float acc[4][4][4];
#pragma unroll
    for (int a = 0; a < 4; a++)
#pragma unroll
        for (int b = 0; b < 4; b++)
#pragma unroll
            for (int c = 0; c < 4; c++) acc[a][b][c] = 0.f;

    for (int k0 = 0; k0 < K; k0 += 16) {
#pragma unroll
        for (int t = 0; t < 2; t++) {
            int r = arow + t * 64;
            int gr = m0 + r;
            float4 v = make_float4(0.f, 0.f, 0.f, 0.f);
            if (gr < NN) v = *(const float4*)(A + (size_t)gr * K + k0 + slot * 4);
            As4[r * 4 + (slot ^ ((r >> 1) & 3))] = v;
        }
#pragma unroll
        for (int t = 0; t < 2; t++) {
            int f4i = tid + t * 256;
            int wr = f4i >> 5, wc = (f4i & 31) * 4;
            *(float4*)&Ws[wr * WS_STRIDE + wc] =
                *(const float4*)(W + (size_t)(k0 + wr) * 128 + wc);
        }
        __syncthreads();
        mma_tile16f(As, Ws, acc, lane, wm, wn);
        __syncthreads();
    }

#pragma unroll
    for (int mt = 0; mt < 4; mt++) {
        int r0 = m0 + wm * 64 + mt * 16 + (lane >> 2);
#pragma unroll
        for (int nt = 0; nt < 4; nt++) {
            int col = wn * 32 + nt * 8 + 2 * (lane & 3);
            float b0 = bias[col], b1 = bias[col + 1];
            if (r0 < NN)
                *(__half2*)(g_h16 + (size_t)r0 * 128 + col) =
                    __floats2half2_rn(acc[mt][nt][0] + b0, acc[mt][nt][1] + b1);
            if (r0 + 8 < NN)
                *(__half2*)(g_h16 + (size_t)(r0 + 8) * 128 + col) =
                    __floats2half2_rn(acc[mt][nt][2] + b0, acc[mt][nt][3] + b1);
        }
    }
}

// ---------------- D GEMM (layer 0) ----------------
__global__ __launch_bounds__(256) void d_gemm(
    const unsigned* __restrict__ Wp, const float* __restrict__ bias)
{
    __shared__ unsigned As2[128 * 16];
    __shared__ unsigned Ws2[16 * WS_STRIDE];
    int tid = threadIdx.x;
    int lane = tid & 31, warp = tid >> 5;
    int wm = warp >> 2, wn = warp & 3;
    int m0 = blockIdx.x * 128;
    int arow = tid >> 2;
    int slot = tid & 3;
    uint4* As4 = (uint4*)As2;

    float acc[4][4][4];
#pragma unroll
    for (int a = 0; a < 4; a++)
#pragma unroll
        for (int b = 0; b < 4; b++)
#pragma unroll
            for (int c = 0; c < 4; c++) acc[a][b][c] = 0.f;

    for (int kt = 0; kt < 4; kt++) {
#pragma unroll
        for (int t = 0; t < 2; t++) {
            int r = arow + t * 64;
            int gr = m0 + r;
            uint4 v = make_uint4(0, 0, 0, 0);
            if (gr < NN)
                v = *(const uint4*)(g_h16 + (size_t)gr * 128 + kt * 32 + slot * 8);
            As4[r * 4 + (slot ^ ((r >> 1) & 3))] = v;
        }
#pragma unroll
        for (int t = 0; t < 2; t++) {
            int f4i = tid + t * 256;
            int wr = f4i >> 5, wc = (f4i & 31) * 4;
            *(uint4*)&Ws2[wr * WS_STRIDE + wc] =
                *(const uint4*)(Wp + (size_t)(kt * 16 + wr) * 128 + wc);
        }
        __syncthreads();
        mma_tile32(As2, Ws2, acc, lane, wm, wn);
        __syncthreads();
    }

#pragma unroll
    for (int mt = 0; mt < 4; mt++) {
        int r0 = m0 + wm * 64 + mt * 16 + (lane >> 2);
#pragma unroll
        for (int nt = 0; nt < 4; nt++) {
            int col = wn * 32 + nt * 8 + 2 * (lane & 3);
            float b0 = bias[col], b1 = bias[col + 1];
            if (r0 < NN)
                *(__half2*)(g_D16 + (size_t)r0 * 128 + col) =
                    __floats2half2_rn(acc[mt][nt][0] + b0, acc[mt][nt][1] + b1);
            if (r0 + 8 < NN)
                *(__half2*)(g_D16 + (size_t)(r0 + 8) * 128 + col) =
                    __floats2half2_rn(acc[mt][nt][2] + b0, acc[mt][nt][3] + b1);
        }
    }
}

// ---------------- fused BN+ReLU + next-layer D GEMM ----------------
__global__ __launch_bounds__(256) void bn_d_gemm(
    const float* __restrict__ gamma, const float* __restrict__ beta,
    const unsigned* __restrict__ Wp, const float* __restrict__ dbias, int doD)
{
    __shared__ unsigned As2[128 * 16];
    __shared__ unsigned Ws2[16 * WS_STRIDE];
    __shared__ float ssc[128], sof[128];
    int tid = threadIdx.x;
    int lane = tid & 31, warp = tid >> 5;
    int wm = warp >> 2, wn = warp & 3;
    int m0 = blockIdx.x * 128;
    int arow = tid >> 2;
    int slot = tid & 3;
    uint4* As4 = (uint4*)As2;

    if (tid < 128) {
        const float invN = 1.f / (float)NN;
        float mu = g_bn[tid] * invN;
        float var = g_bn[128 + tid] * invN - mu * mu;
        float sc = rsqrtf(var + EPS_BN) * gamma[tid];
        ssc[tid] = sc;
        sof[tid] = beta[tid] - mu * sc;
    }
    __syncthreads();

    float acc[4][4][4];
#pragma unroll
    for (int a = 0; a < 4; a++)
#pragma unroll
        for (int b = 0; b < 4; b++)
#pragma unroll
            for (int c = 0; c < 4; c++) acc[a][b][c] = 0.f;

    for (int kt = 0; kt < 4; kt++) {
#pragma unroll
        for (int t = 0; t < 2; t++) {
            int r = arow + t * 64;
            int gr = m0 + r;
            int c0 = kt * 32 + slot * 8;
            uint4 hv = make_uint4(0, 0, 0, 0);
            if (gr < NN) {
                float4 x0 = *(const float4*)(g_h2 + (size_t)gr * 128 + c0);
                float4 x1 = *(const float4*)(g_h2 + (size_t)gr * 128 + c0 + 4);
                float y0 = fmaxf(x0.x * ssc[c0 + 0] + sof[c0 + 0], 0.f);
                float y1 = fmaxf(x0.y * ssc[c0 + 1] + sof[c0 + 1], 0.f);
                float y2 = fmaxf(x0.z * ssc[c0 + 2] + sof[c0 + 2], 0.f);
                float y3 = fmaxf(x0.w * ssc[c0 + 3] + sof[c0 + 3], 0.f);
                float y4 = fmaxf(x1.x * ssc[c0 + 4] + sof[c0 + 4], 0.f);
                float y5 = fmaxf(x1.y * ssc[c0 + 5] + sof[c0 + 5], 0.f);
                float y6 = fmaxf(x1.z * ssc[c0 + 6] + sof[c0 + 6], 0.f);
                float y7 = fmaxf(x1.w * ssc[c0 + 7] + sof[c0 + 7], 0.f);
                __half2 p0 = __floats2half2_rn(y0, y1);
                __half2 p1 = __floats2half2_rn(y2, y3);
                __half2 p2 = __floats2half2_rn(y4, y5);
                __half2 p3 = __floats2half2_rn(y6, y7);
                hv = make_uint4(*(unsigned*)&p0, *(unsigned*)&p1,
                                *(unsigned*)&p2, *(unsigned*)&p3);
                *(uint4*)(g_h16 + (size_t)gr * 128 + c0) = hv;
            }
            As4[r * 4 + (slot ^ ((r >> 1) & 3))] = hv;
        }
        if (doD) {
#pragma unroll
            for (int t = 0; t < 2; t++) {
                int f4i = tid + t * 256;
                int wr = f4i >> 5, wc = (f4i & 31) * 4;
                *(uint4*)&Ws2[wr * WS_STRIDE + wc] =
                    *(const uint4*)(Wp + (size_t)(kt * 16 + wr) * 128 + wc);
            }
        }
        __syncthreads();
        if (doD) mma_tile32(As2, Ws2, acc, lane, wm, wn);
        __syncthreads();
    }

    if (doD) {
#pragma unroll
        for (int mt = 0; mt < 4; mt++) {
            int r0 = m0 + wm * 64 + mt * 16 + (lane >> 2);
#pragma unroll
            for (int nt = 0; nt < 4; nt++) {
                int col = wn * 32 + nt * 8 + 2 * (lane & 3);
                float b0 = dbias[col], b1 = dbias[col + 1];
                if (r0 < NN)
                    *(__half2*)(g_D16 + (size_t)r0 * 128 + col) =
                        __floats2half2_rn(acc[mt][nt][0] + b0, acc[mt][nt][1] + b1);
                if (r0 + 8 < NN)
                    *(__half2*)(g_D16 + (size_t)(r0 + 8) * 128 + col) =
                        __floats2half2_rn(acc[mt][nt][2] + b0, acc[mt][nt][3] + b1);
            }
        }
    }
}

// ---------------- fused edge GEMM (fp16, src+edge, K=160) + aggregation ----------------
__global__ __launch_bounds__(256) void edge_agg(const unsigned* __restrict__ Wp)
{
    extern __shared__ float s_dyn[];
    unsigned* su = (unsigned*)s_dyn;
    float* mt_ = s_dyn;
    __shared__ int sdst[128], ssrc[128], seid[128];

    int tid = threadIdx.x;
    int lane = tid & 31, warp = tid >> 5;
    int wm = warp >> 2, wn = warp & 3;
    int e0 = blockIdx.x * 128;
    int arow = tid >> 2;
    int slot = tid & 3;

    if (tid < 128) {
        int p = e0 + tid;
        sdst[tid] = g_pdst[p];
        ssrc[tid] = g_psrc[p];
        seid[tid] = g_peid[p];
    }
    __syncthreads();

    float acc[4][4][4];
#pragma unroll
    for (int a = 0; a < 4; a++)
#pragma unroll
        for (int b = 0; b < 4; b++)
#pragma unroll
            for (int c = 0; c < 4; c++) acc[a][b][c] = 0.f;

    auto a_sub = [&](int st, int j) { return su + st * 4096 + j * 2048; };
    auto w_sub = [&](int st, int j) { return su + 8192 + st * 4352 + j * 2176; };

    auto load_sub = [&](int kt, int st, int j) {
        unsigned* ab = a_sub(st, j);
        unsigned* wb = w_sub(st, j);
#pragma unroll
        for (int t = 0; t < 2; t++) {
            int r = arow + t * 64;
            const __half* src;
            if (kt < 4) src = g_h16 + (size_t)ssrc[r] * H + kt * 32 + slot * 8;
            else        src = g_ea16 + (size_t)seid[r] * 32 + slot * 8;
            cp16(&ab[r * 16 + ((slot ^ ((r >> 1) & 3)) << 2)], src);
        }
#pragma unroll
        for (int t = 0; t < 2; t++) {
            int f4i = tid + t * 256;
            int wr = f4i >> 5, wc = (f4i & 31) * 4;
            cp16(&wb[wr * WS_STRIDE + wc], Wp + (size_t)(kt * 16 + wr) * 128 + wc);
        }
    };

    load_sub(0, 0, 0); load_sub(1, 0, 1);
    CP_COMMIT();
    for (int p = 0; p < 3; p++) {
        if (p < 2) {
            int st = (p + 1) & 1;
            load_sub(2 * p + 2, st, 0);
            if (2 * p + 3 < 5) load_sub(2 * p + 3, st, 1);
            CP_COMMIT(); CP_WAIT1();
        } else CP_WAIT0();
        __syncthreads();
        int st = p & 1;
        mma_tile32(a_sub(st, 0), w_sub(st, 0), acc, lane, wm, wn);
        if (2 * p + 1 < 5)
            mma_tile32(a_sub(st, 1), w_sub(st, 1), acc, lane, wm, wn);
        __syncthreads();
    }

#pragma unroll
    for (int mt2 = 0; mt2 < 4; mt2++) {
        int r0 = wm * 64 + mt2 * 16 + (lane >> 2);
#pragma unroll
        for (int nt = 0; nt < 4; nt++) {
            int col = wn * 32 + nt * 8 + 2 * (lane & 3);
            *(float2*)&mt_[r0 * 132 + col] =
                make_float2(acc[mt2][nt][0], acc[mt2][nt][1]);
            *(float2*)&mt_[(r0 + 8) * 132 + col] =
                make_float2(acc[mt2][nt][2], acc[mt2][nt][3]);
        }
    }
    __syncthreads();

    int c = tid & 127, g2 = tid >> 7;
    int nfirst = sdst[0], nlast = sdst[127];
    for (int n = nfirst + g2; n <= nlast; n += 2) {
        int s = g_start[n], e = g_start[n + 1];
        if (s == e) continue;
        int lo = max(s, e0), hi = min(e, e0 + 128);
        if (lo >= hi) continue;
        float sumv = 0.f, sq = 0.f, mn = INFINITY, mx = -INFINITY;
        for (int r = lo - e0; r < hi - e0; r++) {
            float v = mt_[r * 132 + c];
            sumv += v; sq += v * v;
            mn = fminf(mn, v); mx = fmaxf(mx, v);
        }
        size_t idx = (size_t)n * H + c;
        if (s >= e0 && e <= e0 + 128) {
            float Dv = __half2float(g_D16[idx]);
            float degc = (float)(e - s);
            float inv = 1.f / degc;
            float mean = sumv * inv;
            float var = fmaxf(sq * inv - mean * mean, 0.f);
            g_mean16[idx] = __float2half_rn(Dv + mean);
            g_std16[idx] = __float2half_rn(sqrtf(var + EPS_STD));
            g_mn16[idx] = __float2half_rn(Dv + mn);
            g_mx16[idx] = __float2half_rn(Dv + mx);
        } else {
            atomicAdd(&g_bsum[idx], sumv);
            atomicAdd(&g_bsq[idx], sq);
            atomicMinF(&g_bmn[idx], mn);
            atomicMaxF(&g_bmx[idx], mx);
        }
    }
}

// ---------------- boundary helpers ----------------
__global__ void bnd_build() {
    int n = blockIdx.x * blockDim.x + threadIdx.x;
    if (n >= NN) return;
    int s = g_start[n], e = g_start[n + 1];
    bool bnd = (s == e) || ((s >> 7) != ((e - 1) >> 7));
    if (bnd) {
        int p = atomicAdd(&g_bcnt, 1);
        g_blist[p] = n;
    }
}
__global__ void init_bnd() {
    int B = g_bcnt;
    int total = B * 128;
    for (int i = blockIdx.x * blockDim.x + threadIdx.x; i < total;
         i += gridDim.x * blockDim.x) {
        int n = g_blist[i >> 7];
        int c = i & 127;
        size_t idx = (size_t)n * H + c;
        g_bsum[idx] = 0.f; g_bsq[idx] = 0.f;
        g_bmn[idx] = INFINITY; g_bmx[idx] = -INFINITY;
    }
}
__global__ void fin_init_bnd(int doInit) {
    int B = g_bcnt;
    int total = B * 128;
    for (int i = blockIdx.x * blockDim.x + threadIdx.x; i < total;
         i += gridDim.x * blockDim.x) {
        int n = g_blist[i >> 7];
        int c = i & 127;
        size_t idx = (size_t)n * H + c;
        int cnt = g_start[n + 1] - g_start[n];
        if (cnt == 0) {
            g_mean16[idx] = __float2half_rn(0.f);
            g_std16[idx] = __float2half_rn(sqrtf(EPS_STD));
            g_mn16[idx] = __float2half_rn(0.f);
            g_mx16[idx] = __float2half_rn(0.f);
        } else {
            float Dv = __half2float(g_D16[idx]);
            float inv = 1.f / (float)cnt;
            float mean = g_bsum[idx] * inv;
            float var = fmaxf(g_bsq[idx] * inv - mean * mean, 0.f);
            g_mean16[idx] = __float2half_rn(Dv + mean);
            g_std16[idx] = __float2half_rn(sqrtf(var + EPS_STD));
            g_mn16[idx] = __float2half_rn(Dv + g_bmn[idx]);
            g_mx16[idx] = __float2half_rn(Dv + g_bmx[idx]);
        }
        if (doInit) {
            g_bsum[idx] = 0.f; g_bsq[idx] = 0.f;
            g_bmn[idx] = INFINITY; g_bmx[idx] = -INFINITY;
        }
    }
}

// ---------------- post-NN gather-GEMM fp16 (composed with lin; BN stats fused) ----------------
__global__ __launch_bounds__(256) void post_gemmt(const unsigned* __restrict__ Wp,
                                                  const float* __restrict__ cbias)
{
    extern __shared__ float s_dyn[];
    unsigned* su = (unsigned*)s_dyn;
    __shared__ float sbn[256];
    int tid = threadIdx.x;
    int lane = tid & 31, warp = tid >> 5;
    int wm = warp >> 2, wn = warp & 3;
    int n0 = blockIdx.x * 128;
    int arow = tid >> 2;
    int slot = tid & 3;
    sbn[tid] = 0.f;

    float sa[8], si2[8];
#pragma unroll
    for (int mt = 0; mt < 4; mt++)
#pragma unroll
        for (int hh = 0; hh < 2; hh++) {
            int n = n0 + wm * 64 + mt * 16 + (lane >> 2) + hh * 8;
            if (n >= NN) n = NN - 1;
            float a = g_amp[n], ia = g_iamp[n];
            sa[mt * 2 + hh] = a;
            si2[mt * 2 + hh] = ia * ia;
        }

    float acc[4][4][4];
#pragma unroll
    for (int a = 0; a < 4; a++)
#pragma unroll
        for (int b = 0; b < 4; b++)
#pragma unroll
            for (int c = 0; c < 4; c++) acc[a][b][c] = 0.f;

    auto a_sub = [&](int st, int j) { return su + st * 4096 + j * 2048; };
    auto w_sub = [&](int st, int j) { return su + 8192 + st * 4352 + j * 2176; };

    auto load_sub = [&](int t, int st, int j) {
        int kt = map_t32(t);
        int b = kt >> 2;
        const __half* srcb;
        if (b == 0) srcb = g_h16;
        else {
            int a = (b - 1) & 3;
            srcb = (a == 0) ? g_mean16 : (a == 1) ? g_mn16 : (a == 2) ? g_mx16 : g_std16;
        }
        int kk0 = (kt & 3) * 32;
        unsigned* ab = a_sub(st, j);
        unsigned* wb = w_sub(st, j);
#pragma unroll
        for (int tt = 0; tt < 2; tt++) {
            int r = arow + tt * 64;
            int n = n0 + r;
            if (n >= NN) n = NN - 1;
            cp16(&ab[r * 16 + ((slot ^ ((r >> 1) & 3)) << 2)],
                 srcb + (size_t)n * H + kk0 + slot * 8);
        }
#pragma unroll
        for (int tt = 0; tt < 2; tt++) {
            int f4i = tid + tt * 256;
            int wr = f4i >> 5, wc = (f4i & 31) * 4;
            cp16(&wb[wr * WS_STRIDE + wc], Wp + (size_t)(kt * 16 + wr) * 128 + wc);
        }
    };

    load_sub(0, 0, 0); load_sub(1, 0, 1);
    CP_COMMIT();
    for (int p = 0; p < 26; p++) {
        if (p < 25) {
            int st = (p + 1) & 1;
            load_sub(2 * p + 2, st, 0);
            load_sub(2 * p + 3, st, 1);
            CP_COMMIT(); CP_WAIT1();
        } else CP_WAIT0();
        __syncthreads();
        int st = p & 1;
        mma_tile32(a_sub(st, 0), w_sub(st, 0), acc, lane, wm, wn);
        mma_tile32(a_sub(st, 1), w_sub(st, 1), acc, lane, wm, wn);
        __syncthreads();
        if (p == 7) {            // U3 done -> * iamp^2
#pragma unroll
            for (int mt = 0; mt < 4; mt++)
#pragma unroll
                for (int nt = 0; nt < 4; nt++) {
                    acc[mt][nt][0] *= si2[mt * 2];     acc[mt][nt][1] *= si2[mt * 2];
                    acc[mt][nt][2] *= si2[mt * 2 + 1]; acc[mt][nt][3] *= si2[mt * 2 + 1];
                }
        } else if (p == 15) {    // U2 done -> * amp
#pragma unroll
            for (int mt = 0; mt < 4; mt++)
#pragma unroll
                for (int nt = 0; nt < 4; nt++) {
                    acc[mt][nt][0] *= sa[mt * 2];     acc[mt][nt][1] *= sa[mt * 2];
                    acc[mt][nt][2] *= sa[mt * 2 + 1]; acc[mt][nt][3] *= sa[mt * 2 + 1];
                }
        }
    }

    // epilogue: composed bias, write h2, fused BN partial stats
    float csum[4][2] = {}, csq[4][2] = {};
#pragma unroll
    for (int mt = 0; mt < 4; mt++) {
        int r0 = n0 + wm * 64 + mt * 16 + (lane >> 2);
#pragma unroll
        for (int nt = 0; nt < 4; nt++) {
            int col = wn * 32 + nt * 8 + 2 * (lane & 3);
            float b0 = cbias[col], b1 = cbias[col + 1];
            float v0 = acc[mt][nt][0] + b0, v1 = acc[mt][nt][1] + b1;
            float v2 = acc[mt][nt][2] + b0, v3 = acc[mt][nt][3] + b1;
            if (r0 < NN) {
                *(float2*)(g_h2 + (size_t)r0 * 128 + col) = make_float2(v0, v1);
                csum[nt][0] += v0; csq[nt][0] += v0 * v0;
                csum[nt][1] += v1; csq[nt][1] += v1 * v1;
            }
            if (r0 + 8 < NN) {
                *(float2*)(g_h2 + (size_t)(r0 + 8) * 128 + col) = make_float2(v2, v3);
                csum[nt][0] += v2; csq[nt][0] += v2 * v2;
                csum[nt][1] += v3; csq[nt][1] += v3 * v3;
            }
        }
    }
#pragma unroll
    for (int nt = 0; nt < 4; nt++)
#pragma unroll
        for (int j = 0; j < 2; j++) {
            float s = csum[nt][j], q = csq[nt][j];
            s += __shfl_down_sync(0xffffffffu, s, 16);
            s += __shfl_down_sync(0xffffffffu, s, 8);
            s += __shfl_down_sync(0xffffffffu, s, 4);
            q += __shfl_down_sync(0xffffffffu, q, 16);
            q += __shfl_down_sync(0xffffffffu, q, 8);
            q += __shfl_down_sync(0xffffffffu, q, 4);
            if (lane < 4) {
                int col = wn * 32 + nt * 8 + 2 * lane + j;
                atomicAdd(&sbn[col], s);
                atomicAdd(&sbn[128 + col], q);
            }
        }
    __syncthreads();
    atomicAdd(&g_bn[tid], sbn[tid]);
}

// ---------------- batched packing / conversion ----------------
__global__ void pack_dL(const float* __restrict__ preW) {
    int idx = blockIdx.x * blockDim.x + threadIdx.x;
    if (idx >= NL * KP_D * 128) return;
    int l = idx / (KP_D * 128);
    int r = idx - l * (KP_D * 128);
    int kp = r >> 7, n = r & 127;
    const float* base = preW + (size_t)l * 384 * H;
    float lo = base[(size_t)(2 * kp) * H + n];
    float hi = base[(size_t)(2 * kp + 1) * H + n];
    __half2 h = __floats2half2_rn(lo, hi);
    g_dWH[idx] = *(unsigned*)&h;
}
__global__ void pack_eL(const float* __restrict__ preW) {
    int idx = blockIdx.x * blockDim.x + threadIdx.x;
    if (idx >= NL * KP_EDGE * 128) return;
    int l = idx / (KP_EDGE * 128);
    int r = idx - l * (KP_EDGE * 128);
    int kp = r >> 7, n = r & 127;
    float v[2];
#pragma unroll
    for (int j = 0; j < 2; j++) {
        int k = 2 * kp + j;
        if (k < 128)      v[j] = preW[(size_t)l * 384 * H + (size_t)(128 + k) * H + n];
        else if (k < 144) v[j] = g_W2[(size_t)l * 16 * H + (size_t)(k - 128) * H + n];
        else              v[j] = 0.f;
    }
    __half2 h = __floats2half2_rn(v[0], v[1]);
    g_WsrcH[idx] = *(unsigned*)&h;
}
__global__ void pack_genL(const float* __restrict__ src, size_t strideL,
                          unsigned* __restrict__ out, int kpairs, int kmax) {
    int idx = blockIdx.x * blockDim.x + threadIdx.x;
    if (idx >= NL * kpairs * 128) return;
    int l = idx / (kpairs * 128);
    int r = idx - l * (kpairs * 128);
    int kp = r >> 7, n = r & 127;
    const float* base = src + (size_t)l * strideL;
    float lo = (2 * kp < kmax) ? base[(size_t)(2 * kp) * 128 + n] : 0.f;
    float hi = (2 * kp + 1 < kmax) ? base[(size_t)(2 * kp + 1) * 128 + n] : 0.f;
    __half2 h = __floats2half2_rn(lo, hi);
    out[idx] = *(unsigned*)&h;
}
__global__ void ea_pack(const float* __restrict__ ea) {
    int idx = blockIdx.x * blockDim.x + threadIdx.x;
    if (idx >= NE * 32) return;
    int e = idx >> 5, j = idx & 31;
    g_ea16[idx] = __float2half_rn(j < 16 ? ea[(size_t)e * 16 + j] : 0.f);
}
__global__ void biasm_kL(const float* __restrict__ be, const float* __restrict__ ebB,
                         const float* __restrict__ preW, const float* __restrict__ pbB) {
    int l = blockIdx.x;
    int j = threadIdx.x;
    const float* T1 = g_T1 + (size_t)l * H * H;
    const float* P2 = preW + (size_t)l * 384 * H + 256 * H;
    float s = pbB[l * H + j];
    for (int k = 0; k < H; k++) s += be[k] * T1[k * H + j];
    for (int k = 0; k < H; k++) s += ebB[l * H + k] * P2[k * H + j];
    g_biasmL[l * H + j] = s;
}
// combined bias: cbias[l][j] = sum_k post_b[l][k] * linW[l][k][j] + lin_b[l][j]
__global__ void cbias_kL(const float* __restrict__ pbB, const float* __restrict__ linW,
                         const float* __restrict__ lbB) {
    int l = blockIdx.x;
    int j = threadIdx.x;
    const float* L = linW + (size_t)l * H * H;
    float s = lbB[l * H + j];
    for (int k = 0; k < H; k++) s += pbB[l * H + k] * L[k * H + j];
    g_cbiasL[l * H + j] = s;
}

// ---------------- sort / scan ----------------
__global__ void deg_count(const int* __restrict__ dstI) {
    int e = blockIdx.x * blockDim.x + threadIdx.x;
    if (e < NE) atomicAdd(&g_cnt[dstI[e]], 1);
}
__global__ __launch_bounds__(256) void scan1() {
    int b = blockIdx.x, t = threadIdx.x;
    int n = b * CHUNK + t;
    int v = (t < CHUNK && n < NN) ? g_cnt[n] : 0;
    int lane = t & 31, wid = t >> 5;
    int x = v;
#pragma unroll
    for (int off = 1; off < 32; off <<= 1) {
        int u = __shfl_up_sync(0xffffffffu, x, off);
        if (lane >= off) x += u;
    }
    __shared__ int wsum[8];
    if (lane == 31) wsum[wid] = x;
    __syncthreads();
    if (t == 0) {
        int r = 0;
#pragma unroll
        for (int i = 0; i < 8; i++) { int tmp = wsum[i]; wsum[i] = r; r += tmp; }
        g_part[b] = r;
    }
    __syncthreads();
    int excl = x - v + wsum[wid];
    if (t < CHUNK && n < NN) g_start[n] = excl;
}
__global__ void scan2() {
    int t = threadIdx.x;
    int v = g_part[t];
    int lane = t & 31, wid = t >> 5;
    int x = v;
#pragma unroll
    for (int off = 1; off < 32; off <<= 1) {
        int u = __shfl_up_sync(0xffffffffu, x, off);
        if (lane >= off) x += u;
    }
    __shared__ int wsum[4];
    if (lane == 31) wsum[wid] = x;
    __syncthreads();
    if (t == 0) {
        int r = 0;
#pragma unroll
        for (int i = 0; i < 4; i++) { int tmp = wsum[i]; wsum[i] = r; r += tmp; }
    }
    __syncthreads();
    g_part[t] = x - v + wsum[wid];
}
__global__ void scan3() {
    int n = blockIdx.x * blockDim.x + threadIdx.x;
    if (n < NN) {
        int s = g_start[n] + g_part[n / CHUNK];
        g_start[n] = s;
        g_cursor[n] = s;
    }
    if (n == 0) g_start[NN] = NE;
}
__global__ void scatter_k(const int* __restrict__ srcI, const int* __restrict__ dstI) {
    int e = blockIdx.x * blockDim.x + threadIdx.x;
    if (e >= NE) return;
    int d = dstI[e];
    int p = atomicAdd(&g_cursor[d], 1);
    g_psrc[p] = srcI[e];
    g_pdst[p] = d;
    g_peid[p] = e;
}
__global__ void amp_k() {
    int n = blockIdx.x * blockDim.x + threadIdx.x;
    if (n >= NN) return;
    float degc = fmaxf((float)g_cnt[n], 1.f);
    float a = logf(degc + 1.f) / AVG_LOG;
    g_amp[n] = a;
    g_iamp[n] = 1.f / a;
}

// ---------------- pool / head ----------------
__global__ void pool_k(const int* __restrict__ batch) {
    int c = threadIdx.x;
    int start = blockIdx.x * 256;
    int end = min(start + 256, NN);
    if (start >= NN) return;
    float acc = 0.f;
    int cur = batch[start];
    for (int n = start; n < end; n++) {
        int g = batch[n];
        if (g != cur) { atomicAdd(&g_pool[cur * H + c], acc); acc = 0.f; cur = g; }
        acc += __half2float(g_h16[(size_t)n * H + c]);
    }
    atomicAdd(&g_pool[cur * H + c], acc);
}
__global__ void head1_k(const float* __restrict__ W1, const float* __restrict__ b1) {
    int idx = blockIdx.x * blockDim.x + threadIdx.x;
    if (idx >= NGR * 64) return;
    int g = idx >> 6, j = idx & 63;
    float s = b1[j];
    for (int k = 0; k < H; k++) s += g_pool[g * H + k] * W1[k * 64 + j];
    g_z[idx] = fmaxf(s, 0.f);
}
__global__ void head2_k(const float* __restrict__ W2, const float* __restrict__ b2,
                        float* __restrict__ out) {
    int idx = blockIdx.x * blockDim.x + threadIdx.x;
    if (idx >= NGR * NOUT) return;
    int g = idx / NOUT, j = idx % NOUT;
    float s = b2[j];
    for (int k = 0; k < 64; k++) s += g_z[g * 64 + k] * W2[k * NOUT + j];
    out[idx] = s;
}

// ---------------- launch ----------------
extern "C" void kernel_launch(void* const* d_in, const int* in_sizes, int n_in,
                              void* d_out, int out_size)
{
    int iEI = 1, iBatch = 2, iEA = 3;
    if (in_sizes[1] == NE * 16) { iEA = 1; iEI = 2; iBatch = 3; }

    const float* x         = (const float*)d_in[0];
    const int*   edge_index= (const int*)  d_in[iEI];
    const int*   batch     = (const int*)  d_in[iBatch];
    const float* edge_attr = (const float*)d_in[iEA];
    const float* node_emb_W= (const float*)d_in[4];
    const float* node_emb_b= (const float*)d_in[5];
    const float* edge_emb_W= (const float*)d_in[6];
    const float* edge_emb_b= (const float*)d_in[7];
    const float* edge_enc_W= (const float*)d_in[8];
    const float* edge_enc_b= (const float*)d_in[9];
    const float* pre_W     = (const float*)d_in[10];
    const float* pre_b     = (const float*)d_in[11];
    const float* post_W    = (const float*)d_in[12];
    const float* post_b    = (const float*)d_in[13];
    const float* lin_W     = (const float*)d_in[14];
    const float* lin_b     = (const float*)d_in[15];
    const float* bn_gamma  = (const float*)d_in[16];
    const float* bn_beta   = (const float*)d_in[17];
    const float* head1_W   = (const float*)d_in[18];
    const float* head1_b   = (const float*)d_in[19];
    const float* head2_W   = (const float*)d_in[20];
    const float* head2_b   = (const float*)d_in[21];

    const int* srcI = edge_index;
    const int* dstI = edge_index + NE;

    float *p_T1, *p_W2, *p_biasm, *p_cbias, *p_bn, *p_pool, *p_wcomb;
    unsigned *p_wsrcH, *p_postWH, *p_dWH;
    int *p_cnt, *p_bcnt;
    cudaGetSymbolAddress((void**)&p_T1,     g_T1);
    cudaGetSymbolAddress((void**)&p_W2,     g_W2);
    cudaGetSymbolAddress((void**)&p_wsrcH,  g_WsrcH);
    cudaGetSymbolAddress((void**)&p_postWH, g_postWH);
    cudaGetSymbolAddress((void**)&p_dWH,    g_dWH);
    cudaGetSymbolAddress((void**)&p_wcomb,  g_Wcomb);
    cudaGetSymbolAddress((void**)&p_biasm,  g_biasmL);
    cudaGetSymbolAddress((void**)&p_cbias,  g_cbiasL);
    cudaGetSymbolAddress((void**)&p_bn,     g_bn);
    cudaGetSymbolAddress((void**)&p_pool,   g_pool);
    cudaGetSymbolAddress((void**)&p_cnt,    g_cnt);
    cudaGetSymbolAddress((void**)&p_bcnt,   g_bcnt);

    cudaFuncSetAttribute(edge_agg, cudaFuncAttributeMaxDynamicSharedMemorySize, BIG_SMEM);
    cudaFuncSetAttribute(post_gemmt, cudaFuncAttributeMaxDynamicSharedMemorySize, BIG_SMEM);

    // sort prep
    cudaMemsetAsync(p_cnt, 0, NN * sizeof(int));
    cudaMemsetAsync(p_bcnt, 0, sizeof(int));
    deg_count<<<(NE + 255) / 256, 256>>>(dstI);
    scan1<<<SCAN_B, 256>>>();
    scan2<<<1, 128>>>();
    emb_gemmt<<<(NN + 127) / 128, 256>>>(x, node_emb_W, node_emb_b, 64);
    scan3<<<(NN + 255) / 256, 256>>>();
    scatter_k<<<(NE + 255) / 256, 256>>>(srcI, dstI);
    amp_k<<<(NN + 255) / 256, 256>>>();
    bnd_build<<<(NN + 255) / 256, 256>>>();
    ea_pack<<<(NE * 32 + 255) / 256, 256>>>(edge_attr);

    // batched weight prep
    gemm128L<<<dim3(1, NL), 256>>>(edge_enc_W, (size_t)H * H,
                                   pre_W + 256 * H, (size_t)384 * H,
                                   p_T1, (size_t)H * H, 128, 128);
    gemm128L<<<dim3(1, NL), 256>>>(edge_emb_W, 0,
                                   p_T1, (size_t)H * H,
                                   p_W2, (size_t)16 * H, 16, 128);
    // composed post weight: Wcomb = postW @ linW  (M=13*128, K=128)
    gemm128L<<<dim3(13, NL), 256>>>(post_W, (size_t)13 * H * H,
                                    lin_W, (size_t)H * H,
                                    p_wcomb, (size_t)13 * H * H, 13 * H, 128);
    biasm_kL<<<NL, 128>>>(edge_emb_b, edge_enc_b, pre_W, pre_b);
    cbias_kL<<<NL, 128>>>(post_b, lin_W, lin_b);
    pack_dL<<<(NL * KP_D * 128 + 255) / 256, 256>>>(pre_W);
    pack_eL<<<(NL * KP_EDGE * 128 + 255) / 256, 256>>>(pre_W);
    pack_genL<<<(NL * KP_POST * 128 + 255) / 256, 256>>>(p_wcomb, (size_t)13 * H * H,
                                                         p_postWH, KP_POST, 13 * H);

    d_gemm<<<(NN + 127) / 128, 256>>>(p_dWH, p_biasm);
    init_bnd<<<64, 256>>>();

    for (int l = 0; l < NL; l++) {
        edge_agg<<<NE / 128, 256, BIG_SMEM>>>(p_wsrcH + (size_t)l * KP_EDGE * H);
        fin_init_bnd<<<64, 256>>>(l < NL - 1 ? 1 : 0);

        cudaMemsetAsync(p_bn, 0, 2 * H * sizeof(float));
        post_gemmt<<<(NN + 127) / 128, 256, BIG_SMEM>>>(
            p_postWH + (size_t)l * KP_POST * H, p_cbias + l * H);

        if (l < NL - 1)
            bn_d_gemm<<<(NN + 127) / 128, 256>>>(bn_gamma + l * H, bn_beta + l * H,
                                                 p_dWH + (size_t)(l + 1) * KP_D * H,
                                                 p_biasm + (l + 1) * H, 1);
        else
            bn_d_gemm<<<(NN + 127) / 128, 256>>>(bn_gamma + l * H, bn_beta + l * H,
                                                 p_dWH, p_biasm, 0);
    }

    cudaMemsetAsync(p_pool, 0, NGR * H * sizeof(float));
    pool_k<<<(NN + 255) / 256, 128>>>(batch);
    head1_k<<<8, 256>>>(head1_W, head1_b);
    head2_k<<<2, 256>>>(head2_W, head2_b, (float*)d_out);
}